// round 5
// baseline (speedup 1.0000x reference)
#include <cuda_runtime.h>
#include <cuda_bf16.h>
#include <math.h>

#define B_    2
#define N_    1024
#define DIM_  512
#define NH_   8
#define HD_   64
#define WIN_  64
#define M_    (B_ * N_)      // 2048
#define DFF_  (4 * DIM_)     // 2048
#define EPSV  1e-7f

// ------------------------ scratch (device globals; no allocation) ------------
__device__ float g_xn  [M_ * DIM_];
__device__ float g_q   [M_ * DIM_];
__device__ float g_k   [M_ * DIM_];
__device__ float g_v   [M_ * DIM_];
__device__ float g_qh  [B_ * NH_ * N_ * HD_];
__device__ float g_kh  [B_ * NH_ * N_ * HD_];
__device__ float g_vt  [B_ * NH_ * N_ * HD_];
__device__ float g_attn[M_ * DIM_];
__device__ float g_xout[M_ * DIM_];
__device__ float g_h   [M_ * DIM_];
__device__ float g_mid [M_ * DFF_];

// ------------------------ helpers -------------------------------------------
__device__ __forceinline__ float warpsum(float v) {
#pragma unroll
    for (int o = 16; o > 0; o >>= 1) v += __shfl_xor_sync(0xffffffffu, v, o);
    return v;
}
__device__ __forceinline__ float warpmax(float v) {
#pragma unroll
    for (int o = 16; o > 0; o >>= 1) v = fmaxf(v, __shfl_xor_sync(0xffffffffu, v, o));
    return v;
}
__device__ __forceinline__ float tf32r(float x) {
    asm("cvt.rna.tf32.f32 %0, %1;" : "=f"(x) : "f"(x));
    return x;
}
__device__ __forceinline__ float sqrt_fast(float x) {
    float r;
    asm("sqrt.approx.f32 %0, %1;" : "=f"(r) : "f"(x));
    return r;
}
__device__ __forceinline__ void mma_tf32(float4& c, float a0f, float a1f,
                                         float a2f, float a3f, float b0f, float b1f) {
    unsigned a0 = __float_as_uint(a0f), a1 = __float_as_uint(a1f);
    unsigned a2 = __float_as_uint(a2f), a3 = __float_as_uint(a3f);
    unsigned b0 = __float_as_uint(b0f), b1 = __float_as_uint(b1f);
    asm volatile(
        "mma.sync.aligned.m16n8k8.row.col.f32.tf32.tf32.f32 "
        "{%0,%1,%2,%3},{%4,%5,%6,%7},{%8,%9},{%0,%1,%2,%3};\n"
        : "+f"(c.x), "+f"(c.y), "+f"(c.z), "+f"(c.w)
        : "r"(a0), "r"(a1), "r"(a2), "r"(a3), "r"(b0), "r"(b1));
}

// ------------------------ layernorm -----------------------------------------
__global__ void ln_kernel(const float* __restrict__ x, const float* __restrict__ s,
                          const float* __restrict__ bsh, float* __restrict__ out) {
    int row = blockIdx.x;
    const float* xr = x + (size_t)row * DIM_;
    float v[4];
    float sum = 0.f, sq = 0.f;
#pragma unroll
    for (int i = 0; i < 4; i++) {
        v[i] = xr[threadIdx.x + i * 128];
        sum += v[i];
        sq  += v[i] * v[i];
    }
    __shared__ float red0[4], red1[4];
    sum = warpsum(sum); sq = warpsum(sq);
    int warp = threadIdx.x >> 5, lane = threadIdx.x & 31;
    if (lane == 0) { red0[warp] = sum; red1[warp] = sq; }
    __syncthreads();
    sum = red0[0] + red0[1] + red0[2] + red0[3];
    sq  = red1[0] + red1[1] + red1[2] + red1[3];
    float mean = sum * (1.0f / DIM_);
    float var  = sq * (1.0f / DIM_) - mean * mean;
    float inv  = rsqrtf(var + 1e-6f);
    float* orow = out + (size_t)row * DIM_;
#pragma unroll
    for (int i = 0; i < 4; i++) {
        int d = threadIdx.x + i * 128;
        orow[d] = (v[i] - mean) * inv * s[d] + bsh[d];
    }
}

// ------------------------ tf32 tensor-core GEMM ------------------------------
// BM=128 BN=64 BK=16, 128 threads = 4 warps (2x2), warp tile 64x32.
// Per k-step: 16 MMA m16n8k8 vs 12 LDS.64. True ping-pong: ONE sync per K-tile;
// prefetched gmem regs stored to buf^1 while MMAs consume buf.
struct GSmem {
    float2 Ap[2][2][4][136];  // [buf][ks][tig][m]  (strides keep tig planes in
    float2 Bp[2][2][4][72];   //  disjoint 64B regions mod 256B -> conflict-free)
};

// EPI: 0 = +bias, 1 = +bias+residual, 2 = gelu(+bias)
template <int EPI>
__device__ __forceinline__ void gemm_core(
    const float* __restrict__ A, const float* __restrict__ Bw,
    const float* __restrict__ bias, const float* __restrict__ res,
    float* __restrict__ C, int Nd, int Kd) {
    __shared__ GSmem sm;
    const int m0 = blockIdx.y * 128, n0 = blockIdx.x * 64;
    const int tid = threadIdx.x;                 // 0..127
    const int lane = tid & 31, wid = tid >> 5;   // 4 warps
    const int g = lane >> 2, tg = lane & 3;
    const int wm = wid >> 1, wn = wid & 1;       // warp grid 2x2

    // loaders: A one row/thread (16 k), B two rows of 4 cols
    const float* aPtr = A + (size_t)(m0 + tid) * Kd;
    const int brow0 = tid >> 4, bc4 = (tid & 15) * 4;
    const float* bPtr0 = Bw + (size_t)brow0 * Nd + n0 + bc4;
    const float* bPtr1 = Bw + (size_t)(brow0 + 8) * Nd + n0 + bc4;

    float4 acc[4][4];
#pragma unroll
    for (int i = 0; i < 4; i++)
#pragma unroll
        for (int j = 0; j < 4; j++) acc[i][j] = make_float4(0.f, 0.f, 0.f, 0.f);

    float4 a0, a1, a2, a3, b0, b1;
    a0 = *(const float4*)(aPtr);
    a1 = *(const float4*)(aPtr + 4);
    a2 = *(const float4*)(aPtr + 8);
    a3 = *(const float4*)(aPtr + 12);
    b0 = *(const float4*)(bPtr0);
    b1 = *(const float4*)(bPtr1);

    auto stA = [&](int buf) {
        sm.Ap[buf][0][0][tid] = make_float2(tf32r(a0.x), tf32r(a1.x));
        sm.Ap[buf][0][1][tid] = make_float2(tf32r(a0.y), tf32r(a1.y));
        sm.Ap[buf][0][2][tid] = make_float2(tf32r(a0.z), tf32r(a1.z));
        sm.Ap[buf][0][3][tid] = make_float2(tf32r(a0.w), tf32r(a1.w));
        sm.Ap[buf][1][0][tid] = make_float2(tf32r(a2.x), tf32r(a3.x));
        sm.Ap[buf][1][1][tid] = make_float2(tf32r(a2.y), tf32r(a3.y));
        sm.Ap[buf][1][2][tid] = make_float2(tf32r(a2.z), tf32r(a3.z));
        sm.Ap[buf][1][3][tid] = make_float2(tf32r(a2.w), tf32r(a3.w));
    };
    auto stB = [&](int buf, int row, float4 v) {
        int ks = row >> 3, rr = row & 7, t = rr & 3, sel = rr >> 2;
        float* d = (float*)&sm.Bp[buf][ks][t][bc4];
        d[0 + sel] = tf32r(v.x);
        d[2 + sel] = tf32r(v.y);
        d[4 + sel] = tf32r(v.z);
        d[6 + sel] = tf32r(v.w);
    };

    stA(0);
    stB(0, brow0, b0);
    stB(0, brow0 + 8, b1);
    __syncthreads();

    const int nT = Kd >> 4;
    for (int t = 0; t < nT; t++) {
        const int buf = t & 1;
        const bool more = (t + 1 < nT);
        if (more) {  // prefetch next tile (LDG issues early, returns under MMA)
            const float* ap = aPtr + (t + 1) * 16;
            a0 = *(const float4*)ap;
            a1 = *(const float4*)(ap + 4);
            a2 = *(const float4*)(ap + 8);
            a3 = *(const float4*)(ap + 12);
            const size_t koff = (size_t)(t + 1) * 16 * Nd;
            b0 = *(const float4*)(bPtr0 + koff);
            b1 = *(const float4*)(bPtr1 + koff);
        }
#pragma unroll
        for (int ks = 0; ks < 2; ks++) {
            float2 la[4][2], lb[4];
#pragma unroll
            for (int mi = 0; mi < 4; mi++) {
                la[mi][0] = sm.Ap[buf][ks][tg][wm * 64 + mi * 16 + g];
                la[mi][1] = sm.Ap[buf][ks][tg][wm * 64 + mi * 16 + g + 8];
            }
#pragma unroll
            for (int nj = 0; nj < 4; nj++)
                lb[nj] = sm.Bp[buf][ks][tg][wn * 32 + nj * 8 + g];
#pragma unroll
            for (int mi = 0; mi < 4; mi++)
#pragma unroll
                for (int nj = 0; nj < 4; nj++)
                    mma_tf32(acc[mi][nj],
                             la[mi][0].x, la[mi][1].x, la[mi][0].y, la[mi][1].y,
                             lb[nj].x, lb[nj].y);
        }
        if (more) {  // store next tile into the other buffer (no barrier needed)
            stA(buf ^ 1);
            stB(buf ^ 1, brow0, b0);
            stB(buf ^ 1, brow0 + 8, b1);
        }
        __syncthreads();
    }

#pragma unroll
    for (int mi = 0; mi < 4; mi++) {
        int r0 = m0 + wm * 64 + mi * 16 + g;
#pragma unroll
        for (int nj = 0; nj < 4; nj++) {
            int col = n0 + wn * 32 + nj * 8 + tg * 2;
            float2 bb = *(const float2*)(bias + col);
            float4 a = acc[mi][nj];
            float2 o0 = make_float2(a.x + bb.x, a.y + bb.y);
            float2 o1 = make_float2(a.z + bb.x, a.w + bb.y);
            if (EPI == 1) {
                float2 r0v = *(const float2*)(res + (size_t)r0 * Nd + col);
                float2 r1v = *(const float2*)(res + (size_t)(r0 + 8) * Nd + col);
                o0.x += r0v.x; o0.y += r0v.y;
                o1.x += r1v.x; o1.y += r1v.y;
            }
            if (EPI == 2) {
                float t0 = o0.x, t1 = o0.y, t2 = o1.x, t3 = o1.y;
                o0.x = t0 / (1.f + __expf(-1.5957691216057308f * (t0 + 0.044715f * t0 * t0 * t0)));
                o0.y = t1 / (1.f + __expf(-1.5957691216057308f * (t1 + 0.044715f * t1 * t1 * t1)));
                o1.x = t2 / (1.f + __expf(-1.5957691216057308f * (t2 + 0.044715f * t2 * t2 * t2)));
                o1.y = t3 / (1.f + __expf(-1.5957691216057308f * (t3 + 0.044715f * t3 * t3 * t3)));
            }
            *(float2*)(C + (size_t)r0 * Nd + col)       = o0;
            *(float2*)(C + (size_t)(r0 + 8) * Nd + col) = o1;
        }
    }
}

__global__ __launch_bounds__(128) void k_gemm_qkv(
    const float* __restrict__ xn,
    const float* __restrict__ Wq, const float* __restrict__ bq,
    const float* __restrict__ Wk, const float* __restrict__ bk,
    const float* __restrict__ Wv, const float* __restrict__ bv,
    float* __restrict__ q, float* __restrict__ k, float* __restrict__ v) {
    int z = blockIdx.z;
    const float* W  = (z == 0) ? Wq : (z == 1) ? Wk : Wv;
    const float* bb = (z == 0) ? bq : (z == 1) ? bk : bv;
    float* o        = (z == 0) ? q  : (z == 1) ? k  : v;
    gemm_core<0>(xn, W, bb, nullptr, o, DIM_, DIM_);
}

template <int EPI>
__global__ __launch_bounds__(128) void k_gemm(
    const float* __restrict__ A, const float* __restrict__ W,
    const float* __restrict__ bias, const float* __restrict__ res,
    float* __restrict__ C, int Nd, int Kd) {
    gemm_core<EPI>(A, W, bias, res, C, Nd, Kd);
}

// ------------------------ prep: hash + rope + expmap0 + transpose ------------
__global__ void prep_kernel(const float* __restrict__ qb, const float* __restrict__ kb,
                            const float* __restrict__ vb, const float* __restrict__ cos_t,
                            const float* __restrict__ sin_t, const float* __restrict__ c_arr,
                            const float* __restrict__ hash_off,
                            float* __restrict__ qh, float* __restrict__ kh,
                            float* __restrict__ vt) {
    int bn = blockIdx.x;
    int b = bn / N_, n = bn % N_;
    int h = threadIdx.x >> 5, lane = threadIdx.x & 31;
    const float LOG9 = 2.1972245773362196f;
    float cs = cos_t[n * 32 + lane];
    float sn = sin_t[n * 32 + lane];
    float cb = c_arr[b];
    float sqrt_c = fmaxf(sqrtf(cb), EPSV);
    size_t in_off  = (size_t)bn * DIM_ + h * HD_;
    size_t out_off = (((size_t)(b * NH_ + h)) * N_ + n) * HD_;

    {
        float v0 = qb[in_off + lane]      + hash_off[h * HD_ + lane]      * LOG9;
        float v1 = qb[in_off + lane + 32] + hash_off[h * HD_ + lane + 32] * LOG9;
        float r0 = v0 * cs - v1 * sn;
        float r1 = v0 * sn + v1 * cs;
        float nrm = sqrtf(warpsum(r0 * r0 + r1 * r1));
        float o0 = 0.f, o1 = 0.f;
        if (nrm >= EPSV) {
            float safe = fmaxf(nrm, EPSV);
            float mag  = tanhf(sqrt_c * safe) / sqrt_c;
            float sc   = mag / safe;
            o0 = sc * r0; o1 = sc * r1;
        }
        qh[out_off + lane] = o0; qh[out_off + lane + 32] = o1;
    }
    {
        float v0 = kb[in_off + lane];
        float v1 = kb[in_off + lane + 32];
        float r0 = v0 * cs - v1 * sn;
        float r1 = v0 * sn + v1 * cs;
        float nrm = sqrtf(warpsum(r0 * r0 + r1 * r1));
        float o0 = 0.f, o1 = 0.f;
        if (nrm >= EPSV) {
            float safe = fmaxf(nrm, EPSV);
            float mag  = tanhf(sqrt_c * safe) / sqrt_c;
            float sc   = mag / safe;
            o0 = sc * r0; o1 = sc * r1;
        }
        kh[out_off + lane] = o0; kh[out_off + lane + 32] = o1;
    }
    vt[out_off + lane]      = vb[in_off + lane];
    vt[out_off + lane + 32] = vb[in_off + lane + 32];
}

// ------------------------ windowed Poincaré attention (persistent) -----------
#define QT2    16
#define KR2    (QT2 + WIN_ - 1)   // 79
#define KS_STR 65
#define QS_STR 68
#define SW_STR 65
#define NTILES ((N_ / QT2) * B_ * NH_)   // 1024
#define RMIN_  5.0000003e-8f             // (1e-7)/(2-1e-7)

__global__ __launch_bounds__(256) void attn2_kernel(
    const float* __restrict__ qh, const float* __restrict__ kh,
    const float* __restrict__ vt, const float* __restrict__ c_arr,
    const float* __restrict__ geo, float* __restrict__ attn_out) {
    __shared__ __align__(16) float Ks[KR2 * KS_STR + 16];  // K tile; reused for V
    __shared__ __align__(16) float Qs[QT2 * QS_STR];
    __shared__ __align__(16) float Sw[QT2 * SW_STR];
    __shared__ float y2s[KR2 + 1];

    const int tid = threadIdx.x;
    const int w = tid >> 5, l = tid & 31;
    const int qi = tid >> 4;          // 0..15
    const int kg = tid & 15;          // 0..15

    for (int t = blockIdx.x; t < NTILES; t += gridDim.x) {
        const int bh = t >> 6;
        const int b = bh >> 3, h = bh & 7;
        const int n0 = (t & 63) << 4;
        const float* Kb = kh + (size_t)bh * (N_ * HD_);
        const float* Vb = vt + (size_t)bh * (N_ * HD_);
        const float* Qb = qh + (size_t)bh * (N_ * HD_);

#pragma unroll
        for (int i = 0; i < 5; i++) {
            int f = tid + i * 256;
            if (f < KR2 * 16) {
                int row = f >> 4, c4 = (f & 15) << 2;
                int gn = n0 - (WIN_ - 1) + row;
                float4 val = make_float4(0.f, 0.f, 0.f, 0.f);
                if (gn >= 0) val = *(const float4*)(Kb + (size_t)gn * HD_ + c4);
                float* d = &Ks[row * KS_STR + c4];
                d[0] = val.x; d[1] = val.y; d[2] = val.z; d[3] = val.w;
            }
        }
        {
            int row = tid >> 4, c4 = (tid & 15) << 2;
            *(float4*)&Qs[row * QS_STR + c4] =
                *(const float4*)(Qb + (size_t)(n0 + row) * HD_ + c4);
        }
        float4 vreg[5];
#pragma unroll
        for (int i = 0; i < 5; i++) {
            int f = tid + i * 256;
            vreg[i] = make_float4(0.f, 0.f, 0.f, 0.f);
            if (f < KR2 * 16) {
                int row = f >> 4, c4 = (f & 15) << 2;
                int gn = n0 - (WIN_ - 1) + row;
                if (gn >= 0) vreg[i] = *(const float4*)(Vb + (size_t)gn * HD_ + c4);
            }
        }
        __syncthreads();

        for (int row = w; row < KR2; row += 8) {
            float a = Ks[row * KS_STR + l];
            float bq = Ks[row * KS_STR + 32 + l];
            float s = warpsum(a * a + bq * bq);
            if (l == 0) y2s[row] = s;
        }
        __syncthreads();

        const float cb = c_arr[b];
        const float sc = fmaxf(sqrtf(cb), EPSV);
        const float gs = geo[h];
        const float p2 = gs / sc;
        const float cc = cb * cb;

        float xy0 = 0.f, xy1 = 0.f, xy2 = 0.f, xy3 = 0.f, q2 = 0.f;
        {
            const float* qrow = &Qs[qi * QS_STR];
            const float* kr = &Ks[(qi + kg) * KS_STR];
#pragma unroll 8
            for (int d = 0; d < HD_; d++) {
                float qv = qrow[d];
                q2  = fmaf(qv, qv, q2);
                xy0 = fmaf(qv, kr[d], xy0);
                xy1 = fmaf(qv, kr[d + 16 * KS_STR], xy1);
                xy2 = fmaf(qv, kr[d + 32 * KS_STR], xy2);
                xy3 = fmaf(qv, kr[d + 48 * KS_STR], xy3);
            }
        }
        {
            const float Bc = 1.f - cb * q2;
            const float c2x2 = cc * q2;
            float xys[4] = {xy0, xy1, xy2, xy3};
#pragma unroll
            for (int j = 0; j < 4; j++) {
                float xy = xys[j];
                float y2 = y2s[qi + kg + 16 * j];
                float u  = fmaf(-2.f * cb, xy, 1.f);
                float A  = fmaf(cb, y2, u);
                float dn2 = fmaf(A * A, q2, fmaf(Bc * Bc, y2, -2.f * A * Bc * xy));
                float den = fmaxf(fmaf(c2x2, y2, u), EPSV);
                float s   = sc * sqrt_fast(fmaxf(dn2, 0.f));
                float ratio = __fdividef(den - s, den + s);
                ratio = fmaxf(ratio, RMIN_);
                Sw[qi * SW_STR + kg + 16 * j] = p2 * __log2f(ratio);
            }
        }
        __syncthreads();

#pragma unroll
        for (int qq = 0; qq < 2; qq++) {
            int q = w + qq * 8;
            float s0 = Sw[q * SW_STR + l];
            float s1 = Sw[q * SW_STR + 32 + l];
            float m = warpmax(fmaxf(s0, s1));
            float e0 = exp2f(s0 - m), e1 = exp2f(s1 - m);
            float inv = __fdividef(1.f, warpsum(e0 + e1));
            Sw[q * SW_STR + l] = e0 * inv;
            Sw[q * SW_STR + 32 + l] = e1 * inv;
        }
        __syncthreads();

#pragma unroll
        for (int i = 0; i < 5; i++) {
            int f = tid + i * 256;
            if (f < KR2 * 16) {
                int row = f >> 4, c4 = (f & 15) << 2;
                *(float4*)&Ks[row * HD_ + c4] = vreg[i];
            }
        }
        __syncthreads();

        {
            const int dg = tid & 15;
            float4 acc = make_float4(0.f, 0.f, 0.f, 0.f);
            const float* wrow = &Sw[qi * SW_STR];
            const float* vbase = &Ks[qi * HD_ + dg * 4];
#pragma unroll 8
            for (int k = 0; k < WIN_; k++) {
                float wk = wrow[k];
                float4 vv = *(const float4*)(vbase + k * HD_);
                acc.x = fmaf(wk, vv.x, acc.x);
                acc.y = fmaf(wk, vv.y, acc.y);
                acc.z = fmaf(wk, vv.z, acc.z);
                acc.w = fmaf(wk, vv.w, acc.w);
            }
            float* orow = attn_out + ((size_t)(b * N_ + n0 + qi)) * DIM_ + h * HD_ + dg * 4;
            *(float4*)orow = acc;
        }
        __syncthreads();
    }
}

// ------------------------ launch --------------------------------------------
extern "C" void kernel_launch(void* const* d_in, const int* in_sizes, int n_in,
                              void* d_out, int out_size) {
    (void)in_sizes; (void)n_in; (void)out_size;
    const float* x     = (const float*)d_in[0];
    const float* fcos  = (const float*)d_in[1];
    const float* fsin  = (const float*)d_in[2];
    const float* c     = (const float*)d_in[3];
    const float* Wq    = (const float*)d_in[4];
    const float* bq    = (const float*)d_in[5];
    const float* Wk    = (const float*)d_in[6];
    const float* bk    = (const float*)d_in[7];
    const float* Wv    = (const float*)d_in[8];
    const float* bv    = (const float*)d_in[9];
    const float* Wo    = (const float*)d_in[10];
    const float* bo    = (const float*)d_in[11];
    const float* W1    = (const float*)d_in[12];
    const float* b1    = (const float*)d_in[13];
    const float* W2    = (const float*)d_in[14];
    const float* b2    = (const float*)d_in[15];
    const float* ln1s  = (const float*)d_in[16];
    const float* ln1b  = (const float*)d_in[17];
    const float* ln2s  = (const float*)d_in[18];
    const float* ln2b  = (const float*)d_in[19];
    const float* geo   = (const float*)d_in[20];
    const float* hasho = (const float*)d_in[21];
    float* out = (float*)d_out;

    float *xn, *q, *k, *v, *qh, *kh, *vt, *attn, *xout, *hh, *mid;
    cudaGetSymbolAddress((void**)&xn,   g_xn);
    cudaGetSymbolAddress((void**)&q,    g_q);
    cudaGetSymbolAddress((void**)&k,    g_k);
    cudaGetSymbolAddress((void**)&v,    g_v);
    cudaGetSymbolAddress((void**)&qh,   g_qh);
    cudaGetSymbolAddress((void**)&kh,   g_kh);
    cudaGetSymbolAddress((void**)&vt,   g_vt);
    cudaGetSymbolAddress((void**)&attn, g_attn);
    cudaGetSymbolAddress((void**)&xout, g_xout);
    cudaGetSymbolAddress((void**)&hh,   g_h);
    cudaGetSymbolAddress((void**)&mid,  g_mid);

    // 1) LN1
    ln_kernel<<<M_, 128>>>(x, ln1s, ln1b, xn);

    // 2) fused QKV projections (384 CTAs x 128 thr)
    dim3 gqkv(DIM_ / 64, M_ / 128, 3);
    k_gemm_qkv<<<gqkv, 128>>>(xn, Wq, bq, Wk, bk, Wv, bv, q, k, v);

    // 3) hash + rope + expmap0 + transpose
    prep_kernel<<<M_, 256>>>(q, k, v, fcos, fsin, c, hasho, qh, kh, vt);

    // 4) sliding-window Poincaré attention (persistent, 2 CTAs/SM)
    attn2_kernel<<<304, 256>>>(qh, kh, vt, c, geo, attn);

    // 5) Wo projection + residual(x)
    dim3 g512(DIM_ / 64, M_ / 128);
    k_gemm<1><<<g512, 128>>>(attn, Wo, bo, x, xout, DIM_, DIM_);

    // 6) LN2
    ln_kernel<<<M_, 128>>>(xout, ln2s, ln2b, hh);

    // 7) FFN1 + gelu
    dim3 gffn1(DFF_ / 64, M_ / 128);
    k_gemm<2><<<gffn1, 128>>>(hh, W1, b1, nullptr, mid, DFF_, DIM_);

    // 8) FFN2 + residual(x_out) -> out
    k_gemm<1><<<g512, 128>>>(mid, W2, b2, xout, out, DIM_, DFF_);
}

// round 6
// speedup vs baseline: 1.1621x; 1.1621x over previous
#include <cuda_runtime.h>
#include <cuda_bf16.h>
#include <math.h>

#define B_    2
#define N_    1024
#define DIM_  512
#define NH_   8
#define HD_   64
#define WIN_  64
#define M_    (B_ * N_)      // 2048
#define DFF_  (4 * DIM_)     // 2048
#define EPSV  1e-7f

// ------------------------ scratch (device globals; no allocation) ------------
__device__ float g_xn  [M_ * DIM_];
__device__ float g_q   [M_ * DIM_];
__device__ float g_k   [M_ * DIM_];
__device__ float g_v   [M_ * DIM_];
__device__ float g_qh  [B_ * NH_ * N_ * HD_];
__device__ float g_kh  [B_ * NH_ * N_ * HD_];
__device__ float g_vt  [B_ * NH_ * N_ * HD_];
__device__ float g_attn[M_ * DIM_];
__device__ float g_xout[M_ * DIM_];
__device__ float g_h   [M_ * DIM_];
__device__ float g_mid [M_ * DFF_];

// ------------------------ helpers -------------------------------------------
__device__ __forceinline__ float warpsum(float v) {
#pragma unroll
    for (int o = 16; o > 0; o >>= 1) v += __shfl_xor_sync(0xffffffffu, v, o);
    return v;
}
__device__ __forceinline__ float warpmax(float v) {
#pragma unroll
    for (int o = 16; o > 0; o >>= 1) v = fmaxf(v, __shfl_xor_sync(0xffffffffu, v, o));
    return v;
}
__device__ __forceinline__ float sqrt_fast(float x) {
    float r;
    asm("sqrt.approx.f32 %0, %1;" : "=f"(r) : "f"(x));
    return r;
}
__device__ __forceinline__ void mma_tf32(float4& c, float a0f, float a1f,
                                         float a2f, float a3f, float b0f, float b1f) {
    unsigned a0 = __float_as_uint(a0f), a1 = __float_as_uint(a1f);
    unsigned a2 = __float_as_uint(a2f), a3 = __float_as_uint(a3f);
    unsigned b0 = __float_as_uint(b0f), b1 = __float_as_uint(b1f);
    asm volatile(
        "mma.sync.aligned.m16n8k8.row.col.f32.tf32.tf32.f32 "
        "{%0,%1,%2,%3},{%4,%5,%6,%7},{%8,%9},{%0,%1,%2,%3};\n"
        : "+f"(c.x), "+f"(c.y), "+f"(c.z), "+f"(c.w)
        : "r"(a0), "r"(a1), "r"(a2), "r"(a3), "r"(b0), "r"(b1));
}

// ------------------------ layernorm -----------------------------------------
__global__ void ln_kernel(const float* __restrict__ x, const float* __restrict__ s,
                          const float* __restrict__ bsh, float* __restrict__ out) {
    int row = blockIdx.x;
    const float* xr = x + (size_t)row * DIM_;
    float v[4];
    float sum = 0.f, sq = 0.f;
#pragma unroll
    for (int i = 0; i < 4; i++) {
        v[i] = xr[threadIdx.x + i * 128];
        sum += v[i];
        sq  += v[i] * v[i];
    }
    __shared__ float red0[4], red1[4];
    sum = warpsum(sum); sq = warpsum(sq);
    int warp = threadIdx.x >> 5, lane = threadIdx.x & 31;
    if (lane == 0) { red0[warp] = sum; red1[warp] = sq; }
    __syncthreads();
    sum = red0[0] + red0[1] + red0[2] + red0[3];
    sq  = red1[0] + red1[1] + red1[2] + red1[3];
    float mean = sum * (1.0f / DIM_);
    float var  = sq * (1.0f / DIM_) - mean * mean;
    float inv  = rsqrtf(var + 1e-6f);
    float* orow = out + (size_t)row * DIM_;
#pragma unroll
    for (int i = 0; i < 4; i++) {
        int d = threadIdx.x + i * 128;
        orow[d] = (v[i] - mean) * inv * s[d] + bsh[d];
    }
}

// ------------------------ tf32 tensor-core GEMM ------------------------------
// BM=128 BN=64 BK=16, 256 threads = 8 warps (4x2), warp tile 32x32.
// True ping-pong: ONE sync per K-tile; prefetched gmem regs stored to buf^1
// while MMAs consume buf. No cvt: mma.sync uses tf32 bits of raw f32 regs.
struct GSmem {
    float2 Ap[2][2][4][136];  // [buf][ks][tig][m]
    float2 Bp[2][2][4][72];   // [buf][ks][tig][n]
};

// EPI: 0 = +bias, 1 = +bias+residual, 2 = gelu(+bias)
template <int EPI>
__device__ __forceinline__ void gemm_core(
    const float* __restrict__ A, const float* __restrict__ Bw,
    const float* __restrict__ bias, const float* __restrict__ res,
    float* __restrict__ C, int Nd, int Kd) {
    __shared__ GSmem sm;
    const int m0 = blockIdx.y * 128, n0 = blockIdx.x * 64;
    const int tid = threadIdx.x;                 // 0..255
    const int lane = tid & 31, wid = tid >> 5;   // 8 warps
    const int g = lane >> 2, tg = lane & 3;
    const int wm = wid >> 1, wn = wid & 1;       // warp grid 4x2

    // loaders: A 2 float4/thread (row am, k-half aks), B 1 float4/thread
    const int am = tid >> 1, aks = tid & 1;
    const int bks = tid & 1, bn4 = ((tid >> 1) & 15) * 4, btg = tid >> 5;
    const float* aPtr = A + (size_t)(m0 + am) * Kd + aks * 8;
    const float* bPtr = Bw + (size_t)(bks * 8 + btg) * Nd + n0 + bn4;
    const int bsel = (btg >> 2) & 1;
    const int bt   = btg & 3;

    float4 acc[2][4];
#pragma unroll
    for (int i = 0; i < 2; i++)
#pragma unroll
        for (int j = 0; j < 4; j++) acc[i][j] = make_float4(0.f, 0.f, 0.f, 0.f);

    float4 av0, av1, bv;
    av0 = *(const float4*)(aPtr);
    av1 = *(const float4*)(aPtr + 4);
    bv  = *(const float4*)(bPtr);

    auto store_tile = [&](int buf) {
        sm.Ap[buf][aks][0][am] = make_float2(av0.x, av1.x);
        sm.Ap[buf][aks][1][am] = make_float2(av0.y, av1.y);
        sm.Ap[buf][aks][2][am] = make_float2(av0.z, av1.z);
        sm.Ap[buf][aks][3][am] = make_float2(av0.w, av1.w);
        float* d = (float*)&sm.Bp[buf][bks][bt][bn4];
        d[0 + bsel] = bv.x;
        d[2 + bsel] = bv.y;
        d[4 + bsel] = bv.z;
        d[6 + bsel] = bv.w;
    };

    store_tile(0);
    __syncthreads();

    const int nT = Kd >> 4;
    for (int t = 0; t < nT; t++) {
        const int buf = t & 1;
        const bool more = (t + 1 < nT);
        if (more) {  // prefetch next K-tile (LDG returns under the MMAs below)
            const float* ap = aPtr + (t + 1) * 16;
            av0 = *(const float4*)ap;
            av1 = *(const float4*)(ap + 4);
            bv  = *(const float4*)(bPtr + (size_t)(t + 1) * 16 * Nd);
        }
#pragma unroll
        for (int ks = 0; ks < 2; ks++) {
            float2 la[2][2], lb[4];
#pragma unroll
            for (int mi = 0; mi < 2; mi++) {
                la[mi][0] = sm.Ap[buf][ks][tg][wm * 32 + mi * 16 + g];
                la[mi][1] = sm.Ap[buf][ks][tg][wm * 32 + mi * 16 + g + 8];
            }
#pragma unroll
            for (int nj = 0; nj < 4; nj++)
                lb[nj] = sm.Bp[buf][ks][tg][wn * 32 + nj * 8 + g];
#pragma unroll
            for (int mi = 0; mi < 2; mi++)
#pragma unroll
                for (int nj = 0; nj < 4; nj++)
                    mma_tf32(acc[mi][nj],
                             la[mi][0].x, la[mi][1].x, la[mi][0].y, la[mi][1].y,
                             lb[nj].x, lb[nj].y);
        }
        if (more) store_tile(buf ^ 1);  // other buffer: no barrier needed here
        __syncthreads();
    }

#pragma unroll
    for (int mi = 0; mi < 2; mi++) {
        int r0 = m0 + wm * 32 + mi * 16 + g;
#pragma unroll
        for (int nj = 0; nj < 4; nj++) {
            int col = n0 + wn * 32 + nj * 8 + tg * 2;
            float2 bb = *(const float2*)(bias + col);
            float4 a = acc[mi][nj];
            float2 o0 = make_float2(a.x + bb.x, a.y + bb.y);
            float2 o1 = make_float2(a.z + bb.x, a.w + bb.y);
            if (EPI == 1) {
                float2 r0v = *(const float2*)(res + (size_t)r0 * Nd + col);
                float2 r1v = *(const float2*)(res + (size_t)(r0 + 8) * Nd + col);
                o0.x += r0v.x; o0.y += r0v.y;
                o1.x += r1v.x; o1.y += r1v.y;
            }
            if (EPI == 2) {
                float t0 = o0.x, t1 = o0.y, t2 = o1.x, t3 = o1.y;
                o0.x = t0 / (1.f + __expf(-1.5957691216057308f * (t0 + 0.044715f * t0 * t0 * t0)));
                o0.y = t1 / (1.f + __expf(-1.5957691216057308f * (t1 + 0.044715f * t1 * t1 * t1)));
                o1.x = t2 / (1.f + __expf(-1.5957691216057308f * (t2 + 0.044715f * t2 * t2 * t2)));
                o1.y = t3 / (1.f + __expf(-1.5957691216057308f * (t3 + 0.044715f * t3 * t3 * t3)));
            }
            *(float2*)(C + (size_t)r0 * Nd + col)       = o0;
            *(float2*)(C + (size_t)(r0 + 8) * Nd + col) = o1;
        }
    }
}

__global__ __launch_bounds__(256, 3) void k_gemm_qkv(
    const float* __restrict__ xn,
    const float* __restrict__ Wq, const float* __restrict__ bq,
    const float* __restrict__ Wk, const float* __restrict__ bk,
    const float* __restrict__ Wv, const float* __restrict__ bv,
    float* __restrict__ q, float* __restrict__ k, float* __restrict__ v) {
    int z = blockIdx.z;
    const float* W  = (z == 0) ? Wq : (z == 1) ? Wk : Wv;
    const float* bb = (z == 0) ? bq : (z == 1) ? bk : bv;
    float* o        = (z == 0) ? q  : (z == 1) ? k  : v;
    gemm_core<0>(xn, W, bb, nullptr, o, DIM_, DIM_);
}

template <int EPI>
__global__ __launch_bounds__(256, 3) void k_gemm(
    const float* __restrict__ A, const float* __restrict__ W,
    const float* __restrict__ bias, const float* __restrict__ res,
    float* __restrict__ C, int Nd, int Kd) {
    gemm_core<EPI>(A, W, bias, res, C, Nd, Kd);
}

// ------------------------ prep: hash + rope + expmap0 + transpose ------------
__global__ void prep_kernel(const float* __restrict__ qb, const float* __restrict__ kb,
                            const float* __restrict__ vb, const float* __restrict__ cos_t,
                            const float* __restrict__ sin_t, const float* __restrict__ c_arr,
                            const float* __restrict__ hash_off,
                            float* __restrict__ qh, float* __restrict__ kh,
                            float* __restrict__ vt) {
    int bn = blockIdx.x;
    int b = bn / N_, n = bn % N_;
    int h = threadIdx.x >> 5, lane = threadIdx.x & 31;
    const float LOG9 = 2.1972245773362196f;
    float cs = cos_t[n * 32 + lane];
    float sn = sin_t[n * 32 + lane];
    float cb = c_arr[b];
    float sqrt_c = fmaxf(sqrtf(cb), EPSV);
    size_t in_off  = (size_t)bn * DIM_ + h * HD_;
    size_t out_off = (((size_t)(b * NH_ + h)) * N_ + n) * HD_;

    {
        float v0 = qb[in_off + lane]      + hash_off[h * HD_ + lane]      * LOG9;
        float v1 = qb[in_off + lane + 32] + hash_off[h * HD_ + lane + 32] * LOG9;
        float r0 = v0 * cs - v1 * sn;
        float r1 = v0 * sn + v1 * cs;
        float nrm = sqrtf(warpsum(r0 * r0 + r1 * r1));
        float o0 = 0.f, o1 = 0.f;
        if (nrm >= EPSV) {
            float safe = fmaxf(nrm, EPSV);
            float mag  = tanhf(sqrt_c * safe) / sqrt_c;
            float sc   = mag / safe;
            o0 = sc * r0; o1 = sc * r1;
        }
        qh[out_off + lane] = o0; qh[out_off + lane + 32] = o1;
    }
    {
        float v0 = kb[in_off + lane];
        float v1 = kb[in_off + lane + 32];
        float r0 = v0 * cs - v1 * sn;
        float r1 = v0 * sn + v1 * cs;
        float nrm = sqrtf(warpsum(r0 * r0 + r1 * r1));
        float o0 = 0.f, o1 = 0.f;
        if (nrm >= EPSV) {
            float safe = fmaxf(nrm, EPSV);
            float mag  = tanhf(sqrt_c * safe) / sqrt_c;
            float sc   = mag / safe;
            o0 = sc * r0; o1 = sc * r1;
        }
        kh[out_off + lane] = o0; kh[out_off + lane + 32] = o1;
    }
    vt[out_off + lane]      = vb[in_off + lane];
    vt[out_off + lane + 32] = vb[in_off + lane + 32];
}

// ------------------------ windowed Poincaré attention (persistent) -----------
#define QT2    16
#define KR2    (QT2 + WIN_ - 1)   // 79
#define KS_STR 65
#define QS_STR 68
#define SW_STR 65
#define NTILES ((N_ / QT2) * B_ * NH_)   // 1024
#define RMIN_  5.0000003e-8f             // (1e-7)/(2-1e-7)

__global__ __launch_bounds__(256) void attn2_kernel(
    const float* __restrict__ qh, const float* __restrict__ kh,
    const float* __restrict__ vt, const float* __restrict__ c_arr,
    const float* __restrict__ geo, float* __restrict__ attn_out) {
    __shared__ __align__(16) float Ks[KR2 * KS_STR + 16];  // K tile; reused for V
    __shared__ __align__(16) float Qs[QT2 * QS_STR];
    __shared__ __align__(16) float Sw[QT2 * SW_STR];
    __shared__ float y2s[KR2 + 1];

    const int tid = threadIdx.x;
    const int w = tid >> 5, l = tid & 31;
    const int qi = tid >> 4;          // 0..15
    const int kg = tid & 15;          // 0..15

    for (int t = blockIdx.x; t < NTILES; t += gridDim.x) {
        const int bh = t >> 6;
        const int b = bh >> 3, h = bh & 7;
        const int n0 = (t & 63) << 4;
        const float* Kb = kh + (size_t)bh * (N_ * HD_);
        const float* Vb = vt + (size_t)bh * (N_ * HD_);
        const float* Qb = qh + (size_t)bh * (N_ * HD_);

#pragma unroll
        for (int i = 0; i < 5; i++) {
            int f = tid + i * 256;
            if (f < KR2 * 16) {
                int row = f >> 4, c4 = (f & 15) << 2;
                int gn = n0 - (WIN_ - 1) + row;
                float4 val = make_float4(0.f, 0.f, 0.f, 0.f);
                if (gn >= 0) val = *(const float4*)(Kb + (size_t)gn * HD_ + c4);
                float* d = &Ks[row * KS_STR + c4];
                d[0] = val.x; d[1] = val.y; d[2] = val.z; d[3] = val.w;
            }
        }
        {
            int row = tid >> 4, c4 = (tid & 15) << 2;
            *(float4*)&Qs[row * QS_STR + c4] =
                *(const float4*)(Qb + (size_t)(n0 + row) * HD_ + c4);
        }
        float4 vreg[5];
#pragma unroll
        for (int i = 0; i < 5; i++) {
            int f = tid + i * 256;
            vreg[i] = make_float4(0.f, 0.f, 0.f, 0.f);
            if (f < KR2 * 16) {
                int row = f >> 4, c4 = (f & 15) << 2;
                int gn = n0 - (WIN_ - 1) + row;
                if (gn >= 0) vreg[i] = *(const float4*)(Vb + (size_t)gn * HD_ + c4);
            }
        }
        __syncthreads();

        for (int row = w; row < KR2; row += 8) {
            float a = Ks[row * KS_STR + l];
            float bq = Ks[row * KS_STR + 32 + l];
            float s = warpsum(a * a + bq * bq);
            if (l == 0) y2s[row] = s;
        }
        __syncthreads();

        const float cb = c_arr[b];
        const float sc = fmaxf(sqrtf(cb), EPSV);
        const float gs = geo[h];
        const float p2 = gs / sc;
        const float cc = cb * cb;

        float xy0 = 0.f, xy1 = 0.f, xy2 = 0.f, xy3 = 0.f, q2 = 0.f;
        {
            const float* qrow = &Qs[qi * QS_STR];
            const float* kr = &Ks[(qi + kg) * KS_STR];
#pragma unroll 8
            for (int d = 0; d < HD_; d++) {
                float qv = qrow[d];
                q2  = fmaf(qv, qv, q2);
                xy0 = fmaf(qv, kr[d], xy0);
                xy1 = fmaf(qv, kr[d + 16 * KS_STR], xy1);
                xy2 = fmaf(qv, kr[d + 32 * KS_STR], xy2);
                xy3 = fmaf(qv, kr[d + 48 * KS_STR], xy3);
            }
        }
        {
            const float Bc = 1.f - cb * q2;
            const float c2x2 = cc * q2;
            float xys[4] = {xy0, xy1, xy2, xy3};
#pragma unroll
            for (int j = 0; j < 4; j++) {
                float xy = xys[j];
                float y2 = y2s[qi + kg + 16 * j];
                float u  = fmaf(-2.f * cb, xy, 1.f);
                float A  = fmaf(cb, y2, u);
                float dn2 = fmaf(A * A, q2, fmaf(Bc * Bc, y2, -2.f * A * Bc * xy));
                float den = fmaxf(fmaf(c2x2, y2, u), EPSV);
                float s   = sc * sqrt_fast(fmaxf(dn2, 0.f));
                float ratio = __fdividef(den - s, den + s);
                ratio = fmaxf(ratio, RMIN_);
                Sw[qi * SW_STR + kg + 16 * j] = p2 * __log2f(ratio);
            }
        }
        __syncthreads();

#pragma unroll
        for (int qq = 0; qq < 2; qq++) {
            int q = w + qq * 8;
            float s0 = Sw[q * SW_STR + l];
            float s1 = Sw[q * SW_STR + 32 + l];
            float m = warpmax(fmaxf(s0, s1));
            float e0 = exp2f(s0 - m), e1 = exp2f(s1 - m);
            float inv = __fdividef(1.f, warpsum(e0 + e1));
            Sw[q * SW_STR + l] = e0 * inv;
            Sw[q * SW_STR + 32 + l] = e1 * inv;
        }
        __syncthreads();

#pragma unroll
        for (int i = 0; i < 5; i++) {
            int f = tid + i * 256;
            if (f < KR2 * 16) {
                int row = f >> 4, c4 = (f & 15) << 2;
                *(float4*)&Ks[row * HD_ + c4] = vreg[i];
            }
        }
        __syncthreads();

        {
            const int dg = tid & 15;
            float4 acc = make_float4(0.f, 0.f, 0.f, 0.f);
            const float* wrow = &Sw[qi * SW_STR];
            const float* vbase = &Ks[qi * HD_ + dg * 4];
#pragma unroll 8
            for (int k = 0; k < WIN_; k++) {
                float wk = wrow[k];
                float4 vv = *(const float4*)(vbase + k * HD_);
                acc.x = fmaf(wk, vv.x, acc.x);
                acc.y = fmaf(wk, vv.y, acc.y);
                acc.z = fmaf(wk, vv.z, acc.z);
                acc.w = fmaf(wk, vv.w, acc.w);
            }
            float* orow = attn_out + ((size_t)(b * N_ + n0 + qi)) * DIM_ + h * HD_ + dg * 4;
            *(float4*)orow = acc;
        }
        __syncthreads();
    }
}

// ------------------------ launch --------------------------------------------
extern "C" void kernel_launch(void* const* d_in, const int* in_sizes, int n_in,
                              void* d_out, int out_size) {
    (void)in_sizes; (void)n_in; (void)out_size;
    const float* x     = (const float*)d_in[0];
    const float* fcos  = (const float*)d_in[1];
    const float* fsin  = (const float*)d_in[2];
    const float* c     = (const float*)d_in[3];
    const float* Wq    = (const float*)d_in[4];
    const float* bq    = (const float*)d_in[5];
    const float* Wk    = (const float*)d_in[6];
    const float* bk    = (const float*)d_in[7];
    const float* Wv    = (const float*)d_in[8];
    const float* bv    = (const float*)d_in[9];
    const float* Wo    = (const float*)d_in[10];
    const float* bo    = (const float*)d_in[11];
    const float* W1    = (const float*)d_in[12];
    const float* b1    = (const float*)d_in[13];
    const float* W2    = (const float*)d_in[14];
    const float* b2    = (const float*)d_in[15];
    const float* ln1s  = (const float*)d_in[16];
    const float* ln1b  = (const float*)d_in[17];
    const float* ln2s  = (const float*)d_in[18];
    const float* ln2b  = (const float*)d_in[19];
    const float* geo   = (const float*)d_in[20];
    const float* hasho = (const float*)d_in[21];
    float* out = (float*)d_out;

    float *xn, *q, *k, *v, *qh, *kh, *vt, *attn, *xout, *hh, *mid;
    cudaGetSymbolAddress((void**)&xn,   g_xn);
    cudaGetSymbolAddress((void**)&q,    g_q);
    cudaGetSymbolAddress((void**)&k,    g_k);
    cudaGetSymbolAddress((void**)&v,    g_v);
    cudaGetSymbolAddress((void**)&qh,   g_qh);
    cudaGetSymbolAddress((void**)&kh,   g_kh);
    cudaGetSymbolAddress((void**)&vt,   g_vt);
    cudaGetSymbolAddress((void**)&attn, g_attn);
    cudaGetSymbolAddress((void**)&xout, g_xout);
    cudaGetSymbolAddress((void**)&hh,   g_h);
    cudaGetSymbolAddress((void**)&mid,  g_mid);

    // 1) LN1
    ln_kernel<<<M_, 128>>>(x, ln1s, ln1b, xn);

    // 2) fused QKV projections (384 CTAs x 256 thr)
    dim3 gqkv(DIM_ / 64, M_ / 128, 3);
    k_gemm_qkv<<<gqkv, 256>>>(xn, Wq, bq, Wk, bk, Wv, bv, q, k, v);

    // 3) hash + rope + expmap0 + transpose
    prep_kernel<<<M_, 256>>>(q, k, v, fcos, fsin, c, hasho, qh, kh, vt);

    // 4) sliding-window Poincaré attention (persistent, 2 CTAs/SM)
    attn2_kernel<<<304, 256>>>(qh, kh, vt, c, geo, attn);

    // 5) Wo projection + residual(x)
    dim3 g512(DIM_ / 64, M_ / 128);
    k_gemm<1><<<g512, 256>>>(attn, Wo, bo, x, xout, DIM_, DIM_);

    // 6) LN2
    ln_kernel<<<M_, 128>>>(xout, ln2s, ln2b, hh);

    // 7) FFN1 + gelu
    dim3 gffn1(DFF_ / 64, M_ / 128);
    k_gemm<2><<<gffn1, 256>>>(hh, W1, b1, nullptr, mid, DFF_, DIM_);

    // 8) FFN2 + residual(x_out) -> out
    k_gemm<1><<<g512, 256>>>(mid, W2, b2, xout, out, DIM_, DFF_);
}

// round 8
// speedup vs baseline: 1.6231x; 1.3966x over previous
#include <cuda_runtime.h>
#include <cuda_bf16.h>
#include <cuda_fp16.h>
#include <math.h>
#include <cstdint>

#define B_    2
#define N_    1024
#define DIM_  512
#define NH_   8
#define HD_   64
#define WIN_  64
#define M_    (B_ * N_)      // 2048
#define DFF_  (4 * DIM_)     // 2048
#define EPSV  1e-7f

// ------------------------ scratch (device globals; no allocation) ------------
__device__ float g_xn  [M_ * DIM_];
__device__ float g_q   [M_ * DIM_];
__device__ float g_k   [M_ * DIM_];
__device__ float g_v   [M_ * DIM_];
__device__ float g_qh  [B_ * NH_ * N_ * HD_];
__device__ float g_kh  [B_ * NH_ * N_ * HD_];
__device__ float g_vt  [B_ * NH_ * N_ * HD_];
__device__ float g_attn[M_ * DIM_];
__device__ float g_xout[M_ * DIM_];
__device__ float g_h   [M_ * DIM_];
__device__ float g_mid [M_ * DFF_];

// ------------------------ helpers -------------------------------------------
__device__ __forceinline__ float warpsum(float v) {
#pragma unroll
    for (int o = 16; o > 0; o >>= 1) v += __shfl_xor_sync(0xffffffffu, v, o);
    return v;
}
__device__ __forceinline__ float warpmax(float v) {
#pragma unroll
    for (int o = 16; o > 0; o >>= 1) v = fmaxf(v, __shfl_xor_sync(0xffffffffu, v, o));
    return v;
}
__device__ __forceinline__ float sqrt_fast(float x) {
    float r;
    asm("sqrt.approx.f32 %0, %1;" : "=f"(r) : "f"(x));
    return r;
}
__device__ __forceinline__ uint32_t packh2(float lo, float hi) {
    __half2 h = __floats2half2_rn(lo, hi);
    return *(uint32_t*)&h;
}
// fp16 tensor-core mma: D(f32) += A(f16,16x16) * B(f16,16x8)
__device__ __forceinline__ void mma_f16(float4& c, uint32_t a0, uint32_t a1,
                                        uint32_t a2, uint32_t a3,
                                        uint32_t b0, uint32_t b1) {
    asm volatile(
        "mma.sync.aligned.m16n8k16.row.col.f32.f16.f16.f32 "
        "{%0,%1,%2,%3},{%4,%5,%6,%7},{%8,%9},{%0,%1,%2,%3};\n"
        : "+f"(c.x), "+f"(c.y), "+f"(c.z), "+f"(c.w)
        : "r"(a0), "r"(a1), "r"(a2), "r"(a3), "r"(b0), "r"(b1));
}

// ------------------------ layernorm -----------------------------------------
__global__ void ln_kernel(const float* __restrict__ x, const float* __restrict__ s,
                          const float* __restrict__ bsh, float* __restrict__ out) {
    int row = blockIdx.x;
    const float* xr = x + (size_t)row * DIM_;
    float v[4];
    float sum = 0.f, sq = 0.f;
#pragma unroll
    for (int i = 0; i < 4; i++) {
        v[i] = xr[threadIdx.x + i * 128];
        sum += v[i];
        sq  += v[i] * v[i];
    }
    __shared__ float red0[4], red1[4];
    sum = warpsum(sum); sq = warpsum(sq);
    int warp = threadIdx.x >> 5, lane = threadIdx.x & 31;
    if (lane == 0) { red0[warp] = sum; red1[warp] = sq; }
    __syncthreads();
    sum = red0[0] + red0[1] + red0[2] + red0[3];
    sq  = red1[0] + red1[1] + red1[2] + red1[3];
    float mean = sum * (1.0f / DIM_);
    float var  = sq * (1.0f / DIM_) - mean * mean;
    float inv  = rsqrtf(var + 1e-6f);
    float* orow = out + (size_t)row * DIM_;
#pragma unroll
    for (int i = 0; i < 4; i++) {
        int d = threadIdx.x + i * 128;
        orow[d] = (v[i] - mean) * inv * s[d] + bsh[d];
    }
}

// ------------------------ fp16 tensor-core GEMM ------------------------------
// BM=128 BN=64 BK=32(halves), 256 thr = 8 warps (4x2), warp tile 32x32.
// Per k16-step: 8 mma m16n8k16 + 8 LDS.64 per warp; 2 steps per K-tile.
// Ping-pong double buffer, ONE __syncthreads per K-tile. fp32->fp16 RN at STS.
// Smem layout: uint2 = (half2 k={2tg,2tg+1}, half2 k={2tg+8,2tg+9}) per row/col.
// tg-plane stride 132 entries (=1056B ≡ 32 mod 128) -> conflict-free LDS.64.
struct GSmem {
    uint2 Ap[2][2][4][132];  // [buf][ks16][tg][row]
    uint2 Bp[2][2][4][68];   // [buf][ks16][tg][col]
};

// EPI: 0 = +bias, 1 = +bias+residual, 2 = gelu(+bias)
template <int EPI>
__device__ __forceinline__ void gemm_core(
    const float* __restrict__ A, const float* __restrict__ Bw,
    const float* __restrict__ bias, const float* __restrict__ res,
    float* __restrict__ C, int Nd, int Kd) {
    __shared__ GSmem sm;
    const int m0 = blockIdx.y * 128, n0 = blockIdx.x * 64;
    const int tid = threadIdx.x;                 // 0..255
    const int lane = tid & 31, wid = tid >> 5;   // 8 warps
    const int g = lane >> 2, tg = lane & 3;
    const int wm = wid >> 1, wn = wid & 1;       // warp grid 4x2

    // A loader: row = tid>>1, k-half kh = tid&1 (16 floats each)
    const int arow = tid >> 1, akh = tid & 1;
    const float* aPtr = A + (size_t)(m0 + arow) * Kd + akh * 16;
    // B loader: k-row = tid>>3, col group = (tid&7)*8 (8 floats)
    const int bkr = tid >> 3, bcg = (tid & 7) * 8;
    const float* bPtr = Bw + (size_t)bkr * Nd + n0 + bcg;
    const int bks = bkr >> 4, bw16 = bkr & 15;
    const int btg = (bw16 < 8) ? (bw16 >> 1) : ((bw16 - 8) >> 1);
    const int bidx = ((bw16 < 8) ? 0 : 2) + (bw16 & 1);  // half index in uint2

    float4 acc[2][4];
#pragma unroll
    for (int i = 0; i < 2; i++)
#pragma unroll
        for (int j = 0; j < 4; j++) acc[i][j] = make_float4(0.f, 0.f, 0.f, 0.f);

    float4 af[4];  // 16 floats of A
    float4 bf[2];  // 8 floats of B
#pragma unroll
    for (int j = 0; j < 4; j++) af[j] = *(const float4*)(aPtr + j * 4);
    bf[0] = *(const float4*)(bPtr);
    bf[1] = *(const float4*)(bPtr + 4);

    auto store_tile = [&](int buf) {
        const float* f = (const float*)af;
#pragma unroll
        for (int t4 = 0; t4 < 4; t4++)
            sm.Ap[buf][akh][t4][arow] =
                make_uint2(packh2(f[2 * t4], f[2 * t4 + 1]),
                           packh2(f[2 * t4 + 8], f[2 * t4 + 9]));
        const float* fb = (const float*)bf;
#pragma unroll
        for (int j = 0; j < 8; j++)
            ((__half*)&sm.Bp[buf][bks][btg][bcg + j])[bidx] = __float2half_rn(fb[j]);
    };

    store_tile(0);
    __syncthreads();

    const int nT = Kd >> 5;
    for (int t = 0; t < nT; t++) {
        const int buf = t & 1;
        const bool more = (t + 1 < nT);
        if (more) {  // prefetch next K-tile (returns under MMAs below)
            const float* ap = aPtr + (t + 1) * 32;
#pragma unroll
            for (int j = 0; j < 4; j++) af[j] = *(const float4*)(ap + j * 4);
            const float* bp = bPtr + (size_t)(t + 1) * 32 * Nd;
            bf[0] = *(const float4*)(bp);
            bf[1] = *(const float4*)(bp + 4);
        }
#pragma unroll
        for (int ks = 0; ks < 2; ks++) {
            uint2 alo[2], ahi[2], bb[4];
#pragma unroll
            for (int mi = 0; mi < 2; mi++) {
                alo[mi] = sm.Ap[buf][ks][tg][wm * 32 + mi * 16 + g];
                ahi[mi] = sm.Ap[buf][ks][tg][wm * 32 + mi * 16 + g + 8];
            }
#pragma unroll
            for (int nj = 0; nj < 4; nj++)
                bb[nj] = sm.Bp[buf][ks][tg][wn * 32 + nj * 8 + g];
#pragma unroll
            for (int mi = 0; mi < 2; mi++)
#pragma unroll
                for (int nj = 0; nj < 4; nj++)
                    mma_f16(acc[mi][nj],
                            alo[mi].x, ahi[mi].x, alo[mi].y, ahi[mi].y,
                            bb[nj].x, bb[nj].y);
        }
        if (more) store_tile(buf ^ 1);  // other buffer: no extra barrier
        __syncthreads();
    }

#pragma unroll
    for (int mi = 0; mi < 2; mi++) {
        int r0 = m0 + wm * 32 + mi * 16 + g;
#pragma unroll
        for (int nj = 0; nj < 4; nj++) {
            int col = n0 + wn * 32 + nj * 8 + tg * 2;
            float2 bbv = *(const float2*)(bias + col);
            float4 a = acc[mi][nj];
            float2 o0 = make_float2(a.x + bbv.x, a.y + bbv.y);
            float2 o1 = make_float2(a.z + bbv.x, a.w + bbv.y);
            if (EPI == 1) {
                float2 r0v = *(const float2*)(res + (size_t)r0 * Nd + col);
                float2 r1v = *(const float2*)(res + (size_t)(r0 + 8) * Nd + col);
                o0.x += r0v.x; o0.y += r0v.y;
                o1.x += r1v.x; o1.y += r1v.y;
            }
            if (EPI == 2) {
                float t0 = o0.x, t1 = o0.y, t2 = o1.x, t3 = o1.y;
                o0.x = t0 / (1.f + __expf(-1.5957691216057308f * (t0 + 0.044715f * t0 * t0 * t0)));
                o0.y = t1 / (1.f + __expf(-1.5957691216057308f * (t1 + 0.044715f * t1 * t1 * t1)));
                o1.x = t2 / (1.f + __expf(-1.5957691216057308f * (t2 + 0.044715f * t2 * t2 * t2)));
                o1.y = t3 / (1.f + __expf(-1.5957691216057308f * (t3 + 0.044715f * t3 * t3 * t3)));
            }
            *(float2*)(C + (size_t)r0 * Nd + col)       = o0;
            *(float2*)(C + (size_t)(r0 + 8) * Nd + col) = o1;
        }
    }
}

__global__ __launch_bounds__(256, 3) void k_gemm_qkv(
    const float* __restrict__ xn,
    const float* __restrict__ Wq, const float* __restrict__ bq,
    const float* __restrict__ Wk, const float* __restrict__ bk,
    const float* __restrict__ Wv, const float* __restrict__ bv,
    float* __restrict__ q, float* __restrict__ k, float* __restrict__ v) {
    int z = blockIdx.z;
    const float* W  = (z == 0) ? Wq : (z == 1) ? Wk : Wv;
    const float* bb = (z == 0) ? bq : (z == 1) ? bk : bv;
    float* o        = (z == 0) ? q  : (z == 1) ? k  : v;
    gemm_core<0>(xn, W, bb, nullptr, o, DIM_, DIM_);
}

template <int EPI>
__global__ __launch_bounds__(256, 3) void k_gemm(
    const float* __restrict__ A, const float* __restrict__ W,
    const float* __restrict__ bias, const float* __restrict__ res,
    float* __restrict__ C, int Nd, int Kd) {
    gemm_core<EPI>(A, W, bias, res, C, Nd, Kd);
}

// ------------------------ prep: hash + rope + expmap0 + transpose ------------
__global__ void prep_kernel(const float* __restrict__ qb, const float* __restrict__ kb,
                            const float* __restrict__ vb, const float* __restrict__ cos_t,
                            const float* __restrict__ sin_t, const float* __restrict__ c_arr,
                            const float* __restrict__ hash_off,
                            float* __restrict__ qh, float* __restrict__ kh,
                            float* __restrict__ vt) {
    int bn = blockIdx.x;
    int b = bn / N_, n = bn % N_;
    int h = threadIdx.x >> 5, lane = threadIdx.x & 31;
    const float LOG9 = 2.1972245773362196f;
    float cs = cos_t[n * 32 + lane];
    float sn = sin_t[n * 32 + lane];
    float cb = c_arr[b];
    float sqrt_c = fmaxf(sqrtf(cb), EPSV);
    size_t in_off  = (size_t)bn * DIM_ + h * HD_;
    size_t out_off = (((size_t)(b * NH_ + h)) * N_ + n) * HD_;

    {
        float v0 = qb[in_off + lane]      + hash_off[h * HD_ + lane]      * LOG9;
        float v1 = qb[in_off + lane + 32] + hash_off[h * HD_ + lane + 32] * LOG9;
        float r0 = v0 * cs - v1 * sn;
        float r1 = v0 * sn + v1 * cs;
        float nrm = sqrtf(warpsum(r0 * r0 + r1 * r1));
        float o0 = 0.f, o1 = 0.f;
        if (nrm >= EPSV) {
            float safe = fmaxf(nrm, EPSV);
            float mag  = tanhf(sqrt_c * safe) / sqrt_c;
            float sc   = mag / safe;
            o0 = sc * r0; o1 = sc * r1;
        }
        qh[out_off + lane] = o0; qh[out_off + lane + 32] = o1;
    }
    {
        float v0 = kb[in_off + lane];
        float v1 = kb[in_off + lane + 32];
        float r0 = v0 * cs - v1 * sn;
        float r1 = v0 * sn + v1 * cs;
        float nrm = sqrtf(warpsum(r0 * r0 + r1 * r1));
        float o0 = 0.f, o1 = 0.f;
        if (nrm >= EPSV) {
            float safe = fmaxf(nrm, EPSV);
            float mag  = tanhf(sqrt_c * safe) / sqrt_c;
            float sc   = mag / safe;
            o0 = sc * r0; o1 = sc * r1;
        }
        kh[out_off + lane] = o0; kh[out_off + lane + 32] = o1;
    }
    vt[out_off + lane]      = vb[in_off + lane];
    vt[out_off + lane + 32] = vb[in_off + lane + 32];
}

// ------------------------ windowed Poincaré attention (persistent) -----------
#define QT2    16
#define KR2    (QT2 + WIN_ - 1)   // 79
#define KS_STR 65
#define QS_STR 68
#define SW_STR 65
#define NTILES ((N_ / QT2) * B_ * NH_)   // 1024
#define RMIN_  5.0000003e-8f             // (1e-7)/(2-1e-7)

__global__ __launch_bounds__(256) void attn2_kernel(
    const float* __restrict__ qh, const float* __restrict__ kh,
    const float* __restrict__ vt, const float* __restrict__ c_arr,
    const float* __restrict__ geo, float* __restrict__ attn_out) {
    __shared__ __align__(16) float Ks[KR2 * KS_STR + 16];  // K tile; reused for V
    __shared__ __align__(16) float Qs[QT2 * QS_STR];
    __shared__ __align__(16) float Sw[QT2 * SW_STR];
    __shared__ float y2s[KR2 + 1];

    const int tid = threadIdx.x;
    const int w = tid >> 5, l = tid & 31;
    const int qi = tid >> 4;
    const int kg = tid & 15;

    for (int t = blockIdx.x; t < NTILES; t += gridDim.x) {
        const int bh = t >> 6;
        const int b = bh >> 3, h = bh & 7;
        const int n0 = (t & 63) << 4;
        const float* Kb = kh + (size_t)bh * (N_ * HD_);
        const float* Vb = vt + (size_t)bh * (N_ * HD_);
        const float* Qb = qh + (size_t)bh * (N_ * HD_);

#pragma unroll
        for (int i = 0; i < 5; i++) {
            int f = tid + i * 256;
            if (f < KR2 * 16) {
                int row = f >> 4, c4 = (f & 15) << 2;
                int gn = n0 - (WIN_ - 1) + row;
                float4 val = make_float4(0.f, 0.f, 0.f, 0.f);
                if (gn >= 0) val = *(const float4*)(Kb + (size_t)gn * HD_ + c4);
                float* d = &Ks[row * KS_STR + c4];
                d[0] = val.x; d[1] = val.y; d[2] = val.z; d[3] = val.w;
            }
        }
        {
            int row = tid >> 4, c4 = (tid & 15) << 2;
            *(float4*)&Qs[row * QS_STR + c4] =
                *(const float4*)(Qb + (size_t)(n0 + row) * HD_ + c4);
        }
        float4 vreg[5];
#pragma unroll
        for (int i = 0; i < 5; i++) {
            int f = tid + i * 256;
            vreg[i] = make_float4(0.f, 0.f, 0.f, 0.f);
            if (f < KR2 * 16) {
                int row = f >> 4, c4 = (f & 15) << 2;
                int gn = n0 - (WIN_ - 1) + row;
                if (gn >= 0) vreg[i] = *(const float4*)(Vb + (size_t)gn * HD_ + c4);
            }
        }
        __syncthreads();

        for (int row = w; row < KR2; row += 8) {
            float a = Ks[row * KS_STR + l];
            float bq = Ks[row * KS_STR + 32 + l];
            float s = warpsum(a * a + bq * bq);
            if (l == 0) y2s[row] = s;
        }
        __syncthreads();

        const float cb = c_arr[b];
        const float sc = fmaxf(sqrtf(cb), EPSV);
        const float gs = geo[h];
        const float p2 = gs / sc;
        const float cc = cb * cb;

        float xy0 = 0.f, xy1 = 0.f, xy2 = 0.f, xy3 = 0.f, q2 = 0.f;
        {
            const float* qrow = &Qs[qi * QS_STR];
            const float* kr = &Ks[(qi + kg) * KS_STR];
#pragma unroll 8
            for (int d = 0; d < HD_; d++) {
                float qv = qrow[d];
                q2  = fmaf(qv, qv, q2);
                xy0 = fmaf(qv, kr[d], xy0);
                xy1 = fmaf(qv, kr[d + 16 * KS_STR], xy1);
                xy2 = fmaf(qv, kr[d + 32 * KS_STR], xy2);
                xy3 = fmaf(qv, kr[d + 48 * KS_STR], xy3);
            }
        }
        {
            const float Bc = 1.f - cb * q2;
            const float c2x2 = cc * q2;
            float xys[4] = {xy0, xy1, xy2, xy3};
#pragma unroll
            for (int j = 0; j < 4; j++) {
                float xy = xys[j];
                float y2 = y2s[qi + kg + 16 * j];
                float u  = fmaf(-2.f * cb, xy, 1.f);
                float A  = fmaf(cb, y2, u);
                float dn2 = fmaf(A * A, q2, fmaf(Bc * Bc, y2, -2.f * A * Bc * xy));
                float den = fmaxf(fmaf(c2x2, y2, u), EPSV);
                float s   = sc * sqrt_fast(fmaxf(dn2, 0.f));
                float ratio = __fdividef(den - s, den + s);
                ratio = fmaxf(ratio, RMIN_);
                Sw[qi * SW_STR + kg + 16 * j] = p2 * __log2f(ratio);
            }
        }
        __syncthreads();

#pragma unroll
        for (int qq = 0; qq < 2; qq++) {
            int q = w + qq * 8;
            float s0 = Sw[q * SW_STR + l];
            float s1 = Sw[q * SW_STR + 32 + l];
            float m = warpmax(fmaxf(s0, s1));
            float e0 = exp2f(s0 - m), e1 = exp2f(s1 - m);
            float inv = __fdividef(1.f, warpsum(e0 + e1));
            Sw[q * SW_STR + l] = e0 * inv;
            Sw[q * SW_STR + 32 + l] = e1 * inv;
        }
        __syncthreads();

#pragma unroll
        for (int i = 0; i < 5; i++) {
            int f = tid + i * 256;
            if (f < KR2 * 16) {
                int row = f >> 4, c4 = (f & 15) << 2;
                *(float4*)&Ks[row * HD_ + c4] = vreg[i];
            }
        }
        __syncthreads();

        {
            const int dg = tid & 15;
            float4 acc = make_float4(0.f, 0.f, 0.f, 0.f);
            const float* wrow = &Sw[qi * SW_STR];
            const float* vbase = &Ks[qi * HD_ + dg * 4];
#pragma unroll 8
            for (int k = 0; k < WIN_; k++) {
                float wk = wrow[k];
                float4 vv = *(const float4*)(vbase + k * HD_);
                acc.x = fmaf(wk, vv.x, acc.x);
                acc.y = fmaf(wk, vv.y, acc.y);
                acc.z = fmaf(wk, vv.z, acc.z);
                acc.w = fmaf(wk, vv.w, acc.w);
            }
            float* orow = attn_out + ((size_t)(b * N_ + n0 + qi)) * DIM_ + h * HD_ + dg * 4;
            *(float4*)orow = acc;
        }
        __syncthreads();
    }
}

// ------------------------ launch --------------------------------------------
extern "C" void kernel_launch(void* const* d_in, const int* in_sizes, int n_in,
                              void* d_out, int out_size) {
    (void)in_sizes; (void)n_in; (void)out_size;
    const float* x     = (const float*)d_in[0];
    const float* fcos  = (const float*)d_in[1];
    const float* fsin  = (const float*)d_in[2];
    const float* c     = (const float*)d_in[3];
    const float* Wq    = (const float*)d_in[4];
    const float* bq    = (const float*)d_in[5];
    const float* Wk    = (const float*)d_in[6];
    const float* bk    = (const float*)d_in[7];
    const float* Wv    = (const float*)d_in[8];
    const float* bv    = (const float*)d_in[9];
    const float* Wo    = (const float*)d_in[10];
    const float* bo    = (const float*)d_in[11];
    const float* W1    = (const float*)d_in[12];
    const float* b1    = (const float*)d_in[13];
    const float* W2    = (const float*)d_in[14];
    const float* b2    = (const float*)d_in[15];
    const float* ln1s  = (const float*)d_in[16];
    const float* ln1b  = (const float*)d_in[17];
    const float* ln2s  = (const float*)d_in[18];
    const float* ln2b  = (const float*)d_in[19];
    const float* geo   = (const float*)d_in[20];
    const float* hasho = (const float*)d_in[21];
    float* out = (float*)d_out;

    float *xn, *q, *k, *v, *qh, *kh, *vt, *attn, *xout, *hh, *mid;
    cudaGetSymbolAddress((void**)&xn,   g_xn);
    cudaGetSymbolAddress((void**)&q,    g_q);
    cudaGetSymbolAddress((void**)&k,    g_k);
    cudaGetSymbolAddress((void**)&v,    g_v);
    cudaGetSymbolAddress((void**)&qh,   g_qh);
    cudaGetSymbolAddress((void**)&kh,   g_kh);
    cudaGetSymbolAddress((void**)&vt,   g_vt);
    cudaGetSymbolAddress((void**)&attn, g_attn);
    cudaGetSymbolAddress((void**)&xout, g_xout);
    cudaGetSymbolAddress((void**)&hh,   g_h);
    cudaGetSymbolAddress((void**)&mid,  g_mid);

    // 1) LN1
    ln_kernel<<<M_, 128>>>(x, ln1s, ln1b, xn);

    // 2) fused QKV projections (384 CTAs x 256 thr)
    dim3 gqkv(DIM_ / 64, M_ / 128, 3);
    k_gemm_qkv<<<gqkv, 256>>>(xn, Wq, bq, Wk, bk, Wv, bv, q, k, v);

    // 3) hash + rope + expmap0 + transpose
    prep_kernel<<<M_, 256>>>(q, k, v, fcos, fsin, c, hasho, qh, kh, vt);

    // 4) sliding-window Poincaré attention (persistent, 2 CTAs/SM)
    attn2_kernel<<<304, 256>>>(qh, kh, vt, c, geo, attn);

    // 5) Wo projection + residual(x)
    dim3 g512(DIM_ / 64, M_ / 128);
    k_gemm<1><<<g512, 256>>>(attn, Wo, bo, x, xout, DIM_, DIM_);

    // 6) LN2
    ln_kernel<<<M_, 128>>>(xout, ln2s, ln2b, hh);

    // 7) FFN1 + gelu
    dim3 gffn1(DFF_ / 64, M_ / 128);
    k_gemm<2><<<gffn1, 256>>>(hh, W1, b1, nullptr, mid, DFF_, DIM_);

    // 8) FFN2 + residual(x_out) -> out
    k_gemm<1><<<g512, 256>>>(mid, W2, b2, xout, out, DIM_, DFF_);
}

// round 10
// speedup vs baseline: 2.3893x; 1.4721x over previous
#include <cuda_runtime.h>
#include <cuda_bf16.h>
#include <cuda_fp16.h>
#include <math.h>
#include <cstdint>

#define B_    2
#define N_    1024
#define DIM_  512
#define NH_   8
#define HD_   64
#define WIN_  64
#define M_    (B_ * N_)      // 2048
#define DFF_  (4 * DIM_)     // 2048
#define EPSV  1e-7f

// ------------------------ scratch (device globals; no allocation) ------------
__device__ __half g_xnh [M_ * DIM_];    // LN1 out (half)
__device__ float  g_q   [M_ * DIM_];
__device__ float  g_k   [M_ * DIM_];
__device__ float  g_v   [M_ * DIM_];
__device__ float  g_qh  [B_ * NH_ * N_ * HD_];
__device__ float  g_kh  [B_ * NH_ * N_ * HD_];
__device__ float  g_vt  [B_ * NH_ * N_ * HD_];
__device__ __half g_attnh[M_ * DIM_];   // attention out (half)
__device__ float  g_xout[M_ * DIM_];
__device__ __half g_hhh [M_ * DIM_];    // LN2 out (half)
__device__ __half g_midh[M_ * DFF_];    // FFN mid (half)
// half weights, concatenated
#define WH_Q 0
#define WH_K 262144
#define WH_V 524288
#define WH_O 786432
#define WH_1 1048576
#define WH_2 2097152
__device__ __half g_wh[3145728];

// ------------------------ helpers -------------------------------------------
__device__ __forceinline__ float warpsum(float v) {
#pragma unroll
    for (int o = 16; o > 0; o >>= 1) v += __shfl_xor_sync(0xffffffffu, v, o);
    return v;
}
__device__ __forceinline__ float warpmax(float v) {
#pragma unroll
    for (int o = 16; o > 0; o >>= 1) v = fmaxf(v, __shfl_xor_sync(0xffffffffu, v, o));
    return v;
}
__device__ __forceinline__ float sqrt_fast(float x) {
    float r;
    asm("sqrt.approx.f32 %0, %1;" : "=f"(r) : "f"(x));
    return r;
}
__device__ __forceinline__ uint32_t packh2(float lo, float hi) {
    __half2 h = __floats2half2_rn(lo, hi);
    return *(uint32_t*)&h;
}
// fp16 tensor-core mma: D(f32) += A(f16,16x16) * B(f16,16x8)
__device__ __forceinline__ void mma_f16(float4& c, uint32_t a0, uint32_t a1,
                                        uint32_t a2, uint32_t a3,
                                        uint32_t b0, uint32_t b1) {
    asm volatile(
        "mma.sync.aligned.m16n8k16.row.col.f32.f16.f16.f32 "
        "{%0,%1,%2,%3},{%4,%5,%6,%7},{%8,%9},{%0,%1,%2,%3};\n"
        : "+f"(c.x), "+f"(c.y), "+f"(c.z), "+f"(c.w)
        : "r"(a0), "r"(a1), "r"(a2), "r"(a3), "r"(b0), "r"(b1));
}

// ------------------------ weight fp32 -> fp16 convert ------------------------
__global__ __launch_bounds__(256) void cvt_w_kernel(
    const float* __restrict__ Wq, const float* __restrict__ Wk,
    const float* __restrict__ Wv, const float* __restrict__ Wo,
    const float* __restrict__ W1, const float* __restrict__ W2,
    __half* __restrict__ out) {
    long i = ((long)blockIdx.x * 256 + threadIdx.x) * 4;   // 4 elems/thread
    if (i >= 3145728) return;
    const float* src;
    long off;
    if      (i <  262144) { src = Wq; off = i; }
    else if (i <  524288) { src = Wk; off = i - 262144; }
    else if (i <  786432) { src = Wv; off = i - 524288; }
    else if (i < 1048576) { src = Wo; off = i - 786432; }
    else if (i < 2097152) { src = W1; off = i - 1048576; }
    else                  { src = W2; off = i - 2097152; }
    float4 v = *(const float4*)(src + off);
    uint2 o = make_uint2(packh2(v.x, v.y), packh2(v.z, v.w));
    *(uint2*)(out + i) = o;
}

// ------------------------ layernorm (half output) ----------------------------
__global__ void ln_kernel(const float* __restrict__ x, const float* __restrict__ s,
                          const float* __restrict__ bsh, __half* __restrict__ out) {
    int row = blockIdx.x;
    const float* xr = x + (size_t)row * DIM_;
    float v[4];
    float sum = 0.f, sq = 0.f;
#pragma unroll
    for (int i = 0; i < 4; i++) {
        v[i] = xr[threadIdx.x + i * 128];
        sum += v[i];
        sq  += v[i] * v[i];
    }
    __shared__ float red0[4], red1[4];
    sum = warpsum(sum); sq = warpsum(sq);
    int warp = threadIdx.x >> 5, lane = threadIdx.x & 31;
    if (lane == 0) { red0[warp] = sum; red1[warp] = sq; }
    __syncthreads();
    sum = red0[0] + red0[1] + red0[2] + red0[3];
    sq  = red1[0] + red1[1] + red1[2] + red1[3];
    float mean = sum * (1.0f / DIM_);
    float var  = sq * (1.0f / DIM_) - mean * mean;
    float inv  = rsqrtf(var + 1e-6f);
    __half* orow = out + (size_t)row * DIM_;
#pragma unroll
    for (int i = 0; i < 4; i++) {
        int d = threadIdx.x + i * 128;
        orow[d] = __float2half_rn((v[i] - mean) * inv * s[d] + bsh[d]);
    }
}

// ------------------------ fp16 tensor-core GEMM (half in) --------------------
// BM=128 BN=64 BK=32, 256 thr = 8 warps (4x2), warp tile 32x32.
// A/B in gmem are ALREADY fp16 -> loaders are pure movement:
//   A: thread (row, khalf) loads 16 halves (2x LDG.128), stores 4x STS.64
//      pre-paired: uint2 = (half2 k={2t4,2t4+1}, half2 k={2t4+8,2t4+9}).
//   B: thread (ks, tg, colpair) loads rows {2tg,2tg+1,2tg+8,2tg+9} x 2 cols
//      (4x LDG.32), interleaves via PRMT, stores 1x STS.128 (2 cols).
// Ping-pong double buffer, ONE __syncthreads per K-tile.
struct GSmem {
    uint2 Ap[2][2][4][132];  // [buf][ks16][tg][row]
    uint2 Bp[2][2][4][68];   // [buf][ks16][tg][col]
};

// EPI: 0 = +bias (f32 out), 1 = +bias+residual (f32 out), 2 = gelu+bias (HALF out)
template <int EPI>
__device__ __forceinline__ void gemm_core(
    const __half* __restrict__ A, const __half* __restrict__ Bw,
    const float* __restrict__ bias, const float* __restrict__ res,
    void* __restrict__ Cv, int Nd, int Kd) {
    __shared__ GSmem sm;
    const int m0 = blockIdx.y * 128, n0 = blockIdx.x * 64;
    const int tid = threadIdx.x;                 // 0..255
    const int lane = tid & 31, wid = tid >> 5;   // 8 warps
    const int g = lane >> 2, tg = lane & 3;
    const int wm = wid >> 1, wn = wid & 1;       // warp grid 4x2

    // A loader: row = tid>>1, k-half = tid&1 (16 halves = 32B)
    const int arow = tid >> 1, akh = tid & 1;
    const __half* aPtr = A + (size_t)(m0 + arow) * Kd + akh * 16;
    // B loader: ks = tid>>7, tg' = (tid>>5)&3, colpair = tid&31
    const int bks = tid >> 7, btg = (tid >> 5) & 3, bcp = tid & 31;
    const __half* bPtr = Bw + (size_t)(bks * 16 + 2 * btg) * Nd + n0 + 2 * bcp;

    float4 acc[2][4];
#pragma unroll
    for (int i = 0; i < 2; i++)
#pragma unroll
        for (int j = 0; j < 4; j++) acc[i][j] = make_float4(0.f, 0.f, 0.f, 0.f);

    uint4 alo, ahi;
    uint32_t w0, w1, w2, w3;
    alo = *(const uint4*)(aPtr);
    ahi = *(const uint4*)(aPtr + 8);
    w0 = *(const uint32_t*)(bPtr);
    w1 = *(const uint32_t*)(bPtr + Nd);
    w2 = *(const uint32_t*)(bPtr + 8 * Nd);
    w3 = *(const uint32_t*)(bPtr + 9 * Nd);

    auto store_tile = [&](int buf) {
        // A: word t4 of alo = halves (2t4, 2t4+1); of ahi = (2t4+8, 2t4+9)
        sm.Ap[buf][akh][0][arow] = make_uint2(alo.x, ahi.x);
        sm.Ap[buf][akh][1][arow] = make_uint2(alo.y, ahi.y);
        sm.Ap[buf][akh][2][arow] = make_uint2(alo.z, ahi.z);
        sm.Ap[buf][akh][3][arow] = make_uint2(alo.w, ahi.w);
        // B: interleave rows into per-column (k,k+1) pairs
        uint32_t lo0 = __byte_perm(w0, w1, 0x5410);  // col 2cp,   k pair low
        uint32_t lo1 = __byte_perm(w0, w1, 0x7632);  // col 2cp+1, k pair low
        uint32_t hi0 = __byte_perm(w2, w3, 0x5410);  // col 2cp,   k pair high
        uint32_t hi1 = __byte_perm(w2, w3, 0x7632);
        *(uint4*)&sm.Bp[buf][bks][btg][2 * bcp] = make_uint4(lo0, hi0, lo1, hi1);
    };

    store_tile(0);
    __syncthreads();

    const int nT = Kd >> 5;
    for (int t = 0; t < nT; t++) {
        const int buf = t & 1;
        const bool more = (t + 1 < nT);
        if (more) {  // prefetch next K-tile
            const __half* ap = aPtr + (t + 1) * 32;
            alo = *(const uint4*)(ap);
            ahi = *(const uint4*)(ap + 8);
            const __half* bp = bPtr + (size_t)(t + 1) * 32 * Nd;
            w0 = *(const uint32_t*)(bp);
            w1 = *(const uint32_t*)(bp + Nd);
            w2 = *(const uint32_t*)(bp + 8 * Nd);
            w3 = *(const uint32_t*)(bp + 9 * Nd);
        }
#pragma unroll
        for (int ks = 0; ks < 2; ks++) {
            uint2 fal[2], fah[2], fb[4];
#pragma unroll
            for (int mi = 0; mi < 2; mi++) {
                fal[mi] = sm.Ap[buf][ks][tg][wm * 32 + mi * 16 + g];
                fah[mi] = sm.Ap[buf][ks][tg][wm * 32 + mi * 16 + g + 8];
            }
#pragma unroll
            for (int nj = 0; nj < 4; nj++)
                fb[nj] = sm.Bp[buf][ks][tg][wn * 32 + nj * 8 + g];
#pragma unroll
            for (int mi = 0; mi < 2; mi++)
#pragma unroll
                for (int nj = 0; nj < 4; nj++)
                    mma_f16(acc[mi][nj],
                            fal[mi].x, fah[mi].x, fal[mi].y, fah[mi].y,
                            fb[nj].x, fb[nj].y);
        }
        if (more) store_tile(buf ^ 1);
        __syncthreads();
    }

#pragma unroll
    for (int mi = 0; mi < 2; mi++) {
        int r0 = m0 + wm * 32 + mi * 16 + g;
#pragma unroll
        for (int nj = 0; nj < 4; nj++) {
            int col = n0 + wn * 32 + nj * 8 + tg * 2;
            float2 bbv = *(const float2*)(bias + col);
            float4 a = acc[mi][nj];
            float2 o0 = make_float2(a.x + bbv.x, a.y + bbv.y);
            float2 o1 = make_float2(a.z + bbv.x, a.w + bbv.y);
            if (EPI == 1) {
                float2 r0v = *(const float2*)(res + (size_t)r0 * Nd + col);
                float2 r1v = *(const float2*)(res + (size_t)(r0 + 8) * Nd + col);
                o0.x += r0v.x; o0.y += r0v.y;
                o1.x += r1v.x; o1.y += r1v.y;
            }
            if (EPI == 2) {
                float t0 = o0.x, t1 = o0.y, t2 = o1.x, t3 = o1.y;
                o0.x = t0 / (1.f + __expf(-1.5957691216057308f * (t0 + 0.044715f * t0 * t0 * t0)));
                o0.y = t1 / (1.f + __expf(-1.5957691216057308f * (t1 + 0.044715f * t1 * t1 * t1)));
                o1.x = t2 / (1.f + __expf(-1.5957691216057308f * (t2 + 0.044715f * t2 * t2 * t2)));
                o1.y = t3 / (1.f + __expf(-1.5957691216057308f * (t3 + 0.044715f * t3 * t3 * t3)));
                __half* Ch = (__half*)Cv;
                *(uint32_t*)(Ch + (size_t)r0 * Nd + col)       = packh2(o0.x, o0.y);
                *(uint32_t*)(Ch + (size_t)(r0 + 8) * Nd + col) = packh2(o1.x, o1.y);
            } else {
                float* C = (float*)Cv;
                *(float2*)(C + (size_t)r0 * Nd + col)       = o0;
                *(float2*)(C + (size_t)(r0 + 8) * Nd + col) = o1;
            }
        }
    }
}

__global__ __launch_bounds__(256, 3) void k_gemm_qkv(
    const __half* __restrict__ xn, const __half* __restrict__ wh,
    const float* __restrict__ bq, const float* __restrict__ bk,
    const float* __restrict__ bv,
    float* __restrict__ q, float* __restrict__ k, float* __restrict__ v) {
    int z = blockIdx.z;
    const __half* W  = wh + ((z == 0) ? WH_Q : (z == 1) ? WH_K : WH_V);
    const float* bb  = (z == 0) ? bq : (z == 1) ? bk : bv;
    float* o         = (z == 0) ? q  : (z == 1) ? k  : v;
    gemm_core<0>(xn, W, bb, nullptr, o, DIM_, DIM_);
}

template <int EPI>
__global__ __launch_bounds__(256, 3) void k_gemm(
    const __half* __restrict__ A, const __half* __restrict__ W,
    const float* __restrict__ bias, const float* __restrict__ res,
    void* __restrict__ C, int Nd, int Kd) {
    gemm_core<EPI>(A, W, bias, res, C, Nd, Kd);
}

// ------------------------ prep: hash + rope + expmap0 + transpose ------------
__global__ void prep_kernel(const float* __restrict__ qb, const float* __restrict__ kb,
                            const float* __restrict__ vb, const float* __restrict__ cos_t,
                            const float* __restrict__ sin_t, const float* __restrict__ c_arr,
                            const float* __restrict__ hash_off,
                            float* __restrict__ qh, float* __restrict__ kh,
                            float* __restrict__ vt) {
    int bn = blockIdx.x;
    int b = bn / N_, n = bn % N_;
    int h = threadIdx.x >> 5, lane = threadIdx.x & 31;
    const float LOG9 = 2.1972245773362196f;
    float cs = cos_t[n * 32 + lane];
    float sn = sin_t[n * 32 + lane];
    float cb = c_arr[b];
    float sqrt_c = fmaxf(sqrtf(cb), EPSV);
    size_t in_off  = (size_t)bn * DIM_ + h * HD_;
    size_t out_off = (((size_t)(b * NH_ + h)) * N_ + n) * HD_;

    {
        float v0 = qb[in_off + lane]      + hash_off[h * HD_ + lane]      * LOG9;
        float v1 = qb[in_off + lane + 32] + hash_off[h * HD_ + lane + 32] * LOG9;
        float r0 = v0 * cs - v1 * sn;
        float r1 = v0 * sn + v1 * cs;
        float nrm = sqrtf(warpsum(r0 * r0 + r1 * r1));
        float o0 = 0.f, o1 = 0.f;
        if (nrm >= EPSV) {
            float safe = fmaxf(nrm, EPSV);
            float mag  = tanhf(sqrt_c * safe) / sqrt_c;
            float sc   = mag / safe;
            o0 = sc * r0; o1 = sc * r1;
        }
        qh[out_off + lane] = o0; qh[out_off + lane + 32] = o1;
    }
    {
        float v0 = kb[in_off + lane];
        float v1 = kb[in_off + lane + 32];
        float r0 = v0 * cs - v1 * sn;
        float r1 = v0 * sn + v1 * cs;
        float nrm = sqrtf(warpsum(r0 * r0 + r1 * r1));
        float o0 = 0.f, o1 = 0.f;
        if (nrm >= EPSV) {
            float safe = fmaxf(nrm, EPSV);
            float mag  = tanhf(sqrt_c * safe) / sqrt_c;
            float sc   = mag / safe;
            o0 = sc * r0; o1 = sc * r1;
        }
        kh[out_off + lane] = o0; kh[out_off + lane + 32] = o1;
    }
    vt[out_off + lane]      = vb[in_off + lane];
    vt[out_off + lane + 32] = vb[in_off + lane + 32];
}

// ------------------------ windowed Poincaré attention (persistent) -----------
#define QT2    16
#define KR2    (QT2 + WIN_ - 1)   // 79
#define KS_STR 65
#define QS_STR 68
#define SW_STR 65
#define NTILES ((N_ / QT2) * B_ * NH_)   // 1024
#define RMIN_  5.0000003e-8f             // (1e-7)/(2-1e-7)

__global__ __launch_bounds__(256) void attn2_kernel(
    const float* __restrict__ qh, const float* __restrict__ kh,
    const float* __restrict__ vt, const float* __restrict__ c_arr,
    const float* __restrict__ geo, __half* __restrict__ attn_out) {
    __shared__ __align__(16) float Ks[KR2 * KS_STR + 16];  // K tile; reused for V
    __shared__ __align__(16) float Qs[QT2 * QS_STR];
    __shared__ __align__(16) float Sw[QT2 * SW_STR];
    __shared__ float y2s[KR2 + 1];

    const int tid = threadIdx.x;
    const int w = tid >> 5, l = tid & 31;
    const int qi = tid >> 4;
    const int kg = tid & 15;

    for (int t = blockIdx.x; t < NTILES; t += gridDim.x) {
        const int bh = t >> 6;
        const int b = bh >> 3, h = bh & 7;
        const int n0 = (t & 63) << 4;
        const float* Kb = kh + (size_t)bh * (N_ * HD_);
        const float* Vb = vt + (size_t)bh * (N_ * HD_);
        const float* Qb = qh + (size_t)bh * (N_ * HD_);

#pragma unroll
        for (int i = 0; i < 5; i++) {
            int f = tid + i * 256;
            if (f < KR2 * 16) {
                int row = f >> 4, c4 = (f & 15) << 2;
                int gn = n0 - (WIN_ - 1) + row;
                float4 val = make_float4(0.f, 0.f, 0.f, 0.f);
                if (gn >= 0) val = *(const float4*)(Kb + (size_t)gn * HD_ + c4);
                float* d = &Ks[row * KS_STR + c4];
                d[0] = val.x; d[1] = val.y; d[2] = val.z; d[3] = val.w;
            }
        }
        {
            int row = tid >> 4, c4 = (tid & 15) << 2;
            *(float4*)&Qs[row * QS_STR + c4] =
                *(const float4*)(Qb + (size_t)(n0 + row) * HD_ + c4);
        }
        float4 vreg[5];
#pragma unroll
        for (int i = 0; i < 5; i++) {
            int f = tid + i * 256;
            vreg[i] = make_float4(0.f, 0.f, 0.f, 0.f);
            if (f < KR2 * 16) {
                int row = f >> 4, c4 = (f & 15) << 2;
                int gn = n0 - (WIN_ - 1) + row;
                if (gn >= 0) vreg[i] = *(const float4*)(Vb + (size_t)gn * HD_ + c4);
            }
        }
        __syncthreads();

        for (int row = w; row < KR2; row += 8) {
            float a = Ks[row * KS_STR + l];
            float bq = Ks[row * KS_STR + 32 + l];
            float s = warpsum(a * a + bq * bq);
            if (l == 0) y2s[row] = s;
        }
        __syncthreads();

        const float cb = c_arr[b];
        const float sc = fmaxf(sqrtf(cb), EPSV);
        const float gs = geo[h];
        const float p2 = gs / sc;
        const float cc = cb * cb;

        float xy0 = 0.f, xy1 = 0.f, xy2 = 0.f, xy3 = 0.f, q2 = 0.f;
        {
            const float* qrow = &Qs[qi * QS_STR];
            const float* kr = &Ks[(qi + kg) * KS_STR];
#pragma unroll 8
            for (int d = 0; d < HD_; d++) {
                float qv = qrow[d];
                q2  = fmaf(qv, qv, q2);
                xy0 = fmaf(qv, kr[d], xy0);
                xy1 = fmaf(qv, kr[d + 16 * KS_STR], xy1);
                xy2 = fmaf(qv, kr[d + 32 * KS_STR], xy2);
                xy3 = fmaf(qv, kr[d + 48 * KS_STR], xy3);
            }
        }
        {
            const float Bc = 1.f - cb * q2;
            const float c2x2 = cc * q2;
            float xys[4] = {xy0, xy1, xy2, xy3};
#pragma unroll
            for (int j = 0; j < 4; j++) {
                float xy = xys[j];
                float y2 = y2s[qi + kg + 16 * j];
                float u  = fmaf(-2.f * cb, xy, 1.f);
                float A  = fmaf(cb, y2, u);
                float dn2 = fmaf(A * A, q2, fmaf(Bc * Bc, y2, -2.f * A * Bc * xy));
                float den = fmaxf(fmaf(c2x2, y2, u), EPSV);
                float s   = sc * sqrt_fast(fmaxf(dn2, 0.f));
                float ratio = __fdividef(den - s, den + s);
                ratio = fmaxf(ratio, RMIN_);
                Sw[qi * SW_STR + kg + 16 * j] = p2 * __log2f(ratio);
            }
        }
        __syncthreads();

#pragma unroll
        for (int qq = 0; qq < 2; qq++) {
            int q = w + qq * 8;
            float s0 = Sw[q * SW_STR + l];
            float s1 = Sw[q * SW_STR + 32 + l];
            float m = warpmax(fmaxf(s0, s1));
            float e0 = exp2f(s0 - m), e1 = exp2f(s1 - m);
            float inv = __fdividef(1.f, warpsum(e0 + e1));
            Sw[q * SW_STR + l] = e0 * inv;
            Sw[q * SW_STR + 32 + l] = e1 * inv;
        }
        __syncthreads();

#pragma unroll
        for (int i = 0; i < 5; i++) {
            int f = tid + i * 256;
            if (f < KR2 * 16) {
                int row = f >> 4, c4 = (f & 15) << 2;
                *(float4*)&Ks[row * HD_ + c4] = vreg[i];
            }
        }
        __syncthreads();

        {
            const int dg = tid & 15;
            float4 acc = make_float4(0.f, 0.f, 0.f, 0.f);
            const float* wrow = &Sw[qi * SW_STR];
            const float* vbase = &Ks[qi * HD_ + dg * 4];
#pragma unroll 8
            for (int k = 0; k < WIN_; k++) {
                float wk = wrow[k];
                float4 vv = *(const float4*)(vbase + k * HD_);
                acc.x = fmaf(wk, vv.x, acc.x);
                acc.y = fmaf(wk, vv.y, acc.y);
                acc.z = fmaf(wk, vv.z, acc.z);
                acc.w = fmaf(wk, vv.w, acc.w);
            }
            __half* orow = attn_out + ((size_t)(b * N_ + n0 + qi)) * DIM_ + h * HD_ + dg * 4;
            *(uint2*)orow = make_uint2(packh2(acc.x, acc.y), packh2(acc.z, acc.w));
        }
        __syncthreads();
    }
}

// ------------------------ launch --------------------------------------------
extern "C" void kernel_launch(void* const* d_in, const int* in_sizes, int n_in,
                              void* d_out, int out_size) {
    (void)in_sizes; (void)n_in; (void)out_size;
    const float* x     = (const float*)d_in[0];
    const float* fcos  = (const float*)d_in[1];
    const float* fsin  = (const float*)d_in[2];
    const float* c     = (const float*)d_in[3];
    const float* Wq    = (const float*)d_in[4];
    const float* bq    = (const float*)d_in[5];
    const float* Wk    = (const float*)d_in[6];
    const float* bk    = (const float*)d_in[7];
    const float* Wv    = (const float*)d_in[8];
    const float* bv    = (const float*)d_in[9];
    const float* Wo    = (const float*)d_in[10];
    const float* bo    = (const float*)d_in[11];
    const float* W1    = (const float*)d_in[12];
    const float* b1    = (const float*)d_in[13];
    const float* W2    = (const float*)d_in[14];
    const float* b2    = (const float*)d_in[15];
    const float* ln1s  = (const float*)d_in[16];
    const float* ln1b  = (const float*)d_in[17];
    const float* ln2s  = (const float*)d_in[18];
    const float* ln2b  = (const float*)d_in[19];
    const float* geo   = (const float*)d_in[20];
    const float* hasho = (const float*)d_in[21];
    float* out = (float*)d_out;

    __half *xnh, *attnh, *hhh, *midh, *wh;
    float *q, *k, *v, *qh, *kh, *vt, *xout;
    cudaGetSymbolAddress((void**)&xnh,   g_xnh);
    cudaGetSymbolAddress((void**)&q,     g_q);
    cudaGetSymbolAddress((void**)&k,     g_k);
    cudaGetSymbolAddress((void**)&v,     g_v);
    cudaGetSymbolAddress((void**)&qh,    g_qh);
    cudaGetSymbolAddress((void**)&kh,    g_kh);
    cudaGetSymbolAddress((void**)&vt,    g_vt);
    cudaGetSymbolAddress((void**)&attnh, g_attnh);
    cudaGetSymbolAddress((void**)&xout,  g_xout);
    cudaGetSymbolAddress((void**)&hhh,   g_hhh);
    cudaGetSymbolAddress((void**)&midh,  g_midh);
    cudaGetSymbolAddress((void**)&wh,    g_wh);

    // 0) weights fp32 -> fp16 (once per launch)
    cvt_w_kernel<<<3072, 256>>>(Wq, Wk, Wv, Wo, W1, W2, wh);

    // 1) LN1 (half out)
    ln_kernel<<<M_, 128>>>(x, ln1s, ln1b, xnh);

    // 2) fused QKV projections
    dim3 gqkv(DIM_ / 64, M_ / 128, 3);
    k_gemm_qkv<<<gqkv, 256>>>(xnh, wh, bq, bk, bv, q, k, v);

    // 3) hash + rope + expmap0 + transpose
    prep_kernel<<<M_, 256>>>(q, k, v, fcos, fsin, c, hasho, qh, kh, vt);

    // 4) sliding-window Poincaré attention (persistent, 2 CTAs/SM; half out)
    attn2_kernel<<<304, 256>>>(qh, kh, vt, c, geo, attnh);

    // 5) Wo projection + residual(x) -> xout (f32)
    dim3 g512(DIM_ / 64, M_ / 128);
    k_gemm<1><<<g512, 256>>>(attnh, wh + WH_O, bo, x, xout, DIM_, DIM_);

    // 6) LN2 (half out)
    ln_kernel<<<M_, 128>>>(xout, ln2s, ln2b, hhh);

    // 7) FFN1 + gelu (half out)
    dim3 gffn1(DFF_ / 64, M_ / 128);
    k_gemm<2><<<gffn1, 256>>>(hhh, wh + WH_1, b1, nullptr, midh, DFF_, DIM_);

    // 8) FFN2 + residual(xout) -> out (f32)
    k_gemm<1><<<g512, 256>>>(midh, wh + WH_2, b2, xout, out, DIM_, DFF_);
}

// round 11
// speedup vs baseline: 2.4213x; 1.0134x over previous
#include <cuda_runtime.h>
#include <cuda_bf16.h>
#include <cuda_fp16.h>
#include <math.h>
#include <cstdint>

#define B_    2
#define N_    1024
#define DIM_  512
#define NH_   8
#define HD_   64
#define WIN_  64
#define M_    (B_ * N_)      // 2048
#define DFF_  (4 * DIM_)     // 2048
#define EPSV  1e-7f

// ------------------------ scratch (device globals; no allocation) ------------
__device__ __half g_xnh [M_ * DIM_];    // LN1 out (half)
__device__ float  g_q   [M_ * DIM_];
__device__ float  g_k   [M_ * DIM_];
__device__ float  g_v   [M_ * DIM_];
__device__ float  g_qh  [B_ * NH_ * N_ * HD_];
__device__ float  g_kh  [B_ * NH_ * N_ * HD_];
__device__ float  g_vt  [B_ * NH_ * N_ * HD_];
__device__ __half g_attnh[M_ * DIM_];   // attention out (half)
__device__ float  g_xout[M_ * DIM_];
__device__ __half g_hhh [M_ * DIM_];    // LN2 out (half)
__device__ __half g_midh[M_ * DFF_];    // FFN mid (half)
// half weights, concatenated
#define WH_Q 0
#define WH_K 262144
#define WH_V 524288
#define WH_O 786432
#define WH_1 1048576
#define WH_2 2097152
__device__ __half g_wh[3145728];

// ------------------------ helpers -------------------------------------------
__device__ __forceinline__ float warpsum(float v) {
#pragma unroll
    for (int o = 16; o > 0; o >>= 1) v += __shfl_xor_sync(0xffffffffu, v, o);
    return v;
}
__device__ __forceinline__ float warpmax(float v) {
#pragma unroll
    for (int o = 16; o > 0; o >>= 1) v = fmaxf(v, __shfl_xor_sync(0xffffffffu, v, o));
    return v;
}
__device__ __forceinline__ float sqrt_fast(float x) {
    float r;
    asm("sqrt.approx.f32 %0, %1;" : "=f"(r) : "f"(x));
    return r;
}
__device__ __forceinline__ uint32_t packh2(float lo, float hi) {
    __half2 h = __floats2half2_rn(lo, hi);
    return *(uint32_t*)&h;
}
// fp16 tensor-core mma: D(f32) += A(f16,16x16) * B(f16,16x8)
__device__ __forceinline__ void mma_f16(float4& c, uint32_t a0, uint32_t a1,
                                        uint32_t a2, uint32_t a3,
                                        uint32_t b0, uint32_t b1) {
    asm volatile(
        "mma.sync.aligned.m16n8k16.row.col.f32.f16.f16.f32 "
        "{%0,%1,%2,%3},{%4,%5,%6,%7},{%8,%9},{%0,%1,%2,%3};\n"
        : "+f"(c.x), "+f"(c.y), "+f"(c.z), "+f"(c.w)
        : "r"(a0), "r"(a1), "r"(a2), "r"(a3), "r"(b0), "r"(b1));
}

// ------------------------ weight fp32 -> fp16 convert ------------------------
__global__ __launch_bounds__(256) void cvt_w_kernel(
    const float* __restrict__ Wq, const float* __restrict__ Wk,
    const float* __restrict__ Wv, const float* __restrict__ Wo,
    const float* __restrict__ W1, const float* __restrict__ W2,
    __half* __restrict__ out) {
    long i = ((long)blockIdx.x * 256 + threadIdx.x) * 4;   // 4 elems/thread
    if (i >= 3145728) return;
    const float* src;
    long off;
    if      (i <  262144) { src = Wq; off = i; }
    else if (i <  524288) { src = Wk; off = i - 262144; }
    else if (i <  786432) { src = Wv; off = i - 524288; }
    else if (i < 1048576) { src = Wo; off = i - 786432; }
    else if (i < 2097152) { src = W1; off = i - 1048576; }
    else                  { src = W2; off = i - 2097152; }
    float4 v = *(const float4*)(src + off);
    uint2 o = make_uint2(packh2(v.x, v.y), packh2(v.z, v.w));
    *(uint2*)(out + i) = o;
}

// ------------------------ layernorm (half output) ----------------------------
__global__ void ln_kernel(const float* __restrict__ x, const float* __restrict__ s,
                          const float* __restrict__ bsh, __half* __restrict__ out) {
    int row = blockIdx.x;
    const float* xr = x + (size_t)row * DIM_;
    float v[4];
    float sum = 0.f, sq = 0.f;
#pragma unroll
    for (int i = 0; i < 4; i++) {
        v[i] = xr[threadIdx.x + i * 128];
        sum += v[i];
        sq  += v[i] * v[i];
    }
    __shared__ float red0[4], red1[4];
    sum = warpsum(sum); sq = warpsum(sq);
    int warp = threadIdx.x >> 5, lane = threadIdx.x & 31;
    if (lane == 0) { red0[warp] = sum; red1[warp] = sq; }
    __syncthreads();
    sum = red0[0] + red0[1] + red0[2] + red0[3];
    sq  = red1[0] + red1[1] + red1[2] + red1[3];
    float mean = sum * (1.0f / DIM_);
    float var  = sq * (1.0f / DIM_) - mean * mean;
    float inv  = rsqrtf(var + 1e-6f);
    __half* orow = out + (size_t)row * DIM_;
#pragma unroll
    for (int i = 0; i < 4; i++) {
        int d = threadIdx.x + i * 128;
        orow[d] = __float2half_rn((v[i] - mean) * inv * s[d] + bsh[d]);
    }
}

// ------------------------ fp16 tensor-core GEMM (half in) --------------------
// BM=128 BN=128 BK=32, 256 thr = 8 warps (2x4), warp tile 64x32.
// Per k16-step per warp: 16 MMA m16n8k16 vs 12 LDS.64.
// Ping-pong double buffer, ONE __syncthreads per K-tile.
//   A loader: thread (row, khalf): 2x LDG.128 -> 4x STS.64 (fragment-paired).
//   B loader: thread (btg, colpair) handles BOTH k-halves:
//             8x LDG.32 + 8x PRMT -> 2x STS.128 (2 cols each).
struct GSmem {
    uint2 Ap[2][2][4][132];  // [buf][ks16][tg][row 0..127]
    uint2 Bp[2][2][4][132];  // [buf][ks16][tg][col 0..127]
};

// EPI: 0 = +bias (f32 out), 1 = +bias+residual (f32 out), 2 = gelu+bias (HALF out)
template <int EPI>
__device__ __forceinline__ void gemm_core(
    const __half* __restrict__ A, const __half* __restrict__ Bw,
    const float* __restrict__ bias, const float* __restrict__ res,
    void* __restrict__ Cv, int Nd, int Kd) {
    __shared__ GSmem sm;
    const int m0 = blockIdx.y * 128, n0 = blockIdx.x * 128;
    const int tid = threadIdx.x;                 // 0..255
    const int lane = tid & 31, wid = tid >> 5;   // 8 warps
    const int g = lane >> 2, tg = lane & 3;
    const int wm = wid >> 2, wn = wid & 3;       // warp grid 2x4

    // A loader: row = tid>>1, k-half = tid&1 (16 halves = 32B)
    const int arow = tid >> 1, akh = tid & 1;
    const __half* aPtr = A + (size_t)(m0 + arow) * Kd + akh * 16;
    // B loader: btg = (tid>>6)&3, colpair = tid&63; handles bks = 0 and 1
    const int btg = (tid >> 6) & 3, bcp = tid & 63;
    const __half* bPtr0 = Bw + (size_t)(2 * btg) * Nd + n0 + 2 * bcp;       // bks=0
    const __half* bPtr1 = bPtr0 + (size_t)16 * Nd;                          // bks=1

    float4 acc[4][4];
#pragma unroll
    for (int i = 0; i < 4; i++)
#pragma unroll
        for (int j = 0; j < 4; j++) acc[i][j] = make_float4(0.f, 0.f, 0.f, 0.f);

    uint4 alo, ahi;
    uint32_t wv[2][4];
    alo = *(const uint4*)(aPtr);
    ahi = *(const uint4*)(aPtr + 8);
#pragma unroll
    for (int s = 0; s < 2; s++) {
        const __half* bp = s ? bPtr1 : bPtr0;
        wv[s][0] = *(const uint32_t*)(bp);
        wv[s][1] = *(const uint32_t*)(bp + Nd);
        wv[s][2] = *(const uint32_t*)(bp + 8 * Nd);
        wv[s][3] = *(const uint32_t*)(bp + 9 * Nd);
    }

    auto store_tile = [&](int buf) {
        sm.Ap[buf][akh][0][arow] = make_uint2(alo.x, ahi.x);
        sm.Ap[buf][akh][1][arow] = make_uint2(alo.y, ahi.y);
        sm.Ap[buf][akh][2][arow] = make_uint2(alo.z, ahi.z);
        sm.Ap[buf][akh][3][arow] = make_uint2(alo.w, ahi.w);
#pragma unroll
        for (int s = 0; s < 2; s++) {
            uint32_t lo0 = __byte_perm(wv[s][0], wv[s][1], 0x5410);
            uint32_t lo1 = __byte_perm(wv[s][0], wv[s][1], 0x7632);
            uint32_t hi0 = __byte_perm(wv[s][2], wv[s][3], 0x5410);
            uint32_t hi1 = __byte_perm(wv[s][2], wv[s][3], 0x7632);
            *(uint4*)&sm.Bp[buf][s][btg][2 * bcp] = make_uint4(lo0, hi0, lo1, hi1);
        }
    };

    store_tile(0);
    __syncthreads();

    const int nT = Kd >> 5;
    for (int t = 0; t < nT; t++) {
        const int buf = t & 1;
        const bool more = (t + 1 < nT);
        if (more) {  // prefetch next K-tile
            const __half* ap = aPtr + (t + 1) * 32;
            alo = *(const uint4*)(ap);
            ahi = *(const uint4*)(ap + 8);
            const size_t koff = (size_t)(t + 1) * 32 * Nd;
#pragma unroll
            for (int s = 0; s < 2; s++) {
                const __half* bp = (s ? bPtr1 : bPtr0) + koff;
                wv[s][0] = *(const uint32_t*)(bp);
                wv[s][1] = *(const uint32_t*)(bp + Nd);
                wv[s][2] = *(const uint32_t*)(bp + 8 * Nd);
                wv[s][3] = *(const uint32_t*)(bp + 9 * Nd);
            }
        }
#pragma unroll
        for (int ks = 0; ks < 2; ks++) {
            uint2 fal[4], fah[4], fb[4];
#pragma unroll
            for (int mi = 0; mi < 4; mi++) {
                fal[mi] = sm.Ap[buf][ks][tg][wm * 64 + mi * 16 + g];
                fah[mi] = sm.Ap[buf][ks][tg][wm * 64 + mi * 16 + g + 8];
            }
#pragma unroll
            for (int nj = 0; nj < 4; nj++)
                fb[nj] = sm.Bp[buf][ks][tg][wn * 32 + nj * 8 + g];
#pragma unroll
            for (int mi = 0; mi < 4; mi++)
#pragma unroll
                for (int nj = 0; nj < 4; nj++)
                    mma_f16(acc[mi][nj],
                            fal[mi].x, fah[mi].x, fal[mi].y, fah[mi].y,
                            fb[nj].x, fb[nj].y);
        }
        if (more) store_tile(buf ^ 1);
        __syncthreads();
    }

#pragma unroll
    for (int mi = 0; mi < 4; mi++) {
        int r0 = m0 + wm * 64 + mi * 16 + g;
#pragma unroll
        for (int nj = 0; nj < 4; nj++) {
            int col = n0 + wn * 32 + nj * 8 + tg * 2;
            float2 bbv = *(const float2*)(bias + col);
            float4 a = acc[mi][nj];
            float2 o0 = make_float2(a.x + bbv.x, a.y + bbv.y);
            float2 o1 = make_float2(a.z + bbv.x, a.w + bbv.y);
            if (EPI == 1) {
                float2 r0v = *(const float2*)(res + (size_t)r0 * Nd + col);
                float2 r1v = *(const float2*)(res + (size_t)(r0 + 8) * Nd + col);
                o0.x += r0v.x; o0.y += r0v.y;
                o1.x += r1v.x; o1.y += r1v.y;
            }
            if (EPI == 2) {
                float t0 = o0.x, t1 = o0.y, t2 = o1.x, t3 = o1.y;
                o0.x = t0 / (1.f + __expf(-1.5957691216057308f * (t0 + 0.044715f * t0 * t0 * t0)));
                o0.y = t1 / (1.f + __expf(-1.5957691216057308f * (t1 + 0.044715f * t1 * t1 * t1)));
                o1.x = t2 / (1.f + __expf(-1.5957691216057308f * (t2 + 0.044715f * t2 * t2 * t2)));
                o1.y = t3 / (1.f + __expf(-1.5957691216057308f * (t3 + 0.044715f * t3 * t3 * t3)));
                __half* Ch = (__half*)Cv;
                *(uint32_t*)(Ch + (size_t)r0 * Nd + col)       = packh2(o0.x, o0.y);
                *(uint32_t*)(Ch + (size_t)(r0 + 8) * Nd + col) = packh2(o1.x, o1.y);
            } else {
                float* C = (float*)Cv;
                *(float2*)(C + (size_t)r0 * Nd + col)       = o0;
                *(float2*)(C + (size_t)(r0 + 8) * Nd + col) = o1;
            }
        }
    }
}

__global__ __launch_bounds__(256, 2) void k_gemm_qkv(
    const __half* __restrict__ xn, const __half* __restrict__ wh,
    const float* __restrict__ bq, const float* __restrict__ bk,
    const float* __restrict__ bv,
    float* __restrict__ q, float* __restrict__ k, float* __restrict__ v) {
    int z = blockIdx.z;
    const __half* W  = wh + ((z == 0) ? WH_Q : (z == 1) ? WH_K : WH_V);
    const float* bb  = (z == 0) ? bq : (z == 1) ? bk : bv;
    float* o         = (z == 0) ? q  : (z == 1) ? k  : v;
    gemm_core<0>(xn, W, bb, nullptr, o, DIM_, DIM_);
}

template <int EPI>
__global__ __launch_bounds__(256, 2) void k_gemm(
    const __half* __restrict__ A, const __half* __restrict__ W,
    const float* __restrict__ bias, const float* __restrict__ res,
    void* __restrict__ C, int Nd, int Kd) {
    gemm_core<EPI>(A, W, bias, res, C, Nd, Kd);
}

// ------------------------ prep: hash + rope + expmap0 + transpose ------------
__global__ void prep_kernel(const float* __restrict__ qb, const float* __restrict__ kb,
                            const float* __restrict__ vb, const float* __restrict__ cos_t,
                            const float* __restrict__ sin_t, const float* __restrict__ c_arr,
                            const float* __restrict__ hash_off,
                            float* __restrict__ qh, float* __restrict__ kh,
                            float* __restrict__ vt) {
    int bn = blockIdx.x;
    int b = bn / N_, n = bn % N_;
    int h = threadIdx.x >> 5, lane = threadIdx.x & 31;
    const float LOG9 = 2.1972245773362196f;
    float cs = cos_t[n * 32 + lane];
    float sn = sin_t[n * 32 + lane];
    float cb = c_arr[b];
    float sqrt_c = fmaxf(sqrtf(cb), EPSV);
    size_t in_off  = (size_t)bn * DIM_ + h * HD_;
    size_t out_off = (((size_t)(b * NH_ + h)) * N_ + n) * HD_;

    {
        float v0 = qb[in_off + lane]      + hash_off[h * HD_ + lane]      * LOG9;
        float v1 = qb[in_off + lane + 32] + hash_off[h * HD_ + lane + 32] * LOG9;
        float r0 = v0 * cs - v1 * sn;
        float r1 = v0 * sn + v1 * cs;
        float nrm = sqrtf(warpsum(r0 * r0 + r1 * r1));
        float o0 = 0.f, o1 = 0.f;
        if (nrm >= EPSV) {
            float safe = fmaxf(nrm, EPSV);
            float mag  = tanhf(sqrt_c * safe) / sqrt_c;
            float sc   = mag / safe;
            o0 = sc * r0; o1 = sc * r1;
        }
        qh[out_off + lane] = o0; qh[out_off + lane + 32] = o1;
    }
    {
        float v0 = kb[in_off + lane];
        float v1 = kb[in_off + lane + 32];
        float r0 = v0 * cs - v1 * sn;
        float r1 = v0 * sn + v1 * cs;
        float nrm = sqrtf(warpsum(r0 * r0 + r1 * r1));
        float o0 = 0.f, o1 = 0.f;
        if (nrm >= EPSV) {
            float safe = fmaxf(nrm, EPSV);
            float mag  = tanhf(sqrt_c * safe) / sqrt_c;
            float sc   = mag / safe;
            o0 = sc * r0; o1 = sc * r1;
        }
        kh[out_off + lane] = o0; kh[out_off + lane + 32] = o1;
    }
    vt[out_off + lane]      = vb[in_off + lane];
    vt[out_off + lane + 32] = vb[in_off + lane + 32];
}

// ------------------------ windowed Poincaré attention (persistent) -----------
#define QT2    16
#define KR2    (QT2 + WIN_ - 1)   // 79
#define KS_STR 65
#define QS_STR 68
#define SW_STR 65
#define NTILES ((N_ / QT2) * B_ * NH_)   // 1024
#define RMIN_  5.0000003e-8f             // (1e-7)/(2-1e-7)

__global__ __launch_bounds__(256) void attn2_kernel(
    const float* __restrict__ qh, const float* __restrict__ kh,
    const float* __restrict__ vt, const float* __restrict__ c_arr,
    const float* __restrict__ geo, __half* __restrict__ attn_out) {
    __shared__ __align__(16) float Ks[KR2 * KS_STR + 16];  // K tile; reused for V
    __shared__ __align__(16) float Qs[QT2 * QS_STR];
    __shared__ __align__(16) float Sw[QT2 * SW_STR];
    __shared__ float y2s[KR2 + 1];

    const int tid = threadIdx.x;
    const int w = tid >> 5, l = tid & 31;
    const int qi = tid >> 4;
    const int kg = tid & 15;

    for (int t = blockIdx.x; t < NTILES; t += gridDim.x) {
        const int bh = t >> 6;
        const int b = bh >> 3, h = bh & 7;
        const int n0 = (t & 63) << 4;
        const float* Kb = kh + (size_t)bh * (N_ * HD_);
        const float* Vb = vt + (size_t)bh * (N_ * HD_);
        const float* Qb = qh + (size_t)bh * (N_ * HD_);

#pragma unroll
        for (int i = 0; i < 5; i++) {
            int f = tid + i * 256;
            if (f < KR2 * 16) {
                int row = f >> 4, c4 = (f & 15) << 2;
                int gn = n0 - (WIN_ - 1) + row;
                float4 val = make_float4(0.f, 0.f, 0.f, 0.f);
                if (gn >= 0) val = *(const float4*)(Kb + (size_t)gn * HD_ + c4);
                float* d = &Ks[row * KS_STR + c4];
                d[0] = val.x; d[1] = val.y; d[2] = val.z; d[3] = val.w;
            }
        }
        {
            int row = tid >> 4, c4 = (tid & 15) << 2;
            *(float4*)&Qs[row * QS_STR + c4] =
                *(const float4*)(Qb + (size_t)(n0 + row) * HD_ + c4);
        }
        float4 vreg[5];
#pragma unroll
        for (int i = 0; i < 5; i++) {
            int f = tid + i * 256;
            vreg[i] = make_float4(0.f, 0.f, 0.f, 0.f);
            if (f < KR2 * 16) {
                int row = f >> 4, c4 = (f & 15) << 2;
                int gn = n0 - (WIN_ - 1) + row;
                if (gn >= 0) vreg[i] = *(const float4*)(Vb + (size_t)gn * HD_ + c4);
            }
        }
        __syncthreads();

        for (int row = w; row < KR2; row += 8) {
            float a = Ks[row * KS_STR + l];
            float bq = Ks[row * KS_STR + 32 + l];
            float s = warpsum(a * a + bq * bq);
            if (l == 0) y2s[row] = s;
        }
        __syncthreads();

        const float cb = c_arr[b];
        const float sc = fmaxf(sqrtf(cb), EPSV);
        const float gs = geo[h];
        const float p2 = gs / sc;
        const float cc = cb * cb;

        float xy0 = 0.f, xy1 = 0.f, xy2 = 0.f, xy3 = 0.f, q2 = 0.f;
        {
            const float* qrow = &Qs[qi * QS_STR];
            const float* kr = &Ks[(qi + kg) * KS_STR];
#pragma unroll 8
            for (int d = 0; d < HD_; d++) {
                float qv = qrow[d];
                q2  = fmaf(qv, qv, q2);
                xy0 = fmaf(qv, kr[d], xy0);
                xy1 = fmaf(qv, kr[d + 16 * KS_STR], xy1);
                xy2 = fmaf(qv, kr[d + 32 * KS_STR], xy2);
                xy3 = fmaf(qv, kr[d + 48 * KS_STR], xy3);
            }
        }
        {
            const float Bc = 1.f - cb * q2;
            const float c2x2 = cc * q2;
            float xys[4] = {xy0, xy1, xy2, xy3};
#pragma unroll
            for (int j = 0; j < 4; j++) {
                float xy = xys[j];
                float y2 = y2s[qi + kg + 16 * j];
                float u  = fmaf(-2.f * cb, xy, 1.f);
                float A  = fmaf(cb, y2, u);
                float dn2 = fmaf(A * A, q2, fmaf(Bc * Bc, y2, -2.f * A * Bc * xy));
                float den = fmaxf(fmaf(c2x2, y2, u), EPSV);
                float s   = sc * sqrt_fast(fmaxf(dn2, 0.f));
                float ratio = __fdividef(den - s, den + s);
                ratio = fmaxf(ratio, RMIN_);
                Sw[qi * SW_STR + kg + 16 * j] = p2 * __log2f(ratio);
            }
        }
        __syncthreads();

#pragma unroll
        for (int qq = 0; qq < 2; qq++) {
            int q = w + qq * 8;
            float s0 = Sw[q * SW_STR + l];
            float s1 = Sw[q * SW_STR + 32 + l];
            float m = warpmax(fmaxf(s0, s1));
            float e0 = exp2f(s0 - m), e1 = exp2f(s1 - m);
            float inv = __fdividef(1.f, warpsum(e0 + e1));
            Sw[q * SW_STR + l] = e0 * inv;
            Sw[q * SW_STR + 32 + l] = e1 * inv;
        }
        __syncthreads();

#pragma unroll
        for (int i = 0; i < 5; i++) {
            int f = tid + i * 256;
            if (f < KR2 * 16) {
                int row = f >> 4, c4 = (f & 15) << 2;
                *(float4*)&Ks[row * HD_ + c4] = vreg[i];
            }
        }
        __syncthreads();

        {
            const int dg = tid & 15;
            float4 acc = make_float4(0.f, 0.f, 0.f, 0.f);
            const float* wrow = &Sw[qi * SW_STR];
            const float* vbase = &Ks[qi * HD_ + dg * 4];
#pragma unroll 8
            for (int k = 0; k < WIN_; k++) {
                float wk = wrow[k];
                float4 vv = *(const float4*)(vbase + k * HD_);
                acc.x = fmaf(wk, vv.x, acc.x);
                acc.y = fmaf(wk, vv.y, acc.y);
                acc.z = fmaf(wk, vv.z, acc.z);
                acc.w = fmaf(wk, vv.w, acc.w);
            }
            __half* orow = attn_out + ((size_t)(b * N_ + n0 + qi)) * DIM_ + h * HD_ + dg * 4;
            *(uint2*)orow = make_uint2(packh2(acc.x, acc.y), packh2(acc.z, acc.w));
        }
        __syncthreads();
    }
}

// ------------------------ launch --------------------------------------------
extern "C" void kernel_launch(void* const* d_in, const int* in_sizes, int n_in,
                              void* d_out, int out_size) {
    (void)in_sizes; (void)n_in; (void)out_size;
    const float* x     = (const float*)d_in[0];
    const float* fcos  = (const float*)d_in[1];
    const float* fsin  = (const float*)d_in[2];
    const float* c     = (const float*)d_in[3];
    const float* Wq    = (const float*)d_in[4];
    const float* bq    = (const float*)d_in[5];
    const float* Wk    = (const float*)d_in[6];
    const float* bk    = (const float*)d_in[7];
    const float* Wv    = (const float*)d_in[8];
    const float* bv    = (const float*)d_in[9];
    const float* Wo    = (const float*)d_in[10];
    const float* bo    = (const float*)d_in[11];
    const float* W1    = (const float*)d_in[12];
    const float* b1    = (const float*)d_in[13];
    const float* W2    = (const float*)d_in[14];
    const float* b2    = (const float*)d_in[15];
    const float* ln1s  = (const float*)d_in[16];
    const float* ln1b  = (const float*)d_in[17];
    const float* ln2s  = (const float*)d_in[18];
    const float* ln2b  = (const float*)d_in[19];
    const float* geo   = (const float*)d_in[20];
    const float* hasho = (const float*)d_in[21];
    float* out = (float*)d_out;

    __half *xnh, *attnh, *hhh, *midh, *wh;
    float *q, *k, *v, *qh, *kh, *vt, *xout;
    cudaGetSymbolAddress((void**)&xnh,   g_xnh);
    cudaGetSymbolAddress((void**)&q,     g_q);
    cudaGetSymbolAddress((void**)&k,     g_k);
    cudaGetSymbolAddress((void**)&v,     g_v);
    cudaGetSymbolAddress((void**)&qh,    g_qh);
    cudaGetSymbolAddress((void**)&kh,    g_kh);
    cudaGetSymbolAddress((void**)&vt,    g_vt);
    cudaGetSymbolAddress((void**)&attnh, g_attnh);
    cudaGetSymbolAddress((void**)&xout,  g_xout);
    cudaGetSymbolAddress((void**)&hhh,   g_hhh);
    cudaGetSymbolAddress((void**)&midh,  g_midh);
    cudaGetSymbolAddress((void**)&wh,    g_wh);

    // 0) weights fp32 -> fp16 (once per launch)
    cvt_w_kernel<<<3072, 256>>>(Wq, Wk, Wv, Wo, W1, W2, wh);

    // 1) LN1 (half out)
    ln_kernel<<<M_, 128>>>(x, ln1s, ln1b, xnh);

    // 2) fused QKV projections (192 CTAs)
    dim3 gqkv(DIM_ / 128, M_ / 128, 3);
    k_gemm_qkv<<<gqkv, 256>>>(xnh, wh, bq, bk, bv, q, k, v);

    // 3) hash + rope + expmap0 + transpose
    prep_kernel<<<M_, 256>>>(q, k, v, fcos, fsin, c, hasho, qh, kh, vt);

    // 4) sliding-window Poincaré attention (persistent, 2 CTAs/SM; half out)
    attn2_kernel<<<304, 256>>>(qh, kh, vt, c, geo, attnh);

    // 5) Wo projection + residual(x) -> xout (f32)
    dim3 g512(DIM_ / 128, M_ / 128);
    k_gemm<1><<<g512, 256>>>(attnh, wh + WH_O, bo, x, xout, DIM_, DIM_);

    // 6) LN2 (half out)
    ln_kernel<<<M_, 128>>>(xout, ln2s, ln2b, hhh);

    // 7) FFN1 + gelu (half out)
    dim3 gffn1(DFF_ / 128, M_ / 128);
    k_gemm<2><<<gffn1, 256>>>(hhh, wh + WH_1, b1, nullptr, midh, DFF_, DIM_);

    // 8) FFN2 + residual(xout) -> out (f32)
    k_gemm<1><<<g512, 256>>>(midh, wh + WH_2, b2, xout, out, DIM_, DFF_);
}

// round 12
// speedup vs baseline: 2.6276x; 1.0852x over previous
#include <cuda_runtime.h>
#include <cuda_bf16.h>
#include <cuda_fp16.h>
#include <math.h>
#include <cstdint>

#define B_    2
#define N_    1024
#define DIM_  512
#define NH_   8
#define HD_   64
#define WIN_  64
#define M_    (B_ * N_)      // 2048
#define DFF_  (4 * DIM_)     // 2048
#define EPSV  1e-7f

// ------------------------ scratch (device globals; no allocation) ------------
__device__ __half g_xnh [M_ * DIM_];    // LN1 out (half)
__device__ float  g_q   [M_ * DIM_];
__device__ float  g_k   [M_ * DIM_];
__device__ float  g_v   [M_ * DIM_];
__device__ float  g_qh  [B_ * NH_ * N_ * HD_];
__device__ float  g_kh  [B_ * NH_ * N_ * HD_];
__device__ float  g_vt  [B_ * NH_ * N_ * HD_];
__device__ __half g_attnh[M_ * DIM_];   // attention out (half)
__device__ float  g_xout[M_ * DIM_];
__device__ __half g_hhh [M_ * DIM_];    // LN2 out (half)
__device__ __half g_midh[M_ * DFF_];    // FFN mid (half)
// half weights, concatenated
#define WH_Q 0
#define WH_K 262144
#define WH_V 524288
#define WH_O 786432
#define WH_1 1048576
#define WH_2 2097152
__device__ __half g_wh[3145728];

// ------------------------ helpers -------------------------------------------
__device__ __forceinline__ float warpsum(float v) {
#pragma unroll
    for (int o = 16; o > 0; o >>= 1) v += __shfl_xor_sync(0xffffffffu, v, o);
    return v;
}
__device__ __forceinline__ float warpmax(float v) {
#pragma unroll
    for (int o = 16; o > 0; o >>= 1) v = fmaxf(v, __shfl_xor_sync(0xffffffffu, v, o));
    return v;
}
__device__ __forceinline__ float sqrt_fast(float x) {
    float r;
    asm("sqrt.approx.f32 %0, %1;" : "=f"(r) : "f"(x));
    return r;
}
__device__ __forceinline__ uint32_t packh2(float lo, float hi) {
    __half2 h = __floats2half2_rn(lo, hi);
    return *(uint32_t*)&h;
}
// fast tanh for x >= 0:  tanh(x) = 1 - 2/(1+e^{2x})
__device__ __forceinline__ float tanh_pos(float x) {
    return 1.f - __fdividef(2.f, 1.f + __expf(2.f * x));
}
// fp16 tensor-core mma: D(f32) += A(f16,16x16) * B(f16,16x8)
__device__ __forceinline__ void mma_f16(float4& c, uint32_t a0, uint32_t a1,
                                        uint32_t a2, uint32_t a3,
                                        uint32_t b0, uint32_t b1) {
    asm volatile(
        "mma.sync.aligned.m16n8k16.row.col.f32.f16.f16.f32 "
        "{%0,%1,%2,%3},{%4,%5,%6,%7},{%8,%9},{%0,%1,%2,%3};\n"
        : "+f"(c.x), "+f"(c.y), "+f"(c.z), "+f"(c.w)
        : "r"(a0), "r"(a1), "r"(a2), "r"(a3), "r"(b0), "r"(b1));
}

// ------------------------ weight fp32 -> fp16 convert ------------------------
__global__ __launch_bounds__(256) void cvt_w_kernel(
    const float* __restrict__ Wq, const float* __restrict__ Wk,
    const float* __restrict__ Wv, const float* __restrict__ Wo,
    const float* __restrict__ W1, const float* __restrict__ W2,
    __half* __restrict__ out) {
    long i = ((long)blockIdx.x * 256 + threadIdx.x) * 4;   // 4 elems/thread
    if (i >= 3145728) return;
    const float* src;
    long off;
    if      (i <  262144) { src = Wq; off = i; }
    else if (i <  524288) { src = Wk; off = i - 262144; }
    else if (i <  786432) { src = Wv; off = i - 524288; }
    else if (i < 1048576) { src = Wo; off = i - 786432; }
    else if (i < 2097152) { src = W1; off = i - 1048576; }
    else                  { src = W2; off = i - 2097152; }
    float4 v = *(const float4*)(src + off);
    uint2 o = make_uint2(packh2(v.x, v.y), packh2(v.z, v.w));
    *(uint2*)(out + i) = o;
}

// ------------------------ layernorm (half output) ----------------------------
__global__ void ln_kernel(const float* __restrict__ x, const float* __restrict__ s,
                          const float* __restrict__ bsh, __half* __restrict__ out) {
    int row = blockIdx.x;
    const float* xr = x + (size_t)row * DIM_;
    float v[4];
    float sum = 0.f, sq = 0.f;
#pragma unroll
    for (int i = 0; i < 4; i++) {
        v[i] = xr[threadIdx.x + i * 128];
        sum += v[i];
        sq  += v[i] * v[i];
    }
    __shared__ float red0[4], red1[4];
    sum = warpsum(sum); sq = warpsum(sq);
    int warp = threadIdx.x >> 5, lane = threadIdx.x & 31;
    if (lane == 0) { red0[warp] = sum; red1[warp] = sq; }
    __syncthreads();
    sum = red0[0] + red0[1] + red0[2] + red0[3];
    sq  = red1[0] + red1[1] + red1[2] + red1[3];
    float mean = sum * (1.0f / DIM_);
    float var  = sq * (1.0f / DIM_) - mean * mean;
    float inv  = rsqrtf(var + 1e-6f);
    __half* orow = out + (size_t)row * DIM_;
#pragma unroll
    for (int i = 0; i < 4; i++) {
        int d = threadIdx.x + i * 128;
        orow[d] = __float2half_rn((v[i] - mean) * inv * s[d] + bsh[d]);
    }
}

// ======================= 128x128 fp16 GEMM (QKV / FFN1) ======================
struct GSmem128 {
    uint2 Ap[2][2][4][132];  // [buf][ks16][tg][row 0..127]
    uint2 Bp[2][2][4][132];  // [buf][ks16][tg][col 0..127]
};

// EPI: 0 = +bias (f32 out), 2 = gelu+bias (HALF out)
template <int EPI>
__device__ __forceinline__ void gemm_core128(
    const __half* __restrict__ A, const __half* __restrict__ Bw,
    const float* __restrict__ bias, void* __restrict__ Cv, int Nd, int Kd) {
    __shared__ GSmem128 sm;
    const int m0 = blockIdx.y * 128, n0 = blockIdx.x * 128;
    const int tid = threadIdx.x;
    const int lane = tid & 31, wid = tid >> 5;
    const int g = lane >> 2, tg = lane & 3;
    const int wm = wid >> 2, wn = wid & 3;       // warp grid 2x4

    const int arow = tid >> 1, akh = tid & 1;
    const __half* aPtr = A + (size_t)(m0 + arow) * Kd + akh * 16;
    const int btg = (tid >> 6) & 3, bcp = tid & 63;
    const __half* bPtr0 = Bw + (size_t)(2 * btg) * Nd + n0 + 2 * bcp;
    const __half* bPtr1 = bPtr0 + (size_t)16 * Nd;

    float4 acc[4][4];
#pragma unroll
    for (int i = 0; i < 4; i++)
#pragma unroll
        for (int j = 0; j < 4; j++) acc[i][j] = make_float4(0.f, 0.f, 0.f, 0.f);

    uint4 alo, ahi;
    uint32_t wv[2][4];
    alo = *(const uint4*)(aPtr);
    ahi = *(const uint4*)(aPtr + 8);
#pragma unroll
    for (int s = 0; s < 2; s++) {
        const __half* bp = s ? bPtr1 : bPtr0;
        wv[s][0] = *(const uint32_t*)(bp);
        wv[s][1] = *(const uint32_t*)(bp + Nd);
        wv[s][2] = *(const uint32_t*)(bp + 8 * Nd);
        wv[s][3] = *(const uint32_t*)(bp + 9 * Nd);
    }

    auto store_tile = [&](int buf) {
        sm.Ap[buf][akh][0][arow] = make_uint2(alo.x, ahi.x);
        sm.Ap[buf][akh][1][arow] = make_uint2(alo.y, ahi.y);
        sm.Ap[buf][akh][2][arow] = make_uint2(alo.z, ahi.z);
        sm.Ap[buf][akh][3][arow] = make_uint2(alo.w, ahi.w);
#pragma unroll
        for (int s = 0; s < 2; s++) {
            uint32_t lo0 = __byte_perm(wv[s][0], wv[s][1], 0x5410);
            uint32_t lo1 = __byte_perm(wv[s][0], wv[s][1], 0x7632);
            uint32_t hi0 = __byte_perm(wv[s][2], wv[s][3], 0x5410);
            uint32_t hi1 = __byte_perm(wv[s][2], wv[s][3], 0x7632);
            *(uint4*)&sm.Bp[buf][s][btg][2 * bcp] = make_uint4(lo0, hi0, lo1, hi1);
        }
    };

    store_tile(0);
    __syncthreads();

    const int nT = Kd >> 5;
    for (int t = 0; t < nT; t++) {
        const int buf = t & 1;
        const bool more = (t + 1 < nT);
        if (more) {
            const __half* ap = aPtr + (t + 1) * 32;
            alo = *(const uint4*)(ap);
            ahi = *(const uint4*)(ap + 8);
            const size_t koff = (size_t)(t + 1) * 32 * Nd;
#pragma unroll
            for (int s = 0; s < 2; s++) {
                const __half* bp = (s ? bPtr1 : bPtr0) + koff;
                wv[s][0] = *(const uint32_t*)(bp);
                wv[s][1] = *(const uint32_t*)(bp + Nd);
                wv[s][2] = *(const uint32_t*)(bp + 8 * Nd);
                wv[s][3] = *(const uint32_t*)(bp + 9 * Nd);
            }
        }
#pragma unroll
        for (int ks = 0; ks < 2; ks++) {
            uint2 fal[4], fah[4], fb[4];
#pragma unroll
            for (int mi = 0; mi < 4; mi++) {
                fal[mi] = sm.Ap[buf][ks][tg][wm * 64 + mi * 16 + g];
                fah[mi] = sm.Ap[buf][ks][tg][wm * 64 + mi * 16 + g + 8];
            }
#pragma unroll
            for (int nj = 0; nj < 4; nj++)
                fb[nj] = sm.Bp[buf][ks][tg][wn * 32 + nj * 8 + g];
#pragma unroll
            for (int mi = 0; mi < 4; mi++)
#pragma unroll
                for (int nj = 0; nj < 4; nj++)
                    mma_f16(acc[mi][nj],
                            fal[mi].x, fah[mi].x, fal[mi].y, fah[mi].y,
                            fb[nj].x, fb[nj].y);
        }
        if (more) store_tile(buf ^ 1);
        __syncthreads();
    }

#pragma unroll
    for (int mi = 0; mi < 4; mi++) {
        int r0 = m0 + wm * 64 + mi * 16 + g;
#pragma unroll
        for (int nj = 0; nj < 4; nj++) {
            int col = n0 + wn * 32 + nj * 8 + tg * 2;
            float2 bbv = *(const float2*)(bias + col);
            float4 a = acc[mi][nj];
            float2 o0 = make_float2(a.x + bbv.x, a.y + bbv.y);
            float2 o1 = make_float2(a.z + bbv.x, a.w + bbv.y);
            if (EPI == 2) {
                float t0 = o0.x, t1 = o0.y, t2 = o1.x, t3 = o1.y;
                o0.x = t0 / (1.f + __expf(-1.5957691216057308f * (t0 + 0.044715f * t0 * t0 * t0)));
                o0.y = t1 / (1.f + __expf(-1.5957691216057308f * (t1 + 0.044715f * t1 * t1 * t1)));
                o1.x = t2 / (1.f + __expf(-1.5957691216057308f * (t2 + 0.044715f * t2 * t2 * t2)));
                o1.y = t3 / (1.f + __expf(-1.5957691216057308f * (t3 + 0.044715f * t3 * t3 * t3)));
                __half* Ch = (__half*)Cv;
                *(uint32_t*)(Ch + (size_t)r0 * Nd + col)       = packh2(o0.x, o0.y);
                *(uint32_t*)(Ch + (size_t)(r0 + 8) * Nd + col) = packh2(o1.x, o1.y);
            } else {
                float* C = (float*)Cv;
                *(float2*)(C + (size_t)r0 * Nd + col)       = o0;
                *(float2*)(C + (size_t)(r0 + 8) * Nd + col) = o1;
            }
        }
    }
}

__global__ __launch_bounds__(256, 2) void k_gemm_qkv(
    const __half* __restrict__ xn, const __half* __restrict__ wh,
    const float* __restrict__ bq, const float* __restrict__ bk,
    const float* __restrict__ bv,
    float* __restrict__ q, float* __restrict__ k, float* __restrict__ v) {
    int z = blockIdx.z;
    const __half* W  = wh + ((z == 0) ? WH_Q : (z == 1) ? WH_K : WH_V);
    const float* bb  = (z == 0) ? bq : (z == 1) ? bk : bv;
    float* o         = (z == 0) ? q  : (z == 1) ? k  : v;
    gemm_core128<0>(xn, W, bb, o, DIM_, DIM_);
}

__global__ __launch_bounds__(256, 2) void k_gemm128_gelu(
    const __half* __restrict__ A, const __half* __restrict__ W,
    const float* __restrict__ bias, void* __restrict__ C, int Nd, int Kd) {
    gemm_core128<2>(A, W, bias, C, Nd, Kd);
}

// ======================= 128x64 fp16 GEMM (Wo / FFN2, +residual) =============
struct GSmem64 {
    uint2 Ap[2][2][4][132];  // [buf][ks16][tg][row]
    uint2 Bp[2][2][4][68];   // [buf][ks16][tg][col]
};

__global__ __launch_bounds__(256, 3) void k_gemm64_res(
    const __half* __restrict__ A, const __half* __restrict__ Bw,
    const float* __restrict__ bias, const float* __restrict__ res,
    float* __restrict__ C, int Nd, int Kd) {
    __shared__ GSmem64 sm;
    const int m0 = blockIdx.y * 128, n0 = blockIdx.x * 64;
    const int tid = threadIdx.x;
    const int lane = tid & 31, wid = tid >> 5;
    const int g = lane >> 2, tg = lane & 3;
    const int wm = wid >> 1, wn = wid & 1;       // warp grid 4x2

    const int arow = tid >> 1, akh = tid & 1;
    const __half* aPtr = A + (size_t)(m0 + arow) * Kd + akh * 16;
    const int bks = tid >> 7, btg = (tid >> 5) & 3, bcp = tid & 31;
    const __half* bPtr = Bw + (size_t)(bks * 16 + 2 * btg) * Nd + n0 + 2 * bcp;

    float4 acc[2][4];
#pragma unroll
    for (int i = 0; i < 2; i++)
#pragma unroll
        for (int j = 0; j < 4; j++) acc[i][j] = make_float4(0.f, 0.f, 0.f, 0.f);

    uint4 alo, ahi;
    uint32_t w0, w1, w2, w3;
    alo = *(const uint4*)(aPtr);
    ahi = *(const uint4*)(aPtr + 8);
    w0 = *(const uint32_t*)(bPtr);
    w1 = *(const uint32_t*)(bPtr + Nd);
    w2 = *(const uint32_t*)(bPtr + 8 * Nd);
    w3 = *(const uint32_t*)(bPtr + 9 * Nd);

    auto store_tile = [&](int buf) {
        sm.Ap[buf][akh][0][arow] = make_uint2(alo.x, ahi.x);
        sm.Ap[buf][akh][1][arow] = make_uint2(alo.y, ahi.y);
        sm.Ap[buf][akh][2][arow] = make_uint2(alo.z, ahi.z);
        sm.Ap[buf][akh][3][arow] = make_uint2(alo.w, ahi.w);
        uint32_t lo0 = __byte_perm(w0, w1, 0x5410);
        uint32_t lo1 = __byte_perm(w0, w1, 0x7632);
        uint32_t hi0 = __byte_perm(w2, w3, 0x5410);
        uint32_t hi1 = __byte_perm(w2, w3, 0x7632);
        *(uint4*)&sm.Bp[buf][bks][btg][2 * bcp] = make_uint4(lo0, hi0, lo1, hi1);
    };

    store_tile(0);
    __syncthreads();

    const int nT = Kd >> 5;
    for (int t = 0; t < nT; t++) {
        const int buf = t & 1;
        const bool more = (t + 1 < nT);
        if (more) {
            const __half* ap = aPtr + (t + 1) * 32;
            alo = *(const uint4*)(ap);
            ahi = *(const uint4*)(ap + 8);
            const __half* bp = bPtr + (size_t)(t + 1) * 32 * Nd;
            w0 = *(const uint32_t*)(bp);
            w1 = *(const uint32_t*)(bp + Nd);
            w2 = *(const uint32_t*)(bp + 8 * Nd);
            w3 = *(const uint32_t*)(bp + 9 * Nd);
        }
#pragma unroll
        for (int ks = 0; ks < 2; ks++) {
            uint2 fal[2], fah[2], fb[4];
#pragma unroll
            for (int mi = 0; mi < 2; mi++) {
                fal[mi] = sm.Ap[buf][ks][tg][wm * 32 + mi * 16 + g];
                fah[mi] = sm.Ap[buf][ks][tg][wm * 32 + mi * 16 + g + 8];
            }
#pragma unroll
            for (int nj = 0; nj < 4; nj++)
                fb[nj] = sm.Bp[buf][ks][tg][wn * 32 + nj * 8 + g];
#pragma unroll
            for (int mi = 0; mi < 2; mi++)
#pragma unroll
                for (int nj = 0; nj < 4; nj++)
                    mma_f16(acc[mi][nj],
                            fal[mi].x, fah[mi].x, fal[mi].y, fah[mi].y,
                            fb[nj].x, fb[nj].y);
        }
        if (more) store_tile(buf ^ 1);
        __syncthreads();
    }

#pragma unroll
    for (int mi = 0; mi < 2; mi++) {
        int r0 = m0 + wm * 32 + mi * 16 + g;
#pragma unroll
        for (int nj = 0; nj < 4; nj++) {
            int col = n0 + wn * 32 + nj * 8 + tg * 2;
            float2 bbv = *(const float2*)(bias + col);
            float4 a = acc[mi][nj];
            float2 r0v = *(const float2*)(res + (size_t)r0 * Nd + col);
            float2 r1v = *(const float2*)(res + (size_t)(r0 + 8) * Nd + col);
            float2 o0 = make_float2(a.x + bbv.x + r0v.x, a.y + bbv.y + r0v.y);
            float2 o1 = make_float2(a.z + bbv.x + r1v.x, a.w + bbv.y + r1v.y);
            *(float2*)(C + (size_t)r0 * Nd + col)       = o0;
            *(float2*)(C + (size_t)(r0 + 8) * Nd + col) = o1;
        }
    }
}

// ------------------------ prep: hash + rope + expmap0 + transpose ------------
__global__ void prep_kernel(const float* __restrict__ qb, const float* __restrict__ kb,
                            const float* __restrict__ vb, const float* __restrict__ cos_t,
                            const float* __restrict__ sin_t, const float* __restrict__ c_arr,
                            const float* __restrict__ hash_off,
                            float* __restrict__ qh, float* __restrict__ kh,
                            float* __restrict__ vt) {
    int bn = blockIdx.x;
    int b = bn / N_, n = bn % N_;
    int h = threadIdx.x >> 5, lane = threadIdx.x & 31;
    const float LOG9 = 2.1972245773362196f;
    float cs = cos_t[n * 32 + lane];
    float sn = sin_t[n * 32 + lane];
    float cb = c_arr[b];
    float sqrt_c = fmaxf(sqrtf(cb), EPSV);
    size_t in_off  = (size_t)bn * DIM_ + h * HD_;
    size_t out_off = (((size_t)(b * NH_ + h)) * N_ + n) * HD_;

    {
        float v0 = qb[in_off + lane]      + hash_off[h * HD_ + lane]      * LOG9;
        float v1 = qb[in_off + lane + 32] + hash_off[h * HD_ + lane + 32] * LOG9;
        float r0 = v0 * cs - v1 * sn;
        float r1 = v0 * sn + v1 * cs;
        float nrm = sqrtf(warpsum(r0 * r0 + r1 * r1));
        float o0 = 0.f, o1 = 0.f;
        if (nrm >= EPSV) {
            float safe = fmaxf(nrm, EPSV);
            float mag  = __fdividef(tanh_pos(sqrt_c * safe), sqrt_c);
            float sc   = __fdividef(mag, safe);
            o0 = sc * r0; o1 = sc * r1;
        }
        qh[out_off + lane] = o0; qh[out_off + lane + 32] = o1;
    }
    {
        float v0 = kb[in_off + lane];
        float v1 = kb[in_off + lane + 32];
        float r0 = v0 * cs - v1 * sn;
        float r1 = v0 * sn + v1 * cs;
        float nrm = sqrtf(warpsum(r0 * r0 + r1 * r1));
        float o0 = 0.f, o1 = 0.f;
        if (nrm >= EPSV) {
            float safe = fmaxf(nrm, EPSV);
            float mag  = __fdividef(tanh_pos(sqrt_c * safe), sqrt_c);
            float sc   = __fdividef(mag, safe);
            o0 = sc * r0; o1 = sc * r1;
        }
        kh[out_off + lane] = o0; kh[out_off + lane + 32] = o1;
    }
    vt[out_off + lane]      = vb[in_off + lane];
    vt[out_off + lane + 32] = vb[in_off + lane + 32];
}

// ------------------------ windowed Poincaré attention (persistent) -----------
#define QT2    16
#define KR2    (QT2 + WIN_ - 1)   // 79
#define KS_STR 65
#define QS_STR 68
#define SW_STR 65
#define NTILES ((N_ / QT2) * B_ * NH_)   // 1024
#define ATT_GRID 512                     // 2 tiles per CTA exactly
#define RMIN_  5.0000003e-8f             // (1e-7)/(2-1e-7)

__global__ __launch_bounds__(256, 4) void attn2_kernel(
    const float* __restrict__ qh, const float* __restrict__ kh,
    const float* __restrict__ vt, const float* __restrict__ c_arr,
    const float* __restrict__ geo, __half* __restrict__ attn_out) {
    __shared__ __align__(16) float Ks[KR2 * KS_STR + 16];  // K tile; reused for V
    __shared__ __align__(16) float Qs[QT2 * QS_STR];
    __shared__ __align__(16) float Sw[QT2 * SW_STR];
    __shared__ float y2s[KR2 + 1];

    const int tid = threadIdx.x;
    const int w = tid >> 5, l = tid & 31;
    const int qi = tid >> 4;
    const int kg = tid & 15;

    for (int t = blockIdx.x; t < NTILES; t += ATT_GRID) {
        const int bh = t >> 6;
        const int b = bh >> 3, h = bh & 7;
        const int n0 = (t & 63) << 4;
        const float* Kb = kh + (size_t)bh * (N_ * HD_);
        const float* Vb = vt + (size_t)bh * (N_ * HD_);
        const float* Qb = qh + (size_t)bh * (N_ * HD_);

#pragma unroll
        for (int i = 0; i < 5; i++) {
            int f = tid + i * 256;
            if (f < KR2 * 16) {
                int row = f >> 4, c4 = (f & 15) << 2;
                int gn = n0 - (WIN_ - 1) + row;
                float4 val = make_float4(0.f, 0.f, 0.f, 0.f);
                if (gn >= 0) val = *(const float4*)(Kb + (size_t)gn * HD_ + c4);
                float* d = &Ks[row * KS_STR + c4];
                d[0] = val.x; d[1] = val.y; d[2] = val.z; d[3] = val.w;
            }
        }
        {
            int row = tid >> 4, c4 = (tid & 15) << 2;
            *(float4*)&Qs[row * QS_STR + c4] =
                *(const float4*)(Qb + (size_t)(n0 + row) * HD_ + c4);
        }
        float4 vreg[5];
#pragma unroll
        for (int i = 0; i < 5; i++) {
            int f = tid + i * 256;
            vreg[i] = make_float4(0.f, 0.f, 0.f, 0.f);
            if (f < KR2 * 16) {
                int row = f >> 4, c4 = (f & 15) << 2;
                int gn = n0 - (WIN_ - 1) + row;
                if (gn >= 0) vreg[i] = *(const float4*)(Vb + (size_t)gn * HD_ + c4);
            }
        }
        __syncthreads();

        for (int row = w; row < KR2; row += 8) {
            float a = Ks[row * KS_STR + l];
            float bq = Ks[row * KS_STR + 32 + l];
            float s = warpsum(a * a + bq * bq);
            if (l == 0) y2s[row] = s;
        }
        __syncthreads();

        const float cb = c_arr[b];
        const float sc = fmaxf(sqrtf(cb), EPSV);
        const float gs = geo[h];
        const float p2 = gs / sc;
        const float cc = cb * cb;

        float xy0 = 0.f, xy1 = 0.f, xy2 = 0.f, xy3 = 0.f, q2 = 0.f;
        {
            const float* qrow = &Qs[qi * QS_STR];
            const float* kr = &Ks[(qi + kg) * KS_STR];
#pragma unroll 8
            for (int d = 0; d < HD_; d++) {
                float qv = qrow[d];
                q2  = fmaf(qv, qv, q2);
                xy0 = fmaf(qv, kr[d], xy0);
                xy1 = fmaf(qv, kr[d + 16 * KS_STR], xy1);
                xy2 = fmaf(qv, kr[d + 32 * KS_STR], xy2);
                xy3 = fmaf(qv, kr[d + 48 * KS_STR], xy3);
            }
        }
        {
            const float Bc = 1.f - cb * q2;
            const float c2x2 = cc * q2;
            float xys[4] = {xy0, xy1, xy2, xy3};
#pragma unroll
            for (int j = 0; j < 4; j++) {
                float xy = xys[j];
                float y2 = y2s[qi + kg + 16 * j];
                float u  = fmaf(-2.f * cb, xy, 1.f);
                float A  = fmaf(cb, y2, u);
                float dn2 = fmaf(A * A, q2, fmaf(Bc * Bc, y2, -2.f * A * Bc * xy));
                float den = fmaxf(fmaf(c2x2, y2, u), EPSV);
                float s   = sc * sqrt_fast(fmaxf(dn2, 0.f));
                float ratio = __fdividef(den - s, den + s);
                ratio = fmaxf(ratio, RMIN_);
                Sw[qi * SW_STR + kg + 16 * j] = p2 * __log2f(ratio);
            }
        }
        __syncthreads();

#pragma unroll
        for (int qq = 0; qq < 2; qq++) {
            int q = w + qq * 8;
            float s0 = Sw[q * SW_STR + l];
            float s1 = Sw[q * SW_STR + 32 + l];
            float m = warpmax(fmaxf(s0, s1));
            float e0 = exp2f(s0 - m), e1 = exp2f(s1 - m);
            float inv = __fdividef(1.f, warpsum(e0 + e1));
            Sw[q * SW_STR + l] = e0 * inv;
            Sw[q * SW_STR + 32 + l] = e1 * inv;
        }
        __syncthreads();

#pragma unroll
        for (int i = 0; i < 5; i++) {
            int f = tid + i * 256;
            if (f < KR2 * 16) {
                int row = f >> 4, c4 = (f & 15) << 2;
                *(float4*)&Ks[row * HD_ + c4] = vreg[i];
            }
        }
        __syncthreads();

        {
            const int dg = tid & 15;
            float4 acc = make_float4(0.f, 0.f, 0.f, 0.f);
            const float* wrow = &Sw[qi * SW_STR];
            const float* vbase = &Ks[qi * HD_ + dg * 4];
#pragma unroll 8
            for (int k = 0; k < WIN_; k++) {
                float wk = wrow[k];
                float4 vv = *(const float4*)(vbase + k * HD_);
                acc.x = fmaf(wk, vv.x, acc.x);
                acc.y = fmaf(wk, vv.y, acc.y);
                acc.z = fmaf(wk, vv.z, acc.z);
                acc.w = fmaf(wk, vv.w, acc.w);
            }
            __half* orow = attn_out + ((size_t)(b * N_ + n0 + qi)) * DIM_ + h * HD_ + dg * 4;
            *(uint2*)orow = make_uint2(packh2(acc.x, acc.y), packh2(acc.z, acc.w));
        }
        __syncthreads();
    }
}

// ------------------------ launch --------------------------------------------
extern "C" void kernel_launch(void* const* d_in, const int* in_sizes, int n_in,
                              void* d_out, int out_size) {
    (void)in_sizes; (void)n_in; (void)out_size;
    const float* x     = (const float*)d_in[0];
    const float* fcos  = (const float*)d_in[1];
    const float* fsin  = (const float*)d_in[2];
    const float* c     = (const float*)d_in[3];
    const float* Wq    = (const float*)d_in[4];
    const float* bq    = (const float*)d_in[5];
    const float* Wk    = (const float*)d_in[6];
    const float* bk    = (const float*)d_in[7];
    const float* Wv    = (const float*)d_in[8];
    const float* bv    = (const float*)d_in[9];
    const float* Wo    = (const float*)d_in[10];
    const float* bo    = (const float*)d_in[11];
    const float* W1    = (const float*)d_in[12];
    const float* b1    = (const float*)d_in[13];
    const float* W2    = (const float*)d_in[14];
    const float* b2    = (const float*)d_in[15];
    const float* ln1s  = (const float*)d_in[16];
    const float* ln1b  = (const float*)d_in[17];
    const float* ln2s  = (const float*)d_in[18];
    const float* ln2b  = (const float*)d_in[19];
    const float* geo   = (const float*)d_in[20];
    const float* hasho = (const float*)d_in[21];
    float* out = (float*)d_out;

    __half *xnh, *attnh, *hhh, *midh, *wh;
    float *q, *k, *v, *qh, *kh, *vt, *xout;
    cudaGetSymbolAddress((void**)&xnh,   g_xnh);
    cudaGetSymbolAddress((void**)&q,     g_q);
    cudaGetSymbolAddress((void**)&k,     g_k);
    cudaGetSymbolAddress((void**)&v,     g_v);
    cudaGetSymbolAddress((void**)&qh,    g_qh);
    cudaGetSymbolAddress((void**)&kh,    g_kh);
    cudaGetSymbolAddress((void**)&vt,    g_vt);
    cudaGetSymbolAddress((void**)&attnh, g_attnh);
    cudaGetSymbolAddress((void**)&xout,  g_xout);
    cudaGetSymbolAddress((void**)&hhh,   g_hhh);
    cudaGetSymbolAddress((void**)&midh,  g_midh);
    cudaGetSymbolAddress((void**)&wh,    g_wh);

    // 0) weights fp32 -> fp16 (once per launch)
    cvt_w_kernel<<<3072, 256>>>(Wq, Wk, Wv, Wo, W1, W2, wh);

    // 1) LN1 (half out)
    ln_kernel<<<M_, 128>>>(x, ln1s, ln1b, xnh);

    // 2) fused QKV projections (128x128 tiles, 192 CTAs)
    dim3 gqkv(DIM_ / 128, M_ / 128, 3);
    k_gemm_qkv<<<gqkv, 256>>>(xnh, wh, bq, bk, bv, q, k, v);

    // 3) hash + rope + expmap0 + transpose (fast tanh)
    prep_kernel<<<M_, 256>>>(q, k, v, fcos, fsin, c, hasho, qh, kh, vt);

    // 4) sliding-window Poincaré attention (512 CTAs = exactly 2 tiles each)
    attn2_kernel<<<ATT_GRID, 256>>>(qh, kh, vt, c, geo, attnh);

    // 5) Wo projection + residual(x) -> xout (128x64 tiles, 128 CTAs)
    dim3 gwo(DIM_ / 64, M_ / 128);
    k_gemm64_res<<<gwo, 256>>>(attnh, wh + WH_O, bo, x, xout, DIM_, DIM_);

    // 6) LN2 (half out)
    ln_kernel<<<M_, 128>>>(xout, ln2s, ln2b, hhh);

    // 7) FFN1 + gelu (128x128 tiles, 256 CTAs)
    dim3 gffn1(DFF_ / 128, M_ / 128);
    k_gemm128_gelu<<<gffn1, 256>>>(hhh, wh + WH_1, b1, midh, DFF_, DIM_);

    // 8) FFN2 + residual(xout) -> out (128x64 tiles, 128 CTAs)
    k_gemm64_res<<<gwo, 256>>>(midh, wh + WH_2, b2, xout, out, DIM_, DFF_);
}

// round 13
// speedup vs baseline: 2.7934x; 1.0631x over previous
#include <cuda_runtime.h>
#include <cuda_bf16.h>
#include <cuda_fp16.h>
#include <math.h>
#include <cstdint>

#define B_    2
#define N_    1024
#define DIM_  512
#define NH_   8
#define HD_   64
#define WIN_  64
#define M_    (B_ * N_)      // 2048
#define DFF_  (4 * DIM_)     // 2048
#define EPSV  1e-7f

// ------------------------ scratch (device globals; no allocation) ------------
__device__ __half g_xnh [M_ * DIM_];    // LN1 out (half)
__device__ __half g_q   [M_ * DIM_];    // QKV outs (half)
__device__ __half g_k   [M_ * DIM_];
__device__ __half g_v   [M_ * DIM_];
__device__ __half g_qh  [B_ * NH_ * N_ * HD_];   // prep outs (half)
__device__ __half g_kh  [B_ * NH_ * N_ * HD_];
__device__ __half g_vt  [B_ * NH_ * N_ * HD_];
__device__ __half g_attnh[M_ * DIM_];   // attention out (half)
__device__ float  g_xout[M_ * DIM_];
__device__ __half g_hhh [M_ * DIM_];    // LN2 out (half)
__device__ __half g_midh[M_ * DFF_];    // FFN mid (half)
// half weights, concatenated
#define WH_Q 0
#define WH_K 262144
#define WH_V 524288
#define WH_O 786432
#define WH_1 1048576
#define WH_2 2097152
__device__ __half g_wh[3145728];

// ------------------------ helpers -------------------------------------------
__device__ __forceinline__ float warpsum(float v) {
#pragma unroll
    for (int o = 16; o > 0; o >>= 1) v += __shfl_xor_sync(0xffffffffu, v, o);
    return v;
}
__device__ __forceinline__ float warpmax(float v) {
#pragma unroll
    for (int o = 16; o > 0; o >>= 1) v = fmaxf(v, __shfl_xor_sync(0xffffffffu, v, o));
    return v;
}
__device__ __forceinline__ float sqrt_fast(float x) {
    float r;
    asm("sqrt.approx.f32 %0, %1;" : "=f"(r) : "f"(x));
    return r;
}
__device__ __forceinline__ uint32_t packh2(float lo, float hi) {
    __half2 h = __floats2half2_rn(lo, hi);
    return *(uint32_t*)&h;
}
__device__ __forceinline__ float2 unpackh2(uint32_t u) {
    return __half22float2(*(__half2*)&u);
}
// fast tanh for x >= 0:  tanh(x) = 1 - 2/(1+e^{2x})
__device__ __forceinline__ float tanh_pos(float x) {
    return 1.f - __fdividef(2.f, 1.f + __expf(2.f * x));
}
// fp16 tensor-core mma: D(f32) += A(f16,16x16) * B(f16,16x8)
__device__ __forceinline__ void mma_f16(float4& c, uint32_t a0, uint32_t a1,
                                        uint32_t a2, uint32_t a3,
                                        uint32_t b0, uint32_t b1) {
    asm volatile(
        "mma.sync.aligned.m16n8k16.row.col.f32.f16.f16.f32 "
        "{%0,%1,%2,%3},{%4,%5,%6,%7},{%8,%9},{%0,%1,%2,%3};\n"
        : "+f"(c.x), "+f"(c.y), "+f"(c.z), "+f"(c.w)
        : "r"(a0), "r"(a1), "r"(a2), "r"(a3), "r"(b0), "r"(b1));
}

// ------------------------ weight fp32 -> fp16 convert ------------------------
__global__ __launch_bounds__(256) void cvt_w_kernel(
    const float* __restrict__ Wq, const float* __restrict__ Wk,
    const float* __restrict__ Wv, const float* __restrict__ Wo,
    const float* __restrict__ W1, const float* __restrict__ W2,
    __half* __restrict__ out) {
    long i = ((long)blockIdx.x * 256 + threadIdx.x) * 4;   // 4 elems/thread
    if (i >= 3145728) return;
    const float* src;
    long off;
    if      (i <  262144) { src = Wq; off = i; }
    else if (i <  524288) { src = Wk; off = i - 262144; }
    else if (i <  786432) { src = Wv; off = i - 524288; }
    else if (i < 1048576) { src = Wo; off = i - 786432; }
    else if (i < 2097152) { src = W1; off = i - 1048576; }
    else                  { src = W2; off = i - 2097152; }
    float4 v = *(const float4*)(src + off);
    uint2 o = make_uint2(packh2(v.x, v.y), packh2(v.z, v.w));
    *(uint2*)(out + i) = o;
}

// ------------------------ layernorm (half output) ----------------------------
__global__ void ln_kernel(const float* __restrict__ x, const float* __restrict__ s,
                          const float* __restrict__ bsh, __half* __restrict__ out) {
    int row = blockIdx.x;
    const float* xr = x + (size_t)row * DIM_;
    float v[4];
    float sum = 0.f, sq = 0.f;
#pragma unroll
    for (int i = 0; i < 4; i++) {
        v[i] = xr[threadIdx.x + i * 128];
        sum += v[i];
        sq  += v[i] * v[i];
    }
    __shared__ float red0[4], red1[4];
    sum = warpsum(sum); sq = warpsum(sq);
    int warp = threadIdx.x >> 5, lane = threadIdx.x & 31;
    if (lane == 0) { red0[warp] = sum; red1[warp] = sq; }
    __syncthreads();
    sum = red0[0] + red0[1] + red0[2] + red0[3];
    sq  = red1[0] + red1[1] + red1[2] + red1[3];
    float mean = sum * (1.0f / DIM_);
    float var  = sq * (1.0f / DIM_) - mean * mean;
    float inv  = rsqrtf(var + 1e-6f);
    __half* orow = out + (size_t)row * DIM_;
#pragma unroll
    for (int i = 0; i < 4; i++) {
        int d = threadIdx.x + i * 128;
        orow[d] = __float2half_rn((v[i] - mean) * inv * s[d] + bsh[d]);
    }
}

// ======================= 128x128 fp16 GEMM (QKV / FFN1) ======================
struct GSmem128 {
    uint2 Ap[2][2][4][132];  // [buf][ks16][tg][row 0..127]
    uint2 Bp[2][2][4][132];  // [buf][ks16][tg][col 0..127]
};

// EPI: 2 = gelu+bias (half out), 3 = +bias (half out)
template <int EPI>
__device__ __forceinline__ void gemm_core128(
    const __half* __restrict__ A, const __half* __restrict__ Bw,
    const float* __restrict__ bias, __half* __restrict__ Ch, int Nd, int Kd) {
    __shared__ GSmem128 sm;
    const int m0 = blockIdx.y * 128, n0 = blockIdx.x * 128;
    const int tid = threadIdx.x;
    const int lane = tid & 31, wid = tid >> 5;
    const int g = lane >> 2, tg = lane & 3;
    const int wm = wid >> 2, wn = wid & 3;       // warp grid 2x4

    const int arow = tid >> 1, akh = tid & 1;
    const __half* aPtr = A + (size_t)(m0 + arow) * Kd + akh * 16;
    const int btg = (tid >> 6) & 3, bcp = tid & 63;
    const __half* bPtr0 = Bw + (size_t)(2 * btg) * Nd + n0 + 2 * bcp;
    const __half* bPtr1 = bPtr0 + (size_t)16 * Nd;

    float4 acc[4][4];
#pragma unroll
    for (int i = 0; i < 4; i++)
#pragma unroll
        for (int j = 0; j < 4; j++) acc[i][j] = make_float4(0.f, 0.f, 0.f, 0.f);

    uint4 alo, ahi;
    uint32_t wv[2][4];
    alo = *(const uint4*)(aPtr);
    ahi = *(const uint4*)(aPtr + 8);
#pragma unroll
    for (int s = 0; s < 2; s++) {
        const __half* bp = s ? bPtr1 : bPtr0;
        wv[s][0] = *(const uint32_t*)(bp);
        wv[s][1] = *(const uint32_t*)(bp + Nd);
        wv[s][2] = *(const uint32_t*)(bp + 8 * Nd);
        wv[s][3] = *(const uint32_t*)(bp + 9 * Nd);
    }

    auto store_tile = [&](int buf) {
        sm.Ap[buf][akh][0][arow] = make_uint2(alo.x, ahi.x);
        sm.Ap[buf][akh][1][arow] = make_uint2(alo.y, ahi.y);
        sm.Ap[buf][akh][2][arow] = make_uint2(alo.z, ahi.z);
        sm.Ap[buf][akh][3][arow] = make_uint2(alo.w, ahi.w);
#pragma unroll
        for (int s = 0; s < 2; s++) {
            uint32_t lo0 = __byte_perm(wv[s][0], wv[s][1], 0x5410);
            uint32_t lo1 = __byte_perm(wv[s][0], wv[s][1], 0x7632);
            uint32_t hi0 = __byte_perm(wv[s][2], wv[s][3], 0x5410);
            uint32_t hi1 = __byte_perm(wv[s][2], wv[s][3], 0x7632);
            *(uint4*)&sm.Bp[buf][s][btg][2 * bcp] = make_uint4(lo0, hi0, lo1, hi1);
        }
    };

    store_tile(0);
    __syncthreads();

    const int nT = Kd >> 5;
    for (int t = 0; t < nT; t++) {
        const int buf = t & 1;
        const bool more = (t + 1 < nT);
        if (more) {
            const __half* ap = aPtr + (t + 1) * 32;
            alo = *(const uint4*)(ap);
            ahi = *(const uint4*)(ap + 8);
            const size_t koff = (size_t)(t + 1) * 32 * Nd;
#pragma unroll
            for (int s = 0; s < 2; s++) {
                const __half* bp = (s ? bPtr1 : bPtr0) + koff;
                wv[s][0] = *(const uint32_t*)(bp);
                wv[s][1] = *(const uint32_t*)(bp + Nd);
                wv[s][2] = *(const uint32_t*)(bp + 8 * Nd);
                wv[s][3] = *(const uint32_t*)(bp + 9 * Nd);
            }
        }
#pragma unroll
        for (int ks = 0; ks < 2; ks++) {
            uint2 fal[4], fah[4], fb[4];
#pragma unroll
            for (int mi = 0; mi < 4; mi++) {
                fal[mi] = sm.Ap[buf][ks][tg][wm * 64 + mi * 16 + g];
                fah[mi] = sm.Ap[buf][ks][tg][wm * 64 + mi * 16 + g + 8];
            }
#pragma unroll
            for (int nj = 0; nj < 4; nj++)
                fb[nj] = sm.Bp[buf][ks][tg][wn * 32 + nj * 8 + g];
#pragma unroll
            for (int mi = 0; mi < 4; mi++)
#pragma unroll
                for (int nj = 0; nj < 4; nj++)
                    mma_f16(acc[mi][nj],
                            fal[mi].x, fah[mi].x, fal[mi].y, fah[mi].y,
                            fb[nj].x, fb[nj].y);
        }
        if (more) store_tile(buf ^ 1);
        __syncthreads();
    }

#pragma unroll
    for (int mi = 0; mi < 4; mi++) {
        int r0 = m0 + wm * 64 + mi * 16 + g;
#pragma unroll
        for (int nj = 0; nj < 4; nj++) {
            int col = n0 + wn * 32 + nj * 8 + tg * 2;
            float2 bbv = *(const float2*)(bias + col);
            float4 a = acc[mi][nj];
            float2 o0 = make_float2(a.x + bbv.x, a.y + bbv.y);
            float2 o1 = make_float2(a.z + bbv.x, a.w + bbv.y);
            if (EPI == 2) {
                float t0 = o0.x, t1 = o0.y, t2 = o1.x, t3 = o1.y;
                o0.x = t0 / (1.f + __expf(-1.5957691216057308f * (t0 + 0.044715f * t0 * t0 * t0)));
                o0.y = t1 / (1.f + __expf(-1.5957691216057308f * (t1 + 0.044715f * t1 * t1 * t1)));
                o1.x = t2 / (1.f + __expf(-1.5957691216057308f * (t2 + 0.044715f * t2 * t2 * t2)));
                o1.y = t3 / (1.f + __expf(-1.5957691216057308f * (t3 + 0.044715f * t3 * t3 * t3)));
            }
            *(uint32_t*)(Ch + (size_t)r0 * Nd + col)       = packh2(o0.x, o0.y);
            *(uint32_t*)(Ch + (size_t)(r0 + 8) * Nd + col) = packh2(o1.x, o1.y);
        }
    }
}

__global__ __launch_bounds__(256, 2) void k_gemm_qkv(
    const __half* __restrict__ xn, const __half* __restrict__ wh,
    const float* __restrict__ bq, const float* __restrict__ bk,
    const float* __restrict__ bv,
    __half* __restrict__ q, __half* __restrict__ k, __half* __restrict__ v) {
    int z = blockIdx.z;
    const __half* W  = wh + ((z == 0) ? WH_Q : (z == 1) ? WH_K : WH_V);
    const float* bb  = (z == 0) ? bq : (z == 1) ? bk : bv;
    __half* o        = (z == 0) ? q  : (z == 1) ? k  : v;
    gemm_core128<3>(xn, W, bb, o, DIM_, DIM_);
}

__global__ __launch_bounds__(256, 2) void k_gemm128_gelu(
    const __half* __restrict__ A, const __half* __restrict__ W,
    const float* __restrict__ bias, __half* __restrict__ C, int Nd, int Kd) {
    gemm_core128<2>(A, W, bias, C, Nd, Kd);
}

// ======================= 128x64 fp16 GEMM (Wo / FFN2, +residual, f32 out) ====
struct GSmem64 {
    uint2 Ap[2][2][4][132];
    uint2 Bp[2][2][4][68];
};

__global__ __launch_bounds__(256, 3) void k_gemm64_res(
    const __half* __restrict__ A, const __half* __restrict__ Bw,
    const float* __restrict__ bias, const float* __restrict__ res,
    float* __restrict__ C, int Nd, int Kd) {
    __shared__ GSmem64 sm;
    const int m0 = blockIdx.y * 128, n0 = blockIdx.x * 64;
    const int tid = threadIdx.x;
    const int lane = tid & 31, wid = tid >> 5;
    const int g = lane >> 2, tg = lane & 3;
    const int wm = wid >> 1, wn = wid & 1;

    const int arow = tid >> 1, akh = tid & 1;
    const __half* aPtr = A + (size_t)(m0 + arow) * Kd + akh * 16;
    const int bks = tid >> 7, btg = (tid >> 5) & 3, bcp = tid & 31;
    const __half* bPtr = Bw + (size_t)(bks * 16 + 2 * btg) * Nd + n0 + 2 * bcp;

    float4 acc[2][4];
#pragma unroll
    for (int i = 0; i < 2; i++)
#pragma unroll
        for (int j = 0; j < 4; j++) acc[i][j] = make_float4(0.f, 0.f, 0.f, 0.f);

    uint4 alo, ahi;
    uint32_t w0, w1, w2, w3;
    alo = *(const uint4*)(aPtr);
    ahi = *(const uint4*)(aPtr + 8);
    w0 = *(const uint32_t*)(bPtr);
    w1 = *(const uint32_t*)(bPtr + Nd);
    w2 = *(const uint32_t*)(bPtr + 8 * Nd);
    w3 = *(const uint32_t*)(bPtr + 9 * Nd);

    auto store_tile = [&](int buf) {
        sm.Ap[buf][akh][0][arow] = make_uint2(alo.x, ahi.x);
        sm.Ap[buf][akh][1][arow] = make_uint2(alo.y, ahi.y);
        sm.Ap[buf][akh][2][arow] = make_uint2(alo.z, ahi.z);
        sm.Ap[buf][akh][3][arow] = make_uint2(alo.w, ahi.w);
        uint32_t lo0 = __byte_perm(w0, w1, 0x5410);
        uint32_t lo1 = __byte_perm(w0, w1, 0x7632);
        uint32_t hi0 = __byte_perm(w2, w3, 0x5410);
        uint32_t hi1 = __byte_perm(w2, w3, 0x7632);
        *(uint4*)&sm.Bp[buf][bks][btg][2 * bcp] = make_uint4(lo0, hi0, lo1, hi1);
    };

    store_tile(0);
    __syncthreads();

    const int nT = Kd >> 5;
    for (int t = 0; t < nT; t++) {
        const int buf = t & 1;
        const bool more = (t + 1 < nT);
        if (more) {
            const __half* ap = aPtr + (t + 1) * 32;
            alo = *(const uint4*)(ap);
            ahi = *(const uint4*)(ap + 8);
            const __half* bp = bPtr + (size_t)(t + 1) * 32 * Nd;
            w0 = *(const uint32_t*)(bp);
            w1 = *(const uint32_t*)(bp + Nd);
            w2 = *(const uint32_t*)(bp + 8 * Nd);
            w3 = *(const uint32_t*)(bp + 9 * Nd);
        }
#pragma unroll
        for (int ks = 0; ks < 2; ks++) {
            uint2 fal[2], fah[2], fb[4];
#pragma unroll
            for (int mi = 0; mi < 2; mi++) {
                fal[mi] = sm.Ap[buf][ks][tg][wm * 32 + mi * 16 + g];
                fah[mi] = sm.Ap[buf][ks][tg][wm * 32 + mi * 16 + g + 8];
            }
#pragma unroll
            for (int nj = 0; nj < 4; nj++)
                fb[nj] = sm.Bp[buf][ks][tg][wn * 32 + nj * 8 + g];
#pragma unroll
            for (int mi = 0; mi < 2; mi++)
#pragma unroll
                for (int nj = 0; nj < 4; nj++)
                    mma_f16(acc[mi][nj],
                            fal[mi].x, fah[mi].x, fal[mi].y, fah[mi].y,
                            fb[nj].x, fb[nj].y);
        }
        if (more) store_tile(buf ^ 1);
        __syncthreads();
    }

#pragma unroll
    for (int mi = 0; mi < 2; mi++) {
        int r0 = m0 + wm * 32 + mi * 16 + g;
#pragma unroll
        for (int nj = 0; nj < 4; nj++) {
            int col = n0 + wn * 32 + nj * 8 + tg * 2;
            float2 bbv = *(const float2*)(bias + col);
            float4 a = acc[mi][nj];
            float2 r0v = *(const float2*)(res + (size_t)r0 * Nd + col);
            float2 r1v = *(const float2*)(res + (size_t)(r0 + 8) * Nd + col);
            float2 o0 = make_float2(a.x + bbv.x + r0v.x, a.y + bbv.y + r0v.y);
            float2 o1 = make_float2(a.z + bbv.x + r1v.x, a.w + bbv.y + r1v.y);
            *(float2*)(C + (size_t)r0 * Nd + col)       = o0;
            *(float2*)(C + (size_t)(r0 + 8) * Nd + col) = o1;
        }
    }
}

// ------------------------ prep (half in, half out) ---------------------------
__global__ void prep_kernel(const __half* __restrict__ qb, const __half* __restrict__ kb,
                            const __half* __restrict__ vb, const float* __restrict__ cos_t,
                            const float* __restrict__ sin_t, const float* __restrict__ c_arr,
                            const float* __restrict__ hash_off,
                            __half* __restrict__ qh, __half* __restrict__ kh,
                            __half* __restrict__ vt) {
    int bn = blockIdx.x;
    int b = bn / N_, n = bn % N_;
    int h = threadIdx.x >> 5, lane = threadIdx.x & 31;
    const float LOG9 = 2.1972245773362196f;
    float cs = cos_t[n * 32 + lane];
    float sn = sin_t[n * 32 + lane];
    float cb = c_arr[b];
    float sqrt_c = fmaxf(sqrtf(cb), EPSV);
    size_t in_off  = (size_t)bn * DIM_ + h * HD_;
    size_t out_off = (((size_t)(b * NH_ + h)) * N_ + n) * HD_;

    {
        float v0 = __half2float(qb[in_off + lane])      + hash_off[h * HD_ + lane]      * LOG9;
        float v1 = __half2float(qb[in_off + lane + 32]) + hash_off[h * HD_ + lane + 32] * LOG9;
        float r0 = v0 * cs - v1 * sn;
        float r1 = v0 * sn + v1 * cs;
        float nrm = sqrtf(warpsum(r0 * r0 + r1 * r1));
        float o0 = 0.f, o1 = 0.f;
        if (nrm >= EPSV) {
            float safe = fmaxf(nrm, EPSV);
            float mag  = __fdividef(tanh_pos(sqrt_c * safe), sqrt_c);
            float sc   = __fdividef(mag, safe);
            o0 = sc * r0; o1 = sc * r1;
        }
        qh[out_off + lane] = __float2half_rn(o0);
        qh[out_off + lane + 32] = __float2half_rn(o1);
    }
    {
        float v0 = __half2float(kb[in_off + lane]);
        float v1 = __half2float(kb[in_off + lane + 32]);
        float r0 = v0 * cs - v1 * sn;
        float r1 = v0 * sn + v1 * cs;
        float nrm = sqrtf(warpsum(r0 * r0 + r1 * r1));
        float o0 = 0.f, o1 = 0.f;
        if (nrm >= EPSV) {
            float safe = fmaxf(nrm, EPSV);
            float mag  = __fdividef(tanh_pos(sqrt_c * safe), sqrt_c);
            float sc   = __fdividef(mag, safe);
            o0 = sc * r0; o1 = sc * r1;
        }
        kh[out_off + lane] = __float2half_rn(o0);
        kh[out_off + lane + 32] = __float2half_rn(o1);
    }
    vt[out_off + lane]      = vb[in_off + lane];
    vt[out_off + lane + 32] = vb[in_off + lane + 32];
}

// ------------------------ windowed Poincaré attention (half K/V) -------------
#define QT2    16
#define KR2    (QT2 + WIN_ - 1)   // 79
#define KU_STR 33                 // uint (half2) stride: rows -> consecutive banks
#define QS_STR 68
#define SW_STR 65
#define NTILES ((N_ / QT2) * B_ * NH_)   // 1024
#define ATT_GRID 512
#define RMIN_  5.0000003e-8f             // (1e-7)/(2-1e-7)

__global__ __launch_bounds__(256, 4) void attn2_kernel(
    const __half* __restrict__ qh, const __half* __restrict__ kh,
    const __half* __restrict__ vt, const float* __restrict__ c_arr,
    const float* __restrict__ geo, __half* __restrict__ attn_out) {
    __shared__ uint32_t Ku[KR2 * KU_STR + 4];   // K tile (half2); reused for V
    __shared__ __align__(16) float Qs[QT2 * QS_STR];
    __shared__ float Sw[QT2 * SW_STR];
    __shared__ float y2s[KR2 + 1];

    const int tid = threadIdx.x;
    const int w = tid >> 5, l = tid & 31;
    const int qi = tid >> 4;
    const int kg = tid & 15;

    for (int t = blockIdx.x; t < NTILES; t += ATT_GRID) {
        const int bh = t >> 6;
        const int b = bh >> 3, h = bh & 7;
        const int n0 = (t & 63) << 4;
        const __half* Kb = kh + (size_t)bh * (N_ * HD_);
        const __half* Vb = vt + (size_t)bh * (N_ * HD_);
        const __half* Qb = qh + (size_t)bh * (N_ * HD_);

        // ---- K tile -> smem (uint4 gmem loads, scalar STS at stride 33)
#pragma unroll
        for (int i = 0; i < 3; i++) {
            int f = tid + i * 256;
            if (f < KR2 * 8) {
                int row = f >> 3, u4 = (f & 7) * 4;
                int gn = n0 - (WIN_ - 1) + row;
                uint4 val = make_uint4(0u, 0u, 0u, 0u);
                if (gn >= 0) val = *(const uint4*)(Kb + (size_t)gn * HD_ + u4 * 2);
                uint32_t* d = &Ku[row * KU_STR + u4];
                d[0] = val.x; d[1] = val.y; d[2] = val.z; d[3] = val.w;
            }
        }
        // ---- Q tile -> smem f32 (half gmem -> float)
        {
            int row = tid >> 4, c4 = (tid & 15) * 4;
            uint2 qv = *(const uint2*)(Qb + (size_t)(n0 + row) * HD_ + c4);
            float2 a = unpackh2(qv.x), bb = unpackh2(qv.y);
            *(float4*)&Qs[row * QS_STR + c4] = make_float4(a.x, a.y, bb.x, bb.y);
        }
        // ---- prefetch V into registers
        uint4 vreg[3];
#pragma unroll
        for (int i = 0; i < 3; i++) {
            int f = tid + i * 256;
            vreg[i] = make_uint4(0u, 0u, 0u, 0u);
            if (f < KR2 * 8) {
                int row = f >> 3, u4 = (f & 7) * 4;
                int gn = n0 - (WIN_ - 1) + row;
                if (gn >= 0) vreg[i] = *(const uint4*)(Vb + (size_t)gn * HD_ + u4 * 2);
            }
        }
        __syncthreads();

        // ---- y2 per key row (1 LDS per lane: 32 uint = 64 halves)
        for (int row = w; row < KR2; row += 8) {
            float2 f = unpackh2(Ku[row * KU_STR + l]);
            float s = warpsum(f.x * f.x + f.y * f.y);
            if (l == 0) y2s[row] = s;
        }
        __syncthreads();

        const float cb = c_arr[b];
        const float sc = fmaxf(sqrtf(cb), EPSV);
        const float gs = geo[h];
        const float p2 = gs / sc;
        const float cc = cb * cb;

        // ---- dots: thread = (query qi, keys kg+16j), 2 dims per iter
        float xy0 = 0.f, xy1 = 0.f, xy2 = 0.f, xy3 = 0.f, q2 = 0.f;
        {
            const float* qrow = &Qs[qi * QS_STR];
            const uint32_t* kr = &Ku[(qi + kg) * KU_STR];
#pragma unroll 8
            for (int d2 = 0; d2 < 32; d2++) {
                float2 qv = *(const float2*)(qrow + 2 * d2);
                float2 f0 = unpackh2(kr[d2]);
                float2 f1 = unpackh2(kr[d2 + 16 * KU_STR]);
                float2 f2 = unpackh2(kr[d2 + 32 * KU_STR]);
                float2 f3 = unpackh2(kr[d2 + 48 * KU_STR]);
                q2  = fmaf(qv.x, qv.x, fmaf(qv.y, qv.y, q2));
                xy0 = fmaf(qv.x, f0.x, fmaf(qv.y, f0.y, xy0));
                xy1 = fmaf(qv.x, f1.x, fmaf(qv.y, f1.y, xy1));
                xy2 = fmaf(qv.x, f2.x, fmaf(qv.y, f2.y, xy2));
                xy3 = fmaf(qv.x, f3.x, fmaf(qv.y, f3.y, xy3));
            }
        }
        {
            const float Bc = 1.f - cb * q2;
            const float c2x2 = cc * q2;
            float xys[4] = {xy0, xy1, xy2, xy3};
#pragma unroll
            for (int j = 0; j < 4; j++) {
                float xy = xys[j];
                float y2 = y2s[qi + kg + 16 * j];
                float u  = fmaf(-2.f * cb, xy, 1.f);
                float A  = fmaf(cb, y2, u);
                float dn2 = fmaf(A * A, q2, fmaf(Bc * Bc, y2, -2.f * A * Bc * xy));
                float den = fmaxf(fmaf(c2x2, y2, u), EPSV);
                float s   = sc * sqrt_fast(fmaxf(dn2, 0.f));
                float ratio = __fdividef(den - s, den + s);
                ratio = fmaxf(ratio, RMIN_);
                Sw[qi * SW_STR + kg + 16 * j] = p2 * __log2f(ratio);
            }
        }
        __syncthreads();

        // ---- softmax (base-2)
#pragma unroll
        for (int qq = 0; qq < 2; qq++) {
            int q = w + qq * 8;
            float s0 = Sw[q * SW_STR + l];
            float s1 = Sw[q * SW_STR + 32 + l];
            float m = warpmax(fmaxf(s0, s1));
            float e0 = exp2f(s0 - m), e1 = exp2f(s1 - m);
            float inv = __fdividef(1.f, warpsum(e0 + e1));
            Sw[q * SW_STR + l] = e0 * inv;
            Sw[q * SW_STR + 32 + l] = e1 * inv;
        }
        __syncthreads();

        // ---- V regs -> smem (same stride-33 layout)
#pragma unroll
        for (int i = 0; i < 3; i++) {
            int f = tid + i * 256;
            if (f < KR2 * 8) {
                int row = f >> 3, u4 = (f & 7) * 4;
                uint32_t* d = &Ku[row * KU_STR + u4];
                d[0] = vreg[i].x; d[1] = vreg[i].y; d[2] = vreg[i].z; d[3] = vreg[i].w;
            }
        }
        __syncthreads();

        // ---- AV: thread = (query qi, dims dg*4..+3); 2 LDS.32 + broadcast/iter
        {
            const int dg = tid & 15;
            float4 acc = make_float4(0.f, 0.f, 0.f, 0.f);
            const float* wrow = &Sw[qi * SW_STR];
            const uint32_t* vbase = &Ku[qi * KU_STR + dg * 2];
#pragma unroll 8
            for (int k = 0; k < WIN_; k++) {
                float wk = wrow[k];
                uint32_t v0 = vbase[k * KU_STR];
                uint32_t v1 = vbase[k * KU_STR + 1];
                float2 a = unpackh2(v0), bb = unpackh2(v1);
                acc.x = fmaf(wk, a.x, acc.x);
                acc.y = fmaf(wk, a.y, acc.y);
                acc.z = fmaf(wk, bb.x, acc.z);
                acc.w = fmaf(wk, bb.y, acc.w);
            }
            __half* orow = attn_out + ((size_t)(b * N_ + n0 + qi)) * DIM_ + h * HD_ + dg * 4;
            *(uint2*)orow = make_uint2(packh2(acc.x, acc.y), packh2(acc.z, acc.w));
        }
        __syncthreads();
    }
}

// ------------------------ launch --------------------------------------------
extern "C" void kernel_launch(void* const* d_in, const int* in_sizes, int n_in,
                              void* d_out, int out_size) {
    (void)in_sizes; (void)n_in; (void)out_size;
    const float* x     = (const float*)d_in[0];
    const float* fcos  = (const float*)d_in[1];
    const float* fsin  = (const float*)d_in[2];
    const float* c     = (const float*)d_in[3];
    const float* Wq    = (const float*)d_in[4];
    const float* bq    = (const float*)d_in[5];
    const float* Wk    = (const float*)d_in[6];
    const float* bk    = (const float*)d_in[7];
    const float* Wv    = (const float*)d_in[8];
    const float* bv    = (const float*)d_in[9];
    const float* Wo    = (const float*)d_in[10];
    const float* bo    = (const float*)d_in[11];
    const float* W1    = (const float*)d_in[12];
    const float* b1    = (const float*)d_in[13];
    const float* W2    = (const float*)d_in[14];
    const float* b2    = (const float*)d_in[15];
    const float* ln1s  = (const float*)d_in[16];
    const float* ln1b  = (const float*)d_in[17];
    const float* ln2s  = (const float*)d_in[18];
    const float* ln2b  = (const float*)d_in[19];
    const float* geo   = (const float*)d_in[20];
    const float* hasho = (const float*)d_in[21];
    float* out = (float*)d_out;

    __half *xnh, *attnh, *hhh, *midh, *wh, *q, *k, *v, *qh, *kh, *vt;
    float *xout;
    cudaGetSymbolAddress((void**)&xnh,   g_xnh);
    cudaGetSymbolAddress((void**)&q,     g_q);
    cudaGetSymbolAddress((void**)&k,     g_k);
    cudaGetSymbolAddress((void**)&v,     g_v);
    cudaGetSymbolAddress((void**)&qh,    g_qh);
    cudaGetSymbolAddress((void**)&kh,    g_kh);
    cudaGetSymbolAddress((void**)&vt,    g_vt);
    cudaGetSymbolAddress((void**)&attnh, g_attnh);
    cudaGetSymbolAddress((void**)&xout,  g_xout);
    cudaGetSymbolAddress((void**)&hhh,   g_hhh);
    cudaGetSymbolAddress((void**)&midh,  g_midh);
    cudaGetSymbolAddress((void**)&wh,    g_wh);

    // 0) weights fp32 -> fp16 (once per launch)
    cvt_w_kernel<<<3072, 256>>>(Wq, Wk, Wv, Wo, W1, W2, wh);

    // 1) LN1 (half out)
    ln_kernel<<<M_, 128>>>(x, ln1s, ln1b, xnh);

    // 2) fused QKV projections (half out)
    dim3 gqkv(DIM_ / 128, M_ / 128, 3);
    k_gemm_qkv<<<gqkv, 256>>>(xnh, wh, bq, bk, bv, q, k, v);

    // 3) hash + rope + expmap0 + transpose (half in/out)
    prep_kernel<<<M_, 256>>>(q, k, v, fcos, fsin, c, hasho, qh, kh, vt);

    // 4) sliding-window Poincaré attention (half K/V in smem)
    attn2_kernel<<<ATT_GRID, 256>>>(qh, kh, vt, c, geo, attnh);

    // 5) Wo projection + residual(x) -> xout (f32)
    dim3 gwo(DIM_ / 64, M_ / 128);
    k_gemm64_res<<<gwo, 256>>>(attnh, wh + WH_O, bo, x, xout, DIM_, DIM_);

    // 6) LN2 (half out)
    ln_kernel<<<M_, 128>>>(xout, ln2s, ln2b, hhh);

    // 7) FFN1 + gelu (half out)
    dim3 gffn1(DFF_ / 128, M_ / 128);
    k_gemm128_gelu<<<gffn1, 256>>>(hhh, wh + WH_1, b1, midh, DFF_, DIM_);

    // 8) FFN2 + residual(xout) -> out (f32)
    k_gemm64_res<<<gwo, 256>>>(midh, wh + WH_2, b2, xout, out, DIM_, DFF_);
}

// round 14
// speedup vs baseline: 2.8592x; 1.0235x over previous
#include <cuda_runtime.h>
#include <cuda_bf16.h>
#include <cuda_fp16.h>
#include <math.h>
#include <cstdint>

#define B_    2
#define N_    1024
#define DIM_  512
#define NH_   8
#define HD_   64
#define WIN_  64
#define M_    (B_ * N_)      // 2048
#define DFF_  (4 * DIM_)     // 2048
#define EPSV  1e-7f

// ------------------------ scratch (device globals; no allocation) ------------
__device__ __half g_xnh [M_ * DIM_];    // LN1 out (half)
__device__ __half g_q   [M_ * DIM_];    // QKV outs (half)
__device__ __half g_k   [M_ * DIM_];
__device__ __half g_v   [M_ * DIM_];
__device__ __half g_qh  [B_ * NH_ * N_ * HD_];   // prep outs (half)
__device__ __half g_kh  [B_ * NH_ * N_ * HD_];
__device__ __half g_vt  [B_ * NH_ * N_ * HD_];
__device__ __half g_attnh[M_ * DIM_];   // attention out (half)
__device__ float  g_xout[M_ * DIM_];
__device__ __half g_hhh [M_ * DIM_];    // LN2 out (half)
__device__ __half g_midh[M_ * DFF_];    // FFN mid (half)
// half weights, concatenated
#define WH_Q 0
#define WH_K 262144
#define WH_V 524288
#define WH_O 786432
#define WH_1 1048576
#define WH_2 2097152
__device__ __half g_wh[3145728];

// ------------------------ helpers -------------------------------------------
__device__ __forceinline__ float warpsum(float v) {
#pragma unroll
    for (int o = 16; o > 0; o >>= 1) v += __shfl_xor_sync(0xffffffffu, v, o);
    return v;
}
__device__ __forceinline__ float warpmax(float v) {
#pragma unroll
    for (int o = 16; o > 0; o >>= 1) v = fmaxf(v, __shfl_xor_sync(0xffffffffu, v, o));
    return v;
}
__device__ __forceinline__ float sqrt_fast(float x) {
    float r;
    asm("sqrt.approx.f32 %0, %1;" : "=f"(r) : "f"(x));
    return r;
}
__device__ __forceinline__ uint32_t packh2(float lo, float hi) {
    __half2 h = __floats2half2_rn(lo, hi);
    return *(uint32_t*)&h;
}
__device__ __forceinline__ float2 unpackh2(uint32_t u) {
    return __half22float2(*(__half2*)&u);
}
// fast tanh for x >= 0:  tanh(x) = 1 - 2/(1+e^{2x})
__device__ __forceinline__ float tanh_pos(float x) {
    return 1.f - __fdividef(2.f, 1.f + __expf(2.f * x));
}
// fp16 tensor-core mma: D(f32) += A(f16,16x16) * B(f16,16x8)
__device__ __forceinline__ void mma_f16(float4& c, uint32_t a0, uint32_t a1,
                                        uint32_t a2, uint32_t a3,
                                        uint32_t b0, uint32_t b1) {
    asm volatile(
        "mma.sync.aligned.m16n8k16.row.col.f32.f16.f16.f32 "
        "{%0,%1,%2,%3},{%4,%5,%6,%7},{%8,%9},{%0,%1,%2,%3};\n"
        : "+f"(c.x), "+f"(c.y), "+f"(c.z), "+f"(c.w)
        : "r"(a0), "r"(a1), "r"(a2), "r"(a3), "r"(b0), "r"(b1));
}

// ------------------------ fused LN1 + weight convert -------------------------
// blocks 0..2047: LN1 rows (128 thr); blocks 2048..8191: weight cvt (512 elems)
__global__ __launch_bounds__(128) void ln1_cvtw_kernel(
    const float* __restrict__ x, const float* __restrict__ s,
    const float* __restrict__ bsh, __half* __restrict__ out,
    const float* __restrict__ Wq, const float* __restrict__ Wk,
    const float* __restrict__ Wv, const float* __restrict__ Wo,
    const float* __restrict__ W1, const float* __restrict__ W2,
    __half* __restrict__ wh) {
    if (blockIdx.x < 2048) {
        int row = blockIdx.x;
        const float* xr = x + (size_t)row * DIM_;
        float v[4];
        float sum = 0.f, sq = 0.f;
#pragma unroll
        for (int i = 0; i < 4; i++) {
            v[i] = xr[threadIdx.x + i * 128];
            sum += v[i];
            sq  += v[i] * v[i];
        }
        __shared__ float red0[4], red1[4];
        sum = warpsum(sum); sq = warpsum(sq);
        int warp = threadIdx.x >> 5, lane = threadIdx.x & 31;
        if (lane == 0) { red0[warp] = sum; red1[warp] = sq; }
        __syncthreads();
        sum = red0[0] + red0[1] + red0[2] + red0[3];
        sq  = red1[0] + red1[1] + red1[2] + red1[3];
        float mean = sum * (1.0f / DIM_);
        float var  = sq * (1.0f / DIM_) - mean * mean;
        float inv  = rsqrtf(var + 1e-6f);
        __half* orow = out + (size_t)row * DIM_;
#pragma unroll
        for (int i = 0; i < 4; i++) {
            int d = threadIdx.x + i * 128;
            orow[d] = __float2half_rn((v[i] - mean) * inv * s[d] + bsh[d]);
        }
    } else {
        long i = ((long)(blockIdx.x - 2048) * 128 + threadIdx.x) * 4;
        if (i >= 3145728) return;
        const float* src;
        long off;
        if      (i <  262144) { src = Wq; off = i; }
        else if (i <  524288) { src = Wk; off = i - 262144; }
        else if (i <  786432) { src = Wv; off = i - 524288; }
        else if (i < 1048576) { src = Wo; off = i - 786432; }
        else if (i < 2097152) { src = W1; off = i - 1048576; }
        else                  { src = W2; off = i - 2097152; }
        float4 v = *(const float4*)(src + off);
        *(uint2*)(wh + i) = make_uint2(packh2(v.x, v.y), packh2(v.z, v.w));
    }
}

// ------------------------ layernorm (half output) ----------------------------
__global__ void ln_kernel(const float* __restrict__ x, const float* __restrict__ s,
                          const float* __restrict__ bsh, __half* __restrict__ out) {
    int row = blockIdx.x;
    const float* xr = x + (size_t)row * DIM_;
    float v[4];
    float sum = 0.f, sq = 0.f;
#pragma unroll
    for (int i = 0; i < 4; i++) {
        v[i] = xr[threadIdx.x + i * 128];
        sum += v[i];
        sq  += v[i] * v[i];
    }
    __shared__ float red0[4], red1[4];
    sum = warpsum(sum); sq = warpsum(sq);
    int warp = threadIdx.x >> 5, lane = threadIdx.x & 31;
    if (lane == 0) { red0[warp] = sum; red1[warp] = sq; }
    __syncthreads();
    sum = red0[0] + red0[1] + red0[2] + red0[3];
    sq  = red1[0] + red1[1] + red1[2] + red1[3];
    float mean = sum * (1.0f / DIM_);
    float var  = sq * (1.0f / DIM_) - mean * mean;
    float inv  = rsqrtf(var + 1e-6f);
    __half* orow = out + (size_t)row * DIM_;
#pragma unroll
    for (int i = 0; i < 4; i++) {
        int d = threadIdx.x + i * 128;
        orow[d] = __float2half_rn((v[i] - mean) * inv * s[d] + bsh[d]);
    }
}

// ======================= 128x128 fp16 GEMM (QKV / FFN1) ======================
struct GSmem128 {
    uint2 Ap[2][2][4][132];  // [buf][ks16][tg][row 0..127]
    uint2 Bp[2][2][4][132];  // [buf][ks16][tg][col 0..127]
};

// EPI: 2 = gelu+bias (half out), 3 = +bias (half out)
template <int EPI>
__device__ __forceinline__ void gemm_core128(
    const __half* __restrict__ A, const __half* __restrict__ Bw,
    const float* __restrict__ bias, __half* __restrict__ Ch, int Nd, int Kd) {
    __shared__ GSmem128 sm;
    const int m0 = blockIdx.y * 128, n0 = blockIdx.x * 128;
    const int tid = threadIdx.x;
    const int lane = tid & 31, wid = tid >> 5;
    const int g = lane >> 2, tg = lane & 3;
    const int wm = wid >> 2, wn = wid & 3;       // warp grid 2x4

    const int arow = tid >> 1, akh = tid & 1;
    const __half* aPtr = A + (size_t)(m0 + arow) * Kd + akh * 16;
    const int btg = (tid >> 6) & 3, bcp = tid & 63;
    const __half* bPtr0 = Bw + (size_t)(2 * btg) * Nd + n0 + 2 * bcp;
    const __half* bPtr1 = bPtr0 + (size_t)16 * Nd;

    float4 acc[4][4];
#pragma unroll
    for (int i = 0; i < 4; i++)
#pragma unroll
        for (int j = 0; j < 4; j++) acc[i][j] = make_float4(0.f, 0.f, 0.f, 0.f);

    uint4 alo, ahi;
    uint32_t wv[2][4];
    alo = *(const uint4*)(aPtr);
    ahi = *(const uint4*)(aPtr + 8);
#pragma unroll
    for (int s = 0; s < 2; s++) {
        const __half* bp = s ? bPtr1 : bPtr0;
        wv[s][0] = *(const uint32_t*)(bp);
        wv[s][1] = *(const uint32_t*)(bp + Nd);
        wv[s][2] = *(const uint32_t*)(bp + 8 * Nd);
        wv[s][3] = *(const uint32_t*)(bp + 9 * Nd);
    }

    auto store_tile = [&](int buf) {
        sm.Ap[buf][akh][0][arow] = make_uint2(alo.x, ahi.x);
        sm.Ap[buf][akh][1][arow] = make_uint2(alo.y, ahi.y);
        sm.Ap[buf][akh][2][arow] = make_uint2(alo.z, ahi.z);
        sm.Ap[buf][akh][3][arow] = make_uint2(alo.w, ahi.w);
#pragma unroll
        for (int s = 0; s < 2; s++) {
            uint32_t lo0 = __byte_perm(wv[s][0], wv[s][1], 0x5410);
            uint32_t lo1 = __byte_perm(wv[s][0], wv[s][1], 0x7632);
            uint32_t hi0 = __byte_perm(wv[s][2], wv[s][3], 0x5410);
            uint32_t hi1 = __byte_perm(wv[s][2], wv[s][3], 0x7632);
            *(uint4*)&sm.Bp[buf][s][btg][2 * bcp] = make_uint4(lo0, hi0, lo1, hi1);
        }
    };

    store_tile(0);
    __syncthreads();

    const int nT = Kd >> 5;
    for (int t = 0; t < nT; t++) {
        const int buf = t & 1;
        const bool more = (t + 1 < nT);
        if (more) {
            const __half* ap = aPtr + (t + 1) * 32;
            alo = *(const uint4*)(ap);
            ahi = *(const uint4*)(ap + 8);
            const size_t koff = (size_t)(t + 1) * 32 * Nd;
#pragma unroll
            for (int s = 0; s < 2; s++) {
                const __half* bp = (s ? bPtr1 : bPtr0) + koff;
                wv[s][0] = *(const uint32_t*)(bp);
                wv[s][1] = *(const uint32_t*)(bp + Nd);
                wv[s][2] = *(const uint32_t*)(bp + 8 * Nd);
                wv[s][3] = *(const uint32_t*)(bp + 9 * Nd);
            }
        }
#pragma unroll
        for (int ks = 0; ks < 2; ks++) {
            uint2 fal[4], fah[4], fb[4];
#pragma unroll
            for (int mi = 0; mi < 4; mi++) {
                fal[mi] = sm.Ap[buf][ks][tg][wm * 64 + mi * 16 + g];
                fah[mi] = sm.Ap[buf][ks][tg][wm * 64 + mi * 16 + g + 8];
            }
#pragma unroll
            for (int nj = 0; nj < 4; nj++)
                fb[nj] = sm.Bp[buf][ks][tg][wn * 32 + nj * 8 + g];
#pragma unroll
            for (int mi = 0; mi < 4; mi++)
#pragma unroll
                for (int nj = 0; nj < 4; nj++)
                    mma_f16(acc[mi][nj],
                            fal[mi].x, fah[mi].x, fal[mi].y, fah[mi].y,
                            fb[nj].x, fb[nj].y);
        }
        if (more) store_tile(buf ^ 1);
        __syncthreads();
    }

#pragma unroll
    for (int mi = 0; mi < 4; mi++) {
        int r0 = m0 + wm * 64 + mi * 16 + g;
#pragma unroll
        for (int nj = 0; nj < 4; nj++) {
            int col = n0 + wn * 32 + nj * 8 + tg * 2;
            float2 bbv = *(const float2*)(bias + col);
            float4 a = acc[mi][nj];
            float2 o0 = make_float2(a.x + bbv.x, a.y + bbv.y);
            float2 o1 = make_float2(a.z + bbv.x, a.w + bbv.y);
            if (EPI == 2) {
                float t0 = o0.x, t1 = o0.y, t2 = o1.x, t3 = o1.y;
                o0.x = t0 / (1.f + __expf(-1.5957691216057308f * (t0 + 0.044715f * t0 * t0 * t0)));
                o0.y = t1 / (1.f + __expf(-1.5957691216057308f * (t1 + 0.044715f * t1 * t1 * t1)));
                o1.x = t2 / (1.f + __expf(-1.5957691216057308f * (t2 + 0.044715f * t2 * t2 * t2)));
                o1.y = t3 / (1.f + __expf(-1.5957691216057308f * (t3 + 0.044715f * t3 * t3 * t3)));
            }
            *(uint32_t*)(Ch + (size_t)r0 * Nd + col)       = packh2(o0.x, o0.y);
            *(uint32_t*)(Ch + (size_t)(r0 + 8) * Nd + col) = packh2(o1.x, o1.y);
        }
    }
}

__global__ __launch_bounds__(256, 2) void k_gemm_qkv(
    const __half* __restrict__ xn, const __half* __restrict__ wh,
    const float* __restrict__ bq, const float* __restrict__ bk,
    const float* __restrict__ bv,
    __half* __restrict__ q, __half* __restrict__ k, __half* __restrict__ v) {
    int z = blockIdx.z;
    const __half* W  = wh + ((z == 0) ? WH_Q : (z == 1) ? WH_K : WH_V);
    const float* bb  = (z == 0) ? bq : (z == 1) ? bk : bv;
    __half* o        = (z == 0) ? q  : (z == 1) ? k  : v;
    gemm_core128<3>(xn, W, bb, o, DIM_, DIM_);
}

__global__ __launch_bounds__(256, 2) void k_gemm128_gelu(
    const __half* __restrict__ A, const __half* __restrict__ W,
    const float* __restrict__ bias, __half* __restrict__ C, int Nd, int Kd) {
    gemm_core128<2>(A, W, bias, C, Nd, Kd);
}

// ======================= 128x64 fp16 GEMM (Wo / FFN2, +residual, f32 out) ====
struct GSmem64 {
    uint2 Ap[2][2][4][132];
    uint2 Bp[2][2][4][68];
};

__global__ __launch_bounds__(256, 3) void k_gemm64_res(
    const __half* __restrict__ A, const __half* __restrict__ Bw,
    const float* __restrict__ bias, const float* __restrict__ res,
    float* __restrict__ C, int Nd, int Kd) {
    __shared__ GSmem64 sm;
    const int m0 = blockIdx.y * 128, n0 = blockIdx.x * 64;
    const int tid = threadIdx.x;
    const int lane = tid & 31, wid = tid >> 5;
    const int g = lane >> 2, tg = lane & 3;
    const int wm = wid >> 1, wn = wid & 1;

    const int arow = tid >> 1, akh = tid & 1;
    const __half* aPtr = A + (size_t)(m0 + arow) * Kd + akh * 16;
    const int bks = tid >> 7, btg = (tid >> 5) & 3, bcp = tid & 31;
    const __half* bPtr = Bw + (size_t)(bks * 16 + 2 * btg) * Nd + n0 + 2 * bcp;

    float4 acc[2][4];
#pragma unroll
    for (int i = 0; i < 2; i++)
#pragma unroll
        for (int j = 0; j < 4; j++) acc[i][j] = make_float4(0.f, 0.f, 0.f, 0.f);

    uint4 alo, ahi;
    uint32_t w0, w1, w2, w3;
    alo = *(const uint4*)(aPtr);
    ahi = *(const uint4*)(aPtr + 8);
    w0 = *(const uint32_t*)(bPtr);
    w1 = *(const uint32_t*)(bPtr + Nd);
    w2 = *(const uint32_t*)(bPtr + 8 * Nd);
    w3 = *(const uint32_t*)(bPtr + 9 * Nd);

    auto store_tile = [&](int buf) {
        sm.Ap[buf][akh][0][arow] = make_uint2(alo.x, ahi.x);
        sm.Ap[buf][akh][1][arow] = make_uint2(alo.y, ahi.y);
        sm.Ap[buf][akh][2][arow] = make_uint2(alo.z, ahi.z);
        sm.Ap[buf][akh][3][arow] = make_uint2(alo.w, ahi.w);
        uint32_t lo0 = __byte_perm(w0, w1, 0x5410);
        uint32_t lo1 = __byte_perm(w0, w1, 0x7632);
        uint32_t hi0 = __byte_perm(w2, w3, 0x5410);
        uint32_t hi1 = __byte_perm(w2, w3, 0x7632);
        *(uint4*)&sm.Bp[buf][bks][btg][2 * bcp] = make_uint4(lo0, hi0, lo1, hi1);
    };

    store_tile(0);
    __syncthreads();

    const int nT = Kd >> 5;
    for (int t = 0; t < nT; t++) {
        const int buf = t & 1;
        const bool more = (t + 1 < nT);
        if (more) {
            const __half* ap = aPtr + (t + 1) * 32;
            alo = *(const uint4*)(ap);
            ahi = *(const uint4*)(ap + 8);
            const __half* bp = bPtr + (size_t)(t + 1) * 32 * Nd;
            w0 = *(const uint32_t*)(bp);
            w1 = *(const uint32_t*)(bp + Nd);
            w2 = *(const uint32_t*)(bp + 8 * Nd);
            w3 = *(const uint32_t*)(bp + 9 * Nd);
        }
#pragma unroll
        for (int ks = 0; ks < 2; ks++) {
            uint2 fal[2], fah[2], fb[4];
#pragma unroll
            for (int mi = 0; mi < 2; mi++) {
                fal[mi] = sm.Ap[buf][ks][tg][wm * 32 + mi * 16 + g];
                fah[mi] = sm.Ap[buf][ks][tg][wm * 32 + mi * 16 + g + 8];
            }
#pragma unroll
            for (int nj = 0; nj < 4; nj++)
                fb[nj] = sm.Bp[buf][ks][tg][wn * 32 + nj * 8 + g];
#pragma unroll
            for (int mi = 0; mi < 2; mi++)
#pragma unroll
                for (int nj = 0; nj < 4; nj++)
                    mma_f16(acc[mi][nj],
                            fal[mi].x, fah[mi].x, fal[mi].y, fah[mi].y,
                            fb[nj].x, fb[nj].y);
        }
        if (more) store_tile(buf ^ 1);
        __syncthreads();
    }

#pragma unroll
    for (int mi = 0; mi < 2; mi++) {
        int r0 = m0 + wm * 32 + mi * 16 + g;
#pragma unroll
        for (int nj = 0; nj < 4; nj++) {
            int col = n0 + wn * 32 + nj * 8 + tg * 2;
            float2 bbv = *(const float2*)(bias + col);
            float4 a = acc[mi][nj];
            float2 r0v = *(const float2*)(res + (size_t)r0 * Nd + col);
            float2 r1v = *(const float2*)(res + (size_t)(r0 + 8) * Nd + col);
            float2 o0 = make_float2(a.x + bbv.x + r0v.x, a.y + bbv.y + r0v.y);
            float2 o1 = make_float2(a.z + bbv.x + r1v.x, a.w + bbv.y + r1v.y);
            *(float2*)(C + (size_t)r0 * Nd + col)       = o0;
            *(float2*)(C + (size_t)(r0 + 8) * Nd + col) = o1;
        }
    }
}

// ------------------------ prep (half in, half out) ---------------------------
__global__ void prep_kernel(const __half* __restrict__ qb, const __half* __restrict__ kb,
                            const __half* __restrict__ vb, const float* __restrict__ cos_t,
                            const float* __restrict__ sin_t, const float* __restrict__ c_arr,
                            const float* __restrict__ hash_off,
                            __half* __restrict__ qh, __half* __restrict__ kh,
                            __half* __restrict__ vt) {
    int bn = blockIdx.x;
    int b = bn / N_, n = bn % N_;
    int h = threadIdx.x >> 5, lane = threadIdx.x & 31;
    const float LOG9 = 2.1972245773362196f;
    float cs = cos_t[n * 32 + lane];
    float sn = sin_t[n * 32 + lane];
    float cb = c_arr[b];
    float sqrt_c = fmaxf(sqrtf(cb), EPSV);
    size_t in_off  = (size_t)bn * DIM_ + h * HD_;
    size_t out_off = (((size_t)(b * NH_ + h)) * N_ + n) * HD_;

    {
        float v0 = __half2float(qb[in_off + lane])      + hash_off[h * HD_ + lane]      * LOG9;
        float v1 = __half2float(qb[in_off + lane + 32]) + hash_off[h * HD_ + lane + 32] * LOG9;
        float r0 = v0 * cs - v1 * sn;
        float r1 = v0 * sn + v1 * cs;
        float nrm = sqrtf(warpsum(r0 * r0 + r1 * r1));
        float o0 = 0.f, o1 = 0.f;
        if (nrm >= EPSV) {
            float safe = fmaxf(nrm, EPSV);
            float mag  = __fdividef(tanh_pos(sqrt_c * safe), sqrt_c);
            float sc   = __fdividef(mag, safe);
            o0 = sc * r0; o1 = sc * r1;
        }
        qh[out_off + lane] = __float2half_rn(o0);
        qh[out_off + lane + 32] = __float2half_rn(o1);
    }
    {
        float v0 = __half2float(kb[in_off + lane]);
        float v1 = __half2float(kb[in_off + lane + 32]);
        float r0 = v0 * cs - v1 * sn;
        float r1 = v0 * sn + v1 * cs;
        float nrm = sqrtf(warpsum(r0 * r0 + r1 * r1));
        float o0 = 0.f, o1 = 0.f;
        if (nrm >= EPSV) {
            float safe = fmaxf(nrm, EPSV);
            float mag  = __fdividef(tanh_pos(sqrt_c * safe), sqrt_c);
            float sc   = __fdividef(mag, safe);
            o0 = sc * r0; o1 = sc * r1;
        }
        kh[out_off + lane] = __float2half_rn(o0);
        kh[out_off + lane + 32] = __float2half_rn(o1);
    }
    vt[out_off + lane]      = vb[in_off + lane];
    vt[out_off + lane + 32] = vb[in_off + lane + 32];
}

// ------------------------ windowed Poincaré attention (QT=32, half K/V) ------
#define QT3    32
#define KR3    (QT3 + WIN_ - 1)   // 95
#define KU_STR 33                 // uint (half2) stride
#define QS_STR 68
#define SW_STR 65
#define NT3    ((N_ / QT3) * B_ * NH_)   // 512 tiles = grid (1 tile/CTA)
#define RMIN_  5.0000003e-8f             // (1e-7)/(2-1e-7)

__global__ __launch_bounds__(256, 3) void attn3_kernel(
    const __half* __restrict__ qh, const __half* __restrict__ kh,
    const __half* __restrict__ vt, const float* __restrict__ c_arr,
    const float* __restrict__ geo, __half* __restrict__ attn_out) {
    __shared__ uint32_t Ku[KR3 * KU_STR + 4];   // K tile (half2); reused for V
    __shared__ __align__(16) float Qs[QT3 * QS_STR];
    __shared__ float Sw[QT3 * SW_STR];
    __shared__ float y2s[KR3 + 1];

    const int tid = threadIdx.x;
    const int w = tid >> 5, l = tid & 31;
    const int qi = tid >> 3;          // 0..31 (query)
    const int kg = tid & 7;           // 0..7  (key group)

    const int t = blockIdx.x;
    const int bh = t >> 5;
    const int b = bh >> 3, h = bh & 7;
    const int n0 = (t & 31) << 5;
    const __half* Kb = kh + (size_t)bh * (N_ * HD_);
    const __half* Vb = vt + (size_t)bh * (N_ * HD_);
    const __half* Qb = qh + (size_t)bh * (N_ * HD_);

    // ---- K tile -> smem (uint4 gmem loads, scalar STS at stride 33)
#pragma unroll
    for (int i = 0; i < 3; i++) {
        int f = tid + i * 256;
        if (f < KR3 * 8) {
            int row = f >> 3, u4 = (f & 7) * 4;
            int gn = n0 - (WIN_ - 1) + row;
            uint4 val = make_uint4(0u, 0u, 0u, 0u);
            if (gn >= 0) val = *(const uint4*)(Kb + (size_t)gn * HD_ + u4 * 2);
            uint32_t* d = &Ku[row * KU_STR + u4];
            d[0] = val.x; d[1] = val.y; d[2] = val.z; d[3] = val.w;
        }
    }
    // ---- Q tile -> smem f32 (thread: row = tid>>3, 8 halves at g8*8)
    {
        int row = tid >> 3, g8 = (tid & 7) * 8;
        uint4 qv = *(const uint4*)(Qb + (size_t)(n0 + row) * HD_ + g8);
        float2 a0 = unpackh2(qv.x), a1 = unpackh2(qv.y);
        float2 a2 = unpackh2(qv.z), a3 = unpackh2(qv.w);
        float* d = &Qs[row * QS_STR + g8];
        *(float4*)(d)     = make_float4(a0.x, a0.y, a1.x, a1.y);
        *(float4*)(d + 4) = make_float4(a2.x, a2.y, a3.x, a3.y);
    }
    // ---- prefetch V into registers
    uint4 vreg[3];
#pragma unroll
    for (int i = 0; i < 3; i++) {
        int f = tid + i * 256;
        vreg[i] = make_uint4(0u, 0u, 0u, 0u);
        if (f < KR3 * 8) {
            int row = f >> 3, u4 = (f & 7) * 4;
            int gn = n0 - (WIN_ - 1) + row;
            if (gn >= 0) vreg[i] = *(const uint4*)(Vb + (size_t)gn * HD_ + u4 * 2);
        }
    }
    __syncthreads();

    // ---- y2 per key row
    for (int row = w; row < KR3; row += 8) {
        float2 f = unpackh2(Ku[row * KU_STR + l]);
        float s = warpsum(f.x * f.x + f.y * f.y);
        if (l == 0) y2s[row] = s;
    }
    __syncthreads();

    const float cb = c_arr[b];
    const float sc = fmaxf(sqrtf(cb), EPSV);
    const float gs = geo[h];
    const float p2 = gs / sc;
    const float cc = cb * cb;

    // ---- dots: thread = (query qi, keys kg+8j, j=0..7)
    float xy[8], q2 = 0.f;
#pragma unroll
    for (int j = 0; j < 8; j++) xy[j] = 0.f;
    {
        const float* qrow = &Qs[qi * QS_STR];
        const uint32_t* kr = &Ku[(qi + kg) * KU_STR];
#pragma unroll 4
        for (int d2 = 0; d2 < 32; d2++) {
            float2 qv = *(const float2*)(qrow + 2 * d2);
            q2 = fmaf(qv.x, qv.x, fmaf(qv.y, qv.y, q2));
#pragma unroll
            for (int j = 0; j < 8; j++) {
                float2 f = unpackh2(kr[d2 + j * 8 * KU_STR]);
                xy[j] = fmaf(qv.x, f.x, fmaf(qv.y, f.y, xy[j]));
            }
        }
    }
    {
        const float Bc = 1.f - cb * q2;
        const float c2x2 = cc * q2;
#pragma unroll
        for (int j = 0; j < 8; j++) {
            float xyv = xy[j];
            float y2 = y2s[qi + kg + 8 * j];
            float u  = fmaf(-2.f * cb, xyv, 1.f);
            float A  = fmaf(cb, y2, u);
            float dn2 = fmaf(A * A, q2, fmaf(Bc * Bc, y2, -2.f * A * Bc * xyv));
            float den = fmaxf(fmaf(c2x2, y2, u), EPSV);
            float s   = sc * sqrt_fast(fmaxf(dn2, 0.f));
            float ratio = __fdividef(den - s, den + s);
            ratio = fmaxf(ratio, RMIN_);
            Sw[qi * SW_STR + kg + 8 * j] = p2 * __log2f(ratio);
        }
    }
    __syncthreads();

    // ---- softmax (base-2): warp w handles queries w, w+8, w+16, w+24
#pragma unroll
    for (int qq = 0; qq < 4; qq++) {
        int q = w + qq * 8;
        float s0 = Sw[q * SW_STR + l];
        float s1 = Sw[q * SW_STR + 32 + l];
        float m = warpmax(fmaxf(s0, s1));
        float e0 = exp2f(s0 - m), e1 = exp2f(s1 - m);
        float inv = __fdividef(1.f, warpsum(e0 + e1));
        Sw[q * SW_STR + l] = e0 * inv;
        Sw[q * SW_STR + 32 + l] = e1 * inv;
    }
    __syncthreads();

    // ---- V regs -> smem (same stride-33 layout)
#pragma unroll
    for (int i = 0; i < 3; i++) {
        int f = tid + i * 256;
        if (f < KR3 * 8) {
            int row = f >> 3, u4 = (f & 7) * 4;
            uint32_t* d = &Ku[row * KU_STR + u4];
            d[0] = vreg[i].x; d[1] = vreg[i].y; d[2] = vreg[i].z; d[3] = vreg[i].w;
        }
    }
    __syncthreads();

    // ---- AV: thread = (query qi, dims dg*8..+7)
    {
        const int dg = tid & 7;
        float acc[8];
#pragma unroll
        for (int j = 0; j < 8; j++) acc[j] = 0.f;
        const float* wrow = &Sw[qi * SW_STR];
        const uint32_t* vbase = &Ku[qi * KU_STR + dg * 4];
#pragma unroll 4
        for (int k = 0; k < WIN_; k++) {
            float wk = wrow[k];
            const uint32_t* vp = vbase + k * KU_STR;
#pragma unroll
            for (int u = 0; u < 4; u++) {
                float2 f = unpackh2(vp[u]);
                acc[2 * u]     = fmaf(wk, f.x, acc[2 * u]);
                acc[2 * u + 1] = fmaf(wk, f.y, acc[2 * u + 1]);
            }
        }
        __half* orow = attn_out + ((size_t)(b * N_ + n0 + qi)) * DIM_ + h * HD_ + dg * 8;
        *(uint4*)orow = make_uint4(packh2(acc[0], acc[1]), packh2(acc[2], acc[3]),
                                   packh2(acc[4], acc[5]), packh2(acc[6], acc[7]));
    }
}

// ------------------------ launch --------------------------------------------
extern "C" void kernel_launch(void* const* d_in, const int* in_sizes, int n_in,
                              void* d_out, int out_size) {
    (void)in_sizes; (void)n_in; (void)out_size;
    const float* x     = (const float*)d_in[0];
    const float* fcos  = (const float*)d_in[1];
    const float* fsin  = (const float*)d_in[2];
    const float* c     = (const float*)d_in[3];
    const float* Wq    = (const float*)d_in[4];
    const float* bq    = (const float*)d_in[5];
    const float* Wk    = (const float*)d_in[6];
    const float* bk    = (const float*)d_in[7];
    const float* Wv    = (const float*)d_in[8];
    const float* bv    = (const float*)d_in[9];
    const float* Wo    = (const float*)d_in[10];
    const float* bo    = (const float*)d_in[11];
    const float* W1    = (const float*)d_in[12];
    const float* b1    = (const float*)d_in[13];
    const float* W2    = (const float*)d_in[14];
    const float* b2    = (const float*)d_in[15];
    const float* ln1s  = (const float*)d_in[16];
    const float* ln1b  = (const float*)d_in[17];
    const float* ln2s  = (const float*)d_in[18];
    const float* ln2b  = (const float*)d_in[19];
    const float* geo   = (const float*)d_in[20];
    const float* hasho = (const float*)d_in[21];
    float* out = (float*)d_out;

    __half *xnh, *attnh, *hhh, *midh, *wh, *q, *k, *v, *qh, *kh, *vt;
    float *xout;
    cudaGetSymbolAddress((void**)&xnh,   g_xnh);
    cudaGetSymbolAddress((void**)&q,     g_q);
    cudaGetSymbolAddress((void**)&k,     g_k);
    cudaGetSymbolAddress((void**)&v,     g_v);
    cudaGetSymbolAddress((void**)&qh,    g_qh);
    cudaGetSymbolAddress((void**)&kh,    g_kh);
    cudaGetSymbolAddress((void**)&vt,    g_vt);
    cudaGetSymbolAddress((void**)&attnh, g_attnh);
    cudaGetSymbolAddress((void**)&xout,  g_xout);
    cudaGetSymbolAddress((void**)&hhh,   g_hhh);
    cudaGetSymbolAddress((void**)&midh,  g_midh);
    cudaGetSymbolAddress((void**)&wh,    g_wh);

    // 0+1) fused: LN1 (blocks 0..2047) + weight cvt (blocks 2048..8191)
    ln1_cvtw_kernel<<<8192, 128>>>(x, ln1s, ln1b, xnh,
                                   Wq, Wk, Wv, Wo, W1, W2, wh);

    // 2) fused QKV projections (half out)
    dim3 gqkv(DIM_ / 128, M_ / 128, 3);
    k_gemm_qkv<<<gqkv, 256>>>(xnh, wh, bq, bk, bv, q, k, v);

    // 3) hash + rope + expmap0 + transpose (half in/out)
    prep_kernel<<<M_, 256>>>(q, k, v, fcos, fsin, c, hasho, qh, kh, vt);

    // 4) sliding-window Poincaré attention (QT=32, 512 CTAs, 1 tile each)
    attn3_kernel<<<NT3, 256>>>(qh, kh, vt, c, geo, attnh);

    // 5) Wo projection + residual(x) -> xout (f32)
    dim3 gwo(DIM_ / 64, M_ / 128);
    k_gemm64_res<<<gwo, 256>>>(attnh, wh + WH_O, bo, x, xout, DIM_, DIM_);

    // 6) LN2 (half out)
    ln_kernel<<<M_, 128>>>(xout, ln2s, ln2b, hhh);

    // 7) FFN1 + gelu (half out)
    dim3 gffn1(DFF_ / 128, M_ / 128);
    k_gemm128_gelu<<<gffn1, 256>>>(hhh, wh + WH_1, b1, midh, DFF_, DIM_);

    // 8) FFN2 + residual(xout) -> out (f32)
    k_gemm64_res<<<gwo, 256>>>(midh, wh + WH_2, b2, xout, out, DIM_, DFF_);
}

// round 15
// speedup vs baseline: 2.9093x; 1.0175x over previous
#include <cuda_runtime.h>
#include <cuda_bf16.h>
#include <cuda_fp16.h>
#include <math.h>
#include <cstdint>

#define B_    2
#define N_    1024
#define DIM_  512
#define NH_   8
#define HD_   64
#define WIN_  64
#define M_    (B_ * N_)      // 2048
#define DFF_  (4 * DIM_)     // 2048
#define EPSV  1e-7f

// ------------------------ scratch (device globals; no allocation) ------------
__device__ __half g_xnh [M_ * DIM_];    // LN1 out (half)
__device__ __half g_q   [M_ * DIM_];    // QKV outs (half)
__device__ __half g_k   [M_ * DIM_];
__device__ __half g_v   [M_ * DIM_];
__device__ __half g_qh  [B_ * NH_ * N_ * HD_];   // prep outs (half)
__device__ __half g_kh  [B_ * NH_ * N_ * HD_];
__device__ __half g_vt  [B_ * NH_ * N_ * HD_];
__device__ __half g_attnh[M_ * DIM_];   // attention out (half)
__device__ float  g_xout[M_ * DIM_];
__device__ __half g_hhh [M_ * DIM_];    // LN2 out (half)
__device__ __half g_midh[M_ * DFF_];    // FFN mid (half)
// half weights, concatenated
#define WH_Q 0
#define WH_K 262144
#define WH_V 524288
#define WH_O 786432
#define WH_1 1048576
#define WH_2 2097152
__device__ __half g_wh[3145728];

// ------------------------ helpers -------------------------------------------
__device__ __forceinline__ float warpsum(float v) {
#pragma unroll
    for (int o = 16; o > 0; o >>= 1) v += __shfl_xor_sync(0xffffffffu, v, o);
    return v;
}
__device__ __forceinline__ float warpmax(float v) {
#pragma unroll
    for (int o = 16; o > 0; o >>= 1) v = fmaxf(v, __shfl_xor_sync(0xffffffffu, v, o));
    return v;
}
__device__ __forceinline__ float sqrt_fast(float x) {
    float r;
    asm("sqrt.approx.f32 %0, %1;" : "=f"(r) : "f"(x));
    return r;
}
__device__ __forceinline__ uint32_t packh2(float lo, float hi) {
    __half2 h = __floats2half2_rn(lo, hi);
    return *(uint32_t*)&h;
}
__device__ __forceinline__ float2 unpackh2(uint32_t u) {
    return __half22float2(*(__half2*)&u);
}
__device__ __forceinline__ __half2 ash2(uint32_t u) { return *(__half2*)&u; }
// fast tanh for x >= 0:  tanh(x) = 1 - 2/(1+e^{2x})
__device__ __forceinline__ float tanh_pos(float x) {
    return 1.f - __fdividef(2.f, 1.f + __expf(2.f * x));
}
// fp16 tensor-core mma: D(f32) += A(f16,16x16) * B(f16,16x8)
__device__ __forceinline__ void mma_f16(float4& c, uint32_t a0, uint32_t a1,
                                        uint32_t a2, uint32_t a3,
                                        uint32_t b0, uint32_t b1) {
    asm volatile(
        "mma.sync.aligned.m16n8k16.row.col.f32.f16.f16.f32 "
        "{%0,%1,%2,%3},{%4,%5,%6,%7},{%8,%9},{%0,%1,%2,%3};\n"
        : "+f"(c.x), "+f"(c.y), "+f"(c.z), "+f"(c.w)
        : "r"(a0), "r"(a1), "r"(a2), "r"(a3), "r"(b0), "r"(b1));
}

// ------------------------ fused LN1 + weight convert -------------------------
__global__ __launch_bounds__(128) void ln1_cvtw_kernel(
    const float* __restrict__ x, const float* __restrict__ s,
    const float* __restrict__ bsh, __half* __restrict__ out,
    const float* __restrict__ Wq, const float* __restrict__ Wk,
    const float* __restrict__ Wv, const float* __restrict__ Wo,
    const float* __restrict__ W1, const float* __restrict__ W2,
    __half* __restrict__ wh) {
    if (blockIdx.x < 2048) {
        int row = blockIdx.x;
        const float* xr = x + (size_t)row * DIM_;
        float v[4];
        float sum = 0.f, sq = 0.f;
#pragma unroll
        for (int i = 0; i < 4; i++) {
            v[i] = xr[threadIdx.x + i * 128];
            sum += v[i];
            sq  += v[i] * v[i];
        }
        __shared__ float red0[4], red1[4];
        sum = warpsum(sum); sq = warpsum(sq);
        int warp = threadIdx.x >> 5, lane = threadIdx.x & 31;
        if (lane == 0) { red0[warp] = sum; red1[warp] = sq; }
        __syncthreads();
        sum = red0[0] + red0[1] + red0[2] + red0[3];
        sq  = red1[0] + red1[1] + red1[2] + red1[3];
        float mean = sum * (1.0f / DIM_);
        float var  = sq * (1.0f / DIM_) - mean * mean;
        float inv  = rsqrtf(var + 1e-6f);
        __half* orow = out + (size_t)row * DIM_;
#pragma unroll
        for (int i = 0; i < 4; i++) {
            int d = threadIdx.x + i * 128;
            orow[d] = __float2half_rn((v[i] - mean) * inv * s[d] + bsh[d]);
        }
    } else {
        long i = ((long)(blockIdx.x - 2048) * 128 + threadIdx.x) * 4;
        if (i >= 3145728) return;
        const float* src;
        long off;
        if      (i <  262144) { src = Wq; off = i; }
        else if (i <  524288) { src = Wk; off = i - 262144; }
        else if (i <  786432) { src = Wv; off = i - 524288; }
        else if (i < 1048576) { src = Wo; off = i - 786432; }
        else if (i < 2097152) { src = W1; off = i - 1048576; }
        else                  { src = W2; off = i - 2097152; }
        float4 v = *(const float4*)(src + off);
        *(uint2*)(wh + i) = make_uint2(packh2(v.x, v.y), packh2(v.z, v.w));
    }
}

// ------------------------ layernorm (half output) ----------------------------
__global__ void ln_kernel(const float* __restrict__ x, const float* __restrict__ s,
                          const float* __restrict__ bsh, __half* __restrict__ out) {
    int row = blockIdx.x;
    const float* xr = x + (size_t)row * DIM_;
    float v[4];
    float sum = 0.f, sq = 0.f;
#pragma unroll
    for (int i = 0; i < 4; i++) {
        v[i] = xr[threadIdx.x + i * 128];
        sum += v[i];
        sq  += v[i] * v[i];
    }
    __shared__ float red0[4], red1[4];
    sum = warpsum(sum); sq = warpsum(sq);
    int warp = threadIdx.x >> 5, lane = threadIdx.x & 31;
    if (lane == 0) { red0[warp] = sum; red1[warp] = sq; }
    __syncthreads();
    sum = red0[0] + red0[1] + red0[2] + red0[3];
    sq  = red1[0] + red1[1] + red1[2] + red1[3];
    float mean = sum * (1.0f / DIM_);
    float var  = sq * (1.0f / DIM_) - mean * mean;
    float inv  = rsqrtf(var + 1e-6f);
    __half* orow = out + (size_t)row * DIM_;
#pragma unroll
    for (int i = 0; i < 4; i++) {
        int d = threadIdx.x + i * 128;
        orow[d] = __float2half_rn((v[i] - mean) * inv * s[d] + bsh[d]);
    }
}

// ======================= 128x128 fp16 GEMM (QKV / FFN1) ======================
struct GSmem128 {
    uint2 Ap[2][2][4][132];  // [buf][ks16][tg][row 0..127]
    uint2 Bp[2][2][4][132];  // [buf][ks16][tg][col 0..127]
};

// EPI: 2 = gelu+bias (half out), 3 = +bias (half out)
template <int EPI>
__device__ __forceinline__ void gemm_core128(
    const __half* __restrict__ A, const __half* __restrict__ Bw,
    const float* __restrict__ bias, __half* __restrict__ Ch, int Nd, int Kd) {
    __shared__ GSmem128 sm;
    const int m0 = blockIdx.y * 128, n0 = blockIdx.x * 128;
    const int tid = threadIdx.x;
    const int lane = tid & 31, wid = tid >> 5;
    const int g = lane >> 2, tg = lane & 3;
    const int wm = wid >> 2, wn = wid & 3;       // warp grid 2x4

    const int arow = tid >> 1, akh = tid & 1;
    const __half* aPtr = A + (size_t)(m0 + arow) * Kd + akh * 16;
    const int btg = (tid >> 6) & 3, bcp = tid & 63;
    const __half* bPtr0 = Bw + (size_t)(2 * btg) * Nd + n0 + 2 * bcp;
    const __half* bPtr1 = bPtr0 + (size_t)16 * Nd;

    float4 acc[4][4];
#pragma unroll
    for (int i = 0; i < 4; i++)
#pragma unroll
        for (int j = 0; j < 4; j++) acc[i][j] = make_float4(0.f, 0.f, 0.f, 0.f);

    uint4 alo, ahi;
    uint32_t wv[2][4];
    alo = *(const uint4*)(aPtr);
    ahi = *(const uint4*)(aPtr + 8);
#pragma unroll
    for (int s = 0; s < 2; s++) {
        const __half* bp = s ? bPtr1 : bPtr0;
        wv[s][0] = *(const uint32_t*)(bp);
        wv[s][1] = *(const uint32_t*)(bp + Nd);
        wv[s][2] = *(const uint32_t*)(bp + 8 * Nd);
        wv[s][3] = *(const uint32_t*)(bp + 9 * Nd);
    }

    auto store_tile = [&](int buf) {
        sm.Ap[buf][akh][0][arow] = make_uint2(alo.x, ahi.x);
        sm.Ap[buf][akh][1][arow] = make_uint2(alo.y, ahi.y);
        sm.Ap[buf][akh][2][arow] = make_uint2(alo.z, ahi.z);
        sm.Ap[buf][akh][3][arow] = make_uint2(alo.w, ahi.w);
#pragma unroll
        for (int s = 0; s < 2; s++) {
            uint32_t lo0 = __byte_perm(wv[s][0], wv[s][1], 0x5410);
            uint32_t lo1 = __byte_perm(wv[s][0], wv[s][1], 0x7632);
            uint32_t hi0 = __byte_perm(wv[s][2], wv[s][3], 0x5410);
            uint32_t hi1 = __byte_perm(wv[s][2], wv[s][3], 0x7632);
            *(uint4*)&sm.Bp[buf][s][btg][2 * bcp] = make_uint4(lo0, hi0, lo1, hi1);
        }
    };

    store_tile(0);
    __syncthreads();

    const int nT = Kd >> 5;
    for (int t = 0; t < nT; t++) {
        const int buf = t & 1;
        const bool more = (t + 1 < nT);
        if (more) {
            const __half* ap = aPtr + (t + 1) * 32;
            alo = *(const uint4*)(ap);
            ahi = *(const uint4*)(ap + 8);
            const size_t koff = (size_t)(t + 1) * 32 * Nd;
#pragma unroll
            for (int s = 0; s < 2; s++) {
                const __half* bp = (s ? bPtr1 : bPtr0) + koff;
                wv[s][0] = *(const uint32_t*)(bp);
                wv[s][1] = *(const uint32_t*)(bp + Nd);
                wv[s][2] = *(const uint32_t*)(bp + 8 * Nd);
                wv[s][3] = *(const uint32_t*)(bp + 9 * Nd);
            }
        }
#pragma unroll
        for (int ks = 0; ks < 2; ks++) {
            uint2 fal[4], fah[4], fb[4];
#pragma unroll
            for (int mi = 0; mi < 4; mi++) {
                fal[mi] = sm.Ap[buf][ks][tg][wm * 64 + mi * 16 + g];
                fah[mi] = sm.Ap[buf][ks][tg][wm * 64 + mi * 16 + g + 8];
            }
#pragma unroll
            for (int nj = 0; nj < 4; nj++)
                fb[nj] = sm.Bp[buf][ks][tg][wn * 32 + nj * 8 + g];
#pragma unroll
            for (int mi = 0; mi < 4; mi++)
#pragma unroll
                for (int nj = 0; nj < 4; nj++)
                    mma_f16(acc[mi][nj],
                            fal[mi].x, fah[mi].x, fal[mi].y, fah[mi].y,
                            fb[nj].x, fb[nj].y);
        }
        if (more) store_tile(buf ^ 1);
        __syncthreads();
    }

#pragma unroll
    for (int mi = 0; mi < 4; mi++) {
        int r0 = m0 + wm * 64 + mi * 16 + g;
#pragma unroll
        for (int nj = 0; nj < 4; nj++) {
            int col = n0 + wn * 32 + nj * 8 + tg * 2;
            float2 bbv = *(const float2*)(bias + col);
            float4 a = acc[mi][nj];
            float2 o0 = make_float2(a.x + bbv.x, a.y + bbv.y);
            float2 o1 = make_float2(a.z + bbv.x, a.w + bbv.y);
            if (EPI == 2) {
                float t0 = o0.x, t1 = o0.y, t2 = o1.x, t3 = o1.y;
                o0.x = t0 / (1.f + __expf(-1.5957691216057308f * (t0 + 0.044715f * t0 * t0 * t0)));
                o0.y = t1 / (1.f + __expf(-1.5957691216057308f * (t1 + 0.044715f * t1 * t1 * t1)));
                o1.x = t2 / (1.f + __expf(-1.5957691216057308f * (t2 + 0.044715f * t2 * t2 * t2)));
                o1.y = t3 / (1.f + __expf(-1.5957691216057308f * (t3 + 0.044715f * t3 * t3 * t3)));
            }
            *(uint32_t*)(Ch + (size_t)r0 * Nd + col)       = packh2(o0.x, o0.y);
            *(uint32_t*)(Ch + (size_t)(r0 + 8) * Nd + col) = packh2(o1.x, o1.y);
        }
    }
}

__global__ __launch_bounds__(256, 2) void k_gemm_qkv(
    const __half* __restrict__ xn, const __half* __restrict__ wh,
    const float* __restrict__ bq, const float* __restrict__ bk,
    const float* __restrict__ bv,
    __half* __restrict__ q, __half* __restrict__ k, __half* __restrict__ v) {
    int z = blockIdx.z;
    const __half* W  = wh + ((z == 0) ? WH_Q : (z == 1) ? WH_K : WH_V);
    const float* bb  = (z == 0) ? bq : (z == 1) ? bk : bv;
    __half* o        = (z == 0) ? q  : (z == 1) ? k  : v;
    gemm_core128<3>(xn, W, bb, o, DIM_, DIM_);
}

__global__ __launch_bounds__(256, 2) void k_gemm128_gelu(
    const __half* __restrict__ A, const __half* __restrict__ W,
    const float* __restrict__ bias, __half* __restrict__ C, int Nd, int Kd) {
    gemm_core128<2>(A, W, bias, C, Nd, Kd);
}

// ======================= 128x64 fp16 GEMM (Wo / FFN2, +residual, f32 out) ====
struct GSmem64 {
    uint2 Ap[2][2][4][132];
    uint2 Bp[2][2][4][68];
};

__global__ __launch_bounds__(256, 3) void k_gemm64_res(
    const __half* __restrict__ A, const __half* __restrict__ Bw,
    const float* __restrict__ bias, const float* __restrict__ res,
    float* __restrict__ C, int Nd, int Kd) {
    __shared__ GSmem64 sm;
    const int m0 = blockIdx.y * 128, n0 = blockIdx.x * 64;
    const int tid = threadIdx.x;
    const int lane = tid & 31, wid = tid >> 5;
    const int g = lane >> 2, tg = lane & 3;
    const int wm = wid >> 1, wn = wid & 1;

    const int arow = tid >> 1, akh = tid & 1;
    const __half* aPtr = A + (size_t)(m0 + arow) * Kd + akh * 16;
    const int bks = tid >> 7, btg = (tid >> 5) & 3, bcp = tid & 31;
    const __half* bPtr = Bw + (size_t)(bks * 16 + 2 * btg) * Nd + n0 + 2 * bcp;

    float4 acc[2][4];
#pragma unroll
    for (int i = 0; i < 2; i++)
#pragma unroll
        for (int j = 0; j < 4; j++) acc[i][j] = make_float4(0.f, 0.f, 0.f, 0.f);

    uint4 alo, ahi;
    uint32_t w0, w1, w2, w3;
    alo = *(const uint4*)(aPtr);
    ahi = *(const uint4*)(aPtr + 8);
    w0 = *(const uint32_t*)(bPtr);
    w1 = *(const uint32_t*)(bPtr + Nd);
    w2 = *(const uint32_t*)(bPtr + 8 * Nd);
    w3 = *(const uint32_t*)(bPtr + 9 * Nd);

    auto store_tile = [&](int buf) {
        sm.Ap[buf][akh][0][arow] = make_uint2(alo.x, ahi.x);
        sm.Ap[buf][akh][1][arow] = make_uint2(alo.y, ahi.y);
        sm.Ap[buf][akh][2][arow] = make_uint2(alo.z, ahi.z);
        sm.Ap[buf][akh][3][arow] = make_uint2(alo.w, ahi.w);
        uint32_t lo0 = __byte_perm(w0, w1, 0x5410);
        uint32_t lo1 = __byte_perm(w0, w1, 0x7632);
        uint32_t hi0 = __byte_perm(w2, w3, 0x5410);
        uint32_t hi1 = __byte_perm(w2, w3, 0x7632);
        *(uint4*)&sm.Bp[buf][bks][btg][2 * bcp] = make_uint4(lo0, hi0, lo1, hi1);
    };

    store_tile(0);
    __syncthreads();

    const int nT = Kd >> 5;
    for (int t = 0; t < nT; t++) {
        const int buf = t & 1;
        const bool more = (t + 1 < nT);
        if (more) {
            const __half* ap = aPtr + (t + 1) * 32;
            alo = *(const uint4*)(ap);
            ahi = *(const uint4*)(ap + 8);
            const __half* bp = bPtr + (size_t)(t + 1) * 32 * Nd;
            w0 = *(const uint32_t*)(bp);
            w1 = *(const uint32_t*)(bp + Nd);
            w2 = *(const uint32_t*)(bp + 8 * Nd);
            w3 = *(const uint32_t*)(bp + 9 * Nd);
        }
#pragma unroll
        for (int ks = 0; ks < 2; ks++) {
            uint2 fal[2], fah[2], fb[4];
#pragma unroll
            for (int mi = 0; mi < 2; mi++) {
                fal[mi] = sm.Ap[buf][ks][tg][wm * 32 + mi * 16 + g];
                fah[mi] = sm.Ap[buf][ks][tg][wm * 32 + mi * 16 + g + 8];
            }
#pragma unroll
            for (int nj = 0; nj < 4; nj++)
                fb[nj] = sm.Bp[buf][ks][tg][wn * 32 + nj * 8 + g];
#pragma unroll
            for (int mi = 0; mi < 2; mi++)
#pragma unroll
                for (int nj = 0; nj < 4; nj++)
                    mma_f16(acc[mi][nj],
                            fal[mi].x, fah[mi].x, fal[mi].y, fah[mi].y,
                            fb[nj].x, fb[nj].y);
        }
        if (more) store_tile(buf ^ 1);
        __syncthreads();
    }

#pragma unroll
    for (int mi = 0; mi < 2; mi++) {
        int r0 = m0 + wm * 32 + mi * 16 + g;
#pragma unroll
        for (int nj = 0; nj < 4; nj++) {
            int col = n0 + wn * 32 + nj * 8 + tg * 2;
            float2 bbv = *(const float2*)(bias + col);
            float4 a = acc[mi][nj];
            float2 r0v = *(const float2*)(res + (size_t)r0 * Nd + col);
            float2 r1v = *(const float2*)(res + (size_t)(r0 + 8) * Nd + col);
            float2 o0 = make_float2(a.x + bbv.x + r0v.x, a.y + bbv.y + r0v.y);
            float2 o1 = make_float2(a.z + bbv.x + r1v.x, a.w + bbv.y + r1v.y);
            *(float2*)(C + (size_t)r0 * Nd + col)       = o0;
            *(float2*)(C + (size_t)(r0 + 8) * Nd + col) = o1;
        }
    }
}

// ------------------------ prep (half in, half out) ---------------------------
__global__ void prep_kernel(const __half* __restrict__ qb, const __half* __restrict__ kb,
                            const __half* __restrict__ vb, const float* __restrict__ cos_t,
                            const float* __restrict__ sin_t, const float* __restrict__ c_arr,
                            const float* __restrict__ hash_off,
                            __half* __restrict__ qh, __half* __restrict__ kh,
                            __half* __restrict__ vt) {
    int bn = blockIdx.x;
    int b = bn / N_, n = bn % N_;
    int h = threadIdx.x >> 5, lane = threadIdx.x & 31;
    const float LOG9 = 2.1972245773362196f;
    float cs = cos_t[n * 32 + lane];
    float sn = sin_t[n * 32 + lane];
    float cb = c_arr[b];
    float sqrt_c = fmaxf(sqrtf(cb), EPSV);
    size_t in_off  = (size_t)bn * DIM_ + h * HD_;
    size_t out_off = (((size_t)(b * NH_ + h)) * N_ + n) * HD_;

    {
        float v0 = __half2float(qb[in_off + lane])      + hash_off[h * HD_ + lane]      * LOG9;
        float v1 = __half2float(qb[in_off + lane + 32]) + hash_off[h * HD_ + lane + 32] * LOG9;
        float r0 = v0 * cs - v1 * sn;
        float r1 = v0 * sn + v1 * cs;
        float nrm = sqrtf(warpsum(r0 * r0 + r1 * r1));
        float o0 = 0.f, o1 = 0.f;
        if (nrm >= EPSV) {
            float safe = fmaxf(nrm, EPSV);
            float mag  = __fdividef(tanh_pos(sqrt_c * safe), sqrt_c);
            float sc   = __fdividef(mag, safe);
            o0 = sc * r0; o1 = sc * r1;
        }
        qh[out_off + lane] = __float2half_rn(o0);
        qh[out_off + lane + 32] = __float2half_rn(o1);
    }
    {
        float v0 = __half2float(kb[in_off + lane]);
        float v1 = __half2float(kb[in_off + lane + 32]);
        float r0 = v0 * cs - v1 * sn;
        float r1 = v0 * sn + v1 * cs;
        float nrm = sqrtf(warpsum(r0 * r0 + r1 * r1));
        float o0 = 0.f, o1 = 0.f;
        if (nrm >= EPSV) {
            float safe = fmaxf(nrm, EPSV);
            float mag  = __fdividef(tanh_pos(sqrt_c * safe), sqrt_c);
            float sc   = __fdividef(mag, safe);
            o0 = sc * r0; o1 = sc * r1;
        }
        kh[out_off + lane] = __float2half_rn(o0);
        kh[out_off + lane + 32] = __float2half_rn(o1);
    }
    vt[out_off + lane]      = vb[in_off + lane];
    vt[out_off + lane + 32] = vb[in_off + lane + 32];
}

// ---------------- windowed Poincaré attention (QT=32, hfma2 inner loops) -----
#define QT3    32
#define KR3    (QT3 + WIN_ - 1)   // 95
#define KU_STR 33                 // uint (half2) stride
#define QU_STR 33                 // Q half2 stride
#define SW_STR 65
#define NT3    ((N_ / QT3) * B_ * NH_)   // 512 tiles = grid
#define RMIN_  5.0000003e-8f             // (1e-7)/(2-1e-7)

__global__ __launch_bounds__(256, 3) void attn4_kernel(
    const __half* __restrict__ qh, const __half* __restrict__ kh,
    const __half* __restrict__ vt, const float* __restrict__ c_arr,
    const float* __restrict__ geo, __half* __restrict__ attn_out) {
    __shared__ uint32_t Ku[KR3 * KU_STR + 4];   // K tile (half2); reused for V
    __shared__ uint32_t Qu[QT3 * QU_STR];       // Q tile (half2)
    __shared__ float Sw[QT3 * SW_STR];
    __shared__ float y2s[KR3 + 1];

    const int tid = threadIdx.x;
    const int w = tid >> 5, l = tid & 31;
    const int qi = tid >> 3;          // 0..31 (query)
    const int kg = tid & 7;           // 0..7  (key group)

    const int t = blockIdx.x;
    const int bh = t >> 5;
    const int b = bh >> 3, h = bh & 7;
    const int n0 = (t & 31) << 5;
    const __half* Kb = kh + (size_t)bh * (N_ * HD_);
    const __half* Vb = vt + (size_t)bh * (N_ * HD_);
    const __half* Qb = qh + (size_t)bh * (N_ * HD_);

    // ---- K tile -> smem (uint4 gmem loads, scalar STS at stride 33)
#pragma unroll
    for (int i = 0; i < 3; i++) {
        int f = tid + i * 256;
        if (f < KR3 * 8) {
            int row = f >> 3, u4 = (f & 7) * 4;
            int gn = n0 - (WIN_ - 1) + row;
            uint4 val = make_uint4(0u, 0u, 0u, 0u);
            if (gn >= 0) val = *(const uint4*)(Kb + (size_t)gn * HD_ + u4 * 2);
            uint32_t* d = &Ku[row * KU_STR + u4];
            d[0] = val.x; d[1] = val.y; d[2] = val.z; d[3] = val.w;
        }
    }
    // ---- Q tile -> smem half2 (straight copy)
    {
        int row = tid >> 3, u4 = (tid & 7) * 4;
        uint4 qv = *(const uint4*)(Qb + (size_t)(n0 + row) * HD_ + u4 * 2);
        uint32_t* d = &Qu[row * QU_STR + u4];
        d[0] = qv.x; d[1] = qv.y; d[2] = qv.z; d[3] = qv.w;
    }
    // ---- prefetch V into registers
    uint4 vreg[3];
#pragma unroll
    for (int i = 0; i < 3; i++) {
        int f = tid + i * 256;
        vreg[i] = make_uint4(0u, 0u, 0u, 0u);
        if (f < KR3 * 8) {
            int row = f >> 3, u4 = (f & 7) * 4;
            int gn = n0 - (WIN_ - 1) + row;
            if (gn >= 0) vreg[i] = *(const uint4*)(Vb + (size_t)gn * HD_ + u4 * 2);
        }
    }
    __syncthreads();

    // ---- y2 per key row (f32)
    for (int row = w; row < KR3; row += 8) {
        float2 f = unpackh2(Ku[row * KU_STR + l]);
        float s = warpsum(f.x * f.x + f.y * f.y);
        if (l == 0) y2s[row] = s;
    }
    __syncthreads();

    const float cb = c_arr[b];
    const float sc = fmaxf(sqrtf(cb), EPSV);
    const float gs = geo[h];
    const float p2 = gs / sc;
    const float cc = cb * cb;

    // ---- dots: hfma2 inner, promote to f32 every 8 half2-steps (16 dims)
    float xy[8], q2 = 0.f;
#pragma unroll
    for (int j = 0; j < 8; j++) xy[j] = 0.f;
    {
        const uint32_t* qrow = &Qu[qi * QU_STR];
        const uint32_t* kr = &Ku[(qi + kg) * KU_STR];
#pragma unroll
        for (int ch = 0; ch < 4; ch++) {
            __half2 hq2 = __half2half2(__float2half(0.f));
            __half2 hxy[8];
#pragma unroll
            for (int j = 0; j < 8; j++) hxy[j] = hq2;
#pragma unroll
            for (int d2 = ch * 8; d2 < ch * 8 + 8; d2++) {
                __half2 qv = ash2(qrow[d2]);
                hq2 = __hfma2(qv, qv, hq2);
#pragma unroll
                for (int j = 0; j < 8; j++) {
                    __half2 kv = ash2(kr[d2 + j * 8 * KU_STR]);
                    hxy[j] = __hfma2(qv, kv, hxy[j]);
                }
            }
            float2 fq = __half22float2(hq2);
            q2 += fq.x + fq.y;
#pragma unroll
            for (int j = 0; j < 8; j++) {
                float2 f = __half22float2(hxy[j]);
                xy[j] += f.x + f.y;
            }
        }
    }
    {
        const float Bc = 1.f - cb * q2;
        const float c2x2 = cc * q2;
#pragma unroll
        for (int j = 0; j < 8; j++) {
            float xyv = xy[j];
            float y2 = y2s[qi + kg + 8 * j];
            float u  = fmaf(-2.f * cb, xyv, 1.f);
            float A  = fmaf(cb, y2, u);
            float dn2 = fmaf(A * A, q2, fmaf(Bc * Bc, y2, -2.f * A * Bc * xyv));
            float den = fmaxf(fmaf(c2x2, y2, u), EPSV);
            float s   = sc * sqrt_fast(fmaxf(dn2, 0.f));
            float ratio = __fdividef(den - s, den + s);
            ratio = fmaxf(ratio, RMIN_);
            Sw[qi * SW_STR + kg + 8 * j] = p2 * __log2f(ratio);
        }
    }
    __syncthreads();

    // ---- softmax (base-2): warp w handles queries w, w+8, w+16, w+24
#pragma unroll
    for (int qq = 0; qq < 4; qq++) {
        int q = w + qq * 8;
        float s0 = Sw[q * SW_STR + l];
        float s1 = Sw[q * SW_STR + 32 + l];
        float m = warpmax(fmaxf(s0, s1));
        float e0 = exp2f(s0 - m), e1 = exp2f(s1 - m);
        float inv = __fdividef(1.f, warpsum(e0 + e1));
        Sw[q * SW_STR + l] = e0 * inv;
        Sw[q * SW_STR + 32 + l] = e1 * inv;
    }
    __syncthreads();

    // ---- V regs -> smem (same stride-33 layout)
#pragma unroll
    for (int i = 0; i < 3; i++) {
        int f = tid + i * 256;
        if (f < KR3 * 8) {
            int row = f >> 3, u4 = (f & 7) * 4;
            uint32_t* d = &Ku[row * KU_STR + u4];
            d[0] = vreg[i].x; d[1] = vreg[i].y; d[2] = vreg[i].z; d[3] = vreg[i].w;
        }
    }
    __syncthreads();

    // ---- AV: hfma2 inner (weights as half2), promote every 8 keys
    {
        const int dg = tid & 7;
        float accf[8];
#pragma unroll
        for (int j = 0; j < 8; j++) accf[j] = 0.f;
        const float* wrow = &Sw[qi * SW_STR];
        const uint32_t* vbase = &Ku[qi * KU_STR + dg * 4];
#pragma unroll
        for (int ch = 0; ch < 8; ch++) {
            __half2 hacc[4];
            hacc[0] = hacc[1] = hacc[2] = hacc[3] = __half2half2(__float2half(0.f));
#pragma unroll
            for (int k = ch * 8; k < ch * 8 + 8; k++) {
                __half2 wh2 = __float2half2_rn(wrow[k]);
                const uint32_t* vp = vbase + k * KU_STR;
#pragma unroll
                for (int u = 0; u < 4; u++)
                    hacc[u] = __hfma2(wh2, ash2(vp[u]), hacc[u]);
            }
#pragma unroll
            for (int u = 0; u < 4; u++) {
                float2 f = __half22float2(hacc[u]);
                accf[2 * u]     += f.x;
                accf[2 * u + 1] += f.y;
            }
        }
        __half* orow = attn_out + ((size_t)(b * N_ + n0 + qi)) * DIM_ + h * HD_ + dg * 8;
        *(uint4*)orow = make_uint4(packh2(accf[0], accf[1]), packh2(accf[2], accf[3]),
                                   packh2(accf[4], accf[5]), packh2(accf[6], accf[7]));
    }
}

// ------------------------ launch --------------------------------------------
extern "C" void kernel_launch(void* const* d_in, const int* in_sizes, int n_in,
                              void* d_out, int out_size) {
    (void)in_sizes; (void)n_in; (void)out_size;
    const float* x     = (const float*)d_in[0];
    const float* fcos  = (const float*)d_in[1];
    const float* fsin  = (const float*)d_in[2];
    const float* c     = (const float*)d_in[3];
    const float* Wq    = (const float*)d_in[4];
    const float* bq    = (const float*)d_in[5];
    const float* Wk    = (const float*)d_in[6];
    const float* bk    = (const float*)d_in[7];
    const float* Wv    = (const float*)d_in[8];
    const float* bv    = (const float*)d_in[9];
    const float* Wo    = (const float*)d_in[10];
    const float* bo    = (const float*)d_in[11];
    const float* W1    = (const float*)d_in[12];
    const float* b1    = (const float*)d_in[13];
    const float* W2    = (const float*)d_in[14];
    const float* b2    = (const float*)d_in[15];
    const float* ln1s  = (const float*)d_in[16];
    const float* ln1b  = (const float*)d_in[17];
    const float* ln2s  = (const float*)d_in[18];
    const float* ln2b  = (const float*)d_in[19];
    const float* geo   = (const float*)d_in[20];
    const float* hasho = (const float*)d_in[21];
    float* out = (float*)d_out;

    __half *xnh, *attnh, *hhh, *midh, *wh, *q, *k, *v, *qh, *kh, *vt;
    float *xout;
    cudaGetSymbolAddress((void**)&xnh,   g_xnh);
    cudaGetSymbolAddress((void**)&q,     g_q);
    cudaGetSymbolAddress((void**)&k,     g_k);
    cudaGetSymbolAddress((void**)&v,     g_v);
    cudaGetSymbolAddress((void**)&qh,    g_qh);
    cudaGetSymbolAddress((void**)&kh,    g_kh);
    cudaGetSymbolAddress((void**)&vt,    g_vt);
    cudaGetSymbolAddress((void**)&attnh, g_attnh);
    cudaGetSymbolAddress((void**)&xout,  g_xout);
    cudaGetSymbolAddress((void**)&hhh,   g_hhh);
    cudaGetSymbolAddress((void**)&midh,  g_midh);
    cudaGetSymbolAddress((void**)&wh,    g_wh);

    // 0+1) fused: LN1 (blocks 0..2047) + weight cvt (blocks 2048..8191)
    ln1_cvtw_kernel<<<8192, 128>>>(x, ln1s, ln1b, xnh,
                                   Wq, Wk, Wv, Wo, W1, W2, wh);

    // 2) fused QKV projections (half out)
    dim3 gqkv(DIM_ / 128, M_ / 128, 3);
    k_gemm_qkv<<<gqkv, 256>>>(xnh, wh, bq, bk, bv, q, k, v);

    // 3) hash + rope + expmap0 + transpose (half in/out)
    prep_kernel<<<M_, 256>>>(q, k, v, fcos, fsin, c, hasho, qh, kh, vt);

    // 4) sliding-window Poincaré attention (hfma2 inner loops)
    attn4_kernel<<<NT3, 256>>>(qh, kh, vt, c, geo, attnh);

    // 5) Wo projection + residual(x) -> xout (f32)
    dim3 gwo(DIM_ / 64, M_ / 128);
    k_gemm64_res<<<gwo, 256>>>(attnh, wh + WH_O, bo, x, xout, DIM_, DIM_);

    // 6) LN2 (half out)
    ln_kernel<<<M_, 128>>>(xout, ln2s, ln2b, hhh);

    // 7) FFN1 + gelu (half out)
    dim3 gffn1(DFF_ / 128, M_ / 128);
    k_gemm128_gelu<<<gffn1, 256>>>(hhh, wh + WH_1, b1, midh, DFF_, DIM_);

    // 8) FFN2 + residual(xout) -> out (f32)
    k_gemm64_res<<<gwo, 256>>>(midh, wh + WH_2, b2, xout, out, DIM_, DFF_);
}

// round 16
// speedup vs baseline: 2.9568x; 1.0163x over previous
#include <cuda_runtime.h>
#include <cuda_bf16.h>
#include <cuda_fp16.h>
#include <math.h>
#include <cstdint>

#define B_    2
#define N_    1024
#define DIM_  512
#define NH_   8
#define HD_   64
#define WIN_  64
#define M_    (B_ * N_)      // 2048
#define DFF_  (4 * DIM_)     // 2048
#define EPSV  1e-7f

// ------------------------ scratch (device globals; no allocation) ------------
__device__ __half g_xnh [M_ * DIM_];    // LN1 out (half)
__device__ __half g_q   [M_ * DIM_];    // QKV outs (half)
__device__ __half g_k   [M_ * DIM_];
__device__ __half g_v   [M_ * DIM_];
__device__ __half g_qh  [B_ * NH_ * N_ * HD_];   // prep outs (half)
__device__ __half g_kh  [B_ * NH_ * N_ * HD_];
__device__ __half g_vt  [B_ * NH_ * N_ * HD_];
__device__ __half g_attnh[M_ * DIM_];   // attention out (half)
__device__ float  g_xout[M_ * DIM_];
__device__ __half g_hhh [M_ * DIM_];    // LN2 out (half)
__device__ __half g_midh[M_ * DFF_];    // FFN mid (half)
// half weights, concatenated
#define WH_Q 0
#define WH_K 262144
#define WH_V 524288
#define WH_O 786432
#define WH_1 1048576
#define WH_2 2097152
__device__ __half g_wh[3145728];

// ------------------------ helpers -------------------------------------------
__device__ __forceinline__ float warpsum(float v) {
#pragma unroll
    for (int o = 16; o > 0; o >>= 1) v += __shfl_xor_sync(0xffffffffu, v, o);
    return v;
}
__device__ __forceinline__ float warpmax(float v) {
#pragma unroll
    for (int o = 16; o > 0; o >>= 1) v = fmaxf(v, __shfl_xor_sync(0xffffffffu, v, o));
    return v;
}
__device__ __forceinline__ float sqrt_fast(float x) {
    float r;
    asm("sqrt.approx.f32 %0, %1;" : "=f"(r) : "f"(x));
    return r;
}
__device__ __forceinline__ uint32_t packh2(float lo, float hi) {
    __half2 h = __floats2half2_rn(lo, hi);
    return *(uint32_t*)&h;
}
__device__ __forceinline__ float2 unpackh2(uint32_t u) {
    return __half22float2(*(__half2*)&u);
}
__device__ __forceinline__ __half2 ash2(uint32_t u) { return *(__half2*)&u; }
// fast tanh for x >= 0:  tanh(x) = 1 - 2/(1+e^{2x})
__device__ __forceinline__ float tanh_pos(float x) {
    return 1.f - __fdividef(2.f, 1.f + __expf(2.f * x));
}
// fp16 tensor-core mma: D(f32) += A(f16,16x16) * B(f16,16x8)
__device__ __forceinline__ void mma_f16(float4& c, uint32_t a0, uint32_t a1,
                                        uint32_t a2, uint32_t a3,
                                        uint32_t b0, uint32_t b1) {
    asm volatile(
        "mma.sync.aligned.m16n8k16.row.col.f32.f16.f16.f32 "
        "{%0,%1,%2,%3},{%4,%5,%6,%7},{%8,%9},{%0,%1,%2,%3};\n"
        : "+f"(c.x), "+f"(c.y), "+f"(c.z), "+f"(c.w)
        : "r"(a0), "r"(a1), "r"(a2), "r"(a3), "r"(b0), "r"(b1));
}

// ------------------------ fused LN1 + weight convert -------------------------
__global__ __launch_bounds__(128) void ln1_cvtw_kernel(
    const float* __restrict__ x, const float* __restrict__ s,
    const float* __restrict__ bsh, __half* __restrict__ out,
    const float* __restrict__ Wq, const float* __restrict__ Wk,
    const float* __restrict__ Wv, const float* __restrict__ Wo,
    const float* __restrict__ W1, const float* __restrict__ W2,
    __half* __restrict__ wh) {
    if (blockIdx.x < 2048) {
        int row = blockIdx.x;
        const float* xr = x + (size_t)row * DIM_;
        float v[4];
        float sum = 0.f, sq = 0.f;
#pragma unroll
        for (int i = 0; i < 4; i++) {
            v[i] = xr[threadIdx.x + i * 128];
            sum += v[i];
            sq  += v[i] * v[i];
        }
        __shared__ float red0[4], red1[4];
        sum = warpsum(sum); sq = warpsum(sq);
        int warp = threadIdx.x >> 5, lane = threadIdx.x & 31;
        if (lane == 0) { red0[warp] = sum; red1[warp] = sq; }
        __syncthreads();
        sum = red0[0] + red0[1] + red0[2] + red0[3];
        sq  = red1[0] + red1[1] + red1[2] + red1[3];
        float mean = sum * (1.0f / DIM_);
        float var  = sq * (1.0f / DIM_) - mean * mean;
        float inv  = rsqrtf(var + 1e-6f);
        __half* orow = out + (size_t)row * DIM_;
#pragma unroll
        for (int i = 0; i < 4; i++) {
            int d = threadIdx.x + i * 128;
            orow[d] = __float2half_rn((v[i] - mean) * inv * s[d] + bsh[d]);
        }
    } else {
        long i = ((long)(blockIdx.x - 2048) * 128 + threadIdx.x) * 4;
        if (i >= 3145728) return;
        const float* src;
        long off;
        if      (i <  262144) { src = Wq; off = i; }
        else if (i <  524288) { src = Wk; off = i - 262144; }
        else if (i <  786432) { src = Wv; off = i - 524288; }
        else if (i < 1048576) { src = Wo; off = i - 786432; }
        else if (i < 2097152) { src = W1; off = i - 1048576; }
        else                  { src = W2; off = i - 2097152; }
        float4 v = *(const float4*)(src + off);
        *(uint2*)(wh + i) = make_uint2(packh2(v.x, v.y), packh2(v.z, v.w));
    }
}

// ------------------------ layernorm (half output) ----------------------------
__global__ void ln_kernel(const float* __restrict__ x, const float* __restrict__ s,
                          const float* __restrict__ bsh, __half* __restrict__ out) {
    int row = blockIdx.x;
    const float* xr = x + (size_t)row * DIM_;
    float v[4];
    float sum = 0.f, sq = 0.f;
#pragma unroll
    for (int i = 0; i < 4; i++) {
        v[i] = xr[threadIdx.x + i * 128];
        sum += v[i];
        sq  += v[i] * v[i];
    }
    __shared__ float red0[4], red1[4];
    sum = warpsum(sum); sq = warpsum(sq);
    int warp = threadIdx.x >> 5, lane = threadIdx.x & 31;
    if (lane == 0) { red0[warp] = sum; red1[warp] = sq; }
    __syncthreads();
    sum = red0[0] + red0[1] + red0[2] + red0[3];
    sq  = red1[0] + red1[1] + red1[2] + red1[3];
    float mean = sum * (1.0f / DIM_);
    float var  = sq * (1.0f / DIM_) - mean * mean;
    float inv  = rsqrtf(var + 1e-6f);
    __half* orow = out + (size_t)row * DIM_;
#pragma unroll
    for (int i = 0; i < 4; i++) {
        int d = threadIdx.x + i * 128;
        orow[d] = __float2half_rn((v[i] - mean) * inv * s[d] + bsh[d]);
    }
}

// ======================= 128x128 fp16 GEMM (QKV / FFN1) ======================
struct GSmem128 {
    uint2 Ap[2][2][4][132];  // [buf][ks16][tg][row 0..127]
    uint2 Bp[2][2][4][132];  // [buf][ks16][tg][col 0..127]
};

// EPI: 2 = gelu+bias (half out), 3 = +bias (half out)
template <int EPI>
__device__ __forceinline__ void gemm_core128(
    const __half* __restrict__ A, const __half* __restrict__ Bw,
    const float* __restrict__ bias, __half* __restrict__ Ch, int Nd, int Kd) {
    __shared__ GSmem128 sm;
    const int m0 = blockIdx.y * 128, n0 = blockIdx.x * 128;
    const int tid = threadIdx.x;
    const int lane = tid & 31, wid = tid >> 5;
    const int g = lane >> 2, tg = lane & 3;
    const int wm = wid >> 2, wn = wid & 3;       // warp grid 2x4

    const int arow = tid >> 1, akh = tid & 1;
    const __half* aPtr = A + (size_t)(m0 + arow) * Kd + akh * 16;
    const int btg = (tid >> 6) & 3, bcp = tid & 63;
    const __half* bPtr0 = Bw + (size_t)(2 * btg) * Nd + n0 + 2 * bcp;
    const __half* bPtr1 = bPtr0 + (size_t)16 * Nd;

    float4 acc[4][4];
#pragma unroll
    for (int i = 0; i < 4; i++)
#pragma unroll
        for (int j = 0; j < 4; j++) acc[i][j] = make_float4(0.f, 0.f, 0.f, 0.f);

    uint4 alo, ahi;
    uint32_t wv[2][4];
    alo = *(const uint4*)(aPtr);
    ahi = *(const uint4*)(aPtr + 8);
#pragma unroll
    for (int s = 0; s < 2; s++) {
        const __half* bp = s ? bPtr1 : bPtr0;
        wv[s][0] = *(const uint32_t*)(bp);
        wv[s][1] = *(const uint32_t*)(bp + Nd);
        wv[s][2] = *(const uint32_t*)(bp + 8 * Nd);
        wv[s][3] = *(const uint32_t*)(bp + 9 * Nd);
    }

    auto store_tile = [&](int buf) {
        sm.Ap[buf][akh][0][arow] = make_uint2(alo.x, ahi.x);
        sm.Ap[buf][akh][1][arow] = make_uint2(alo.y, ahi.y);
        sm.Ap[buf][akh][2][arow] = make_uint2(alo.z, ahi.z);
        sm.Ap[buf][akh][3][arow] = make_uint2(alo.w, ahi.w);
#pragma unroll
        for (int s = 0; s < 2; s++) {
            uint32_t lo0 = __byte_perm(wv[s][0], wv[s][1], 0x5410);
            uint32_t lo1 = __byte_perm(wv[s][0], wv[s][1], 0x7632);
            uint32_t hi0 = __byte_perm(wv[s][2], wv[s][3], 0x5410);
            uint32_t hi1 = __byte_perm(wv[s][2], wv[s][3], 0x7632);
            *(uint4*)&sm.Bp[buf][s][btg][2 * bcp] = make_uint4(lo0, hi0, lo1, hi1);
        }
    };

    store_tile(0);
    __syncthreads();

    const int nT = Kd >> 5;
    for (int t = 0; t < nT; t++) {
        const int buf = t & 1;
        const bool more = (t + 1 < nT);
        if (more) {
            const __half* ap = aPtr + (t + 1) * 32;
            alo = *(const uint4*)(ap);
            ahi = *(const uint4*)(ap + 8);
            const size_t koff = (size_t)(t + 1) * 32 * Nd;
#pragma unroll
            for (int s = 0; s < 2; s++) {
                const __half* bp = (s ? bPtr1 : bPtr0) + koff;
                wv[s][0] = *(const uint32_t*)(bp);
                wv[s][1] = *(const uint32_t*)(bp + Nd);
                wv[s][2] = *(const uint32_t*)(bp + 8 * Nd);
                wv[s][3] = *(const uint32_t*)(bp + 9 * Nd);
            }
        }
#pragma unroll
        for (int ks = 0; ks < 2; ks++) {
            uint2 fal[4], fah[4], fb[4];
#pragma unroll
            for (int mi = 0; mi < 4; mi++) {
                fal[mi] = sm.Ap[buf][ks][tg][wm * 64 + mi * 16 + g];
                fah[mi] = sm.Ap[buf][ks][tg][wm * 64 + mi * 16 + g + 8];
            }
#pragma unroll
            for (int nj = 0; nj < 4; nj++)
                fb[nj] = sm.Bp[buf][ks][tg][wn * 32 + nj * 8 + g];
#pragma unroll
            for (int mi = 0; mi < 4; mi++)
#pragma unroll
                for (int nj = 0; nj < 4; nj++)
                    mma_f16(acc[mi][nj],
                            fal[mi].x, fah[mi].x, fal[mi].y, fah[mi].y,
                            fb[nj].x, fb[nj].y);
        }
        if (more) store_tile(buf ^ 1);
        __syncthreads();
    }

#pragma unroll
    for (int mi = 0; mi < 4; mi++) {
        int r0 = m0 + wm * 64 + mi * 16 + g;
#pragma unroll
        for (int nj = 0; nj < 4; nj++) {
            int col = n0 + wn * 32 + nj * 8 + tg * 2;
            float2 bbv = *(const float2*)(bias + col);
            float4 a = acc[mi][nj];
            float2 o0 = make_float2(a.x + bbv.x, a.y + bbv.y);
            float2 o1 = make_float2(a.z + bbv.x, a.w + bbv.y);
            if (EPI == 2) {
                float t0 = o0.x, t1 = o0.y, t2 = o1.x, t3 = o1.y;
                o0.x = t0 / (1.f + __expf(-1.5957691216057308f * (t0 + 0.044715f * t0 * t0 * t0)));
                o0.y = t1 / (1.f + __expf(-1.5957691216057308f * (t1 + 0.044715f * t1 * t1 * t1)));
                o1.x = t2 / (1.f + __expf(-1.5957691216057308f * (t2 + 0.044715f * t2 * t2 * t2)));
                o1.y = t3 / (1.f + __expf(-1.5957691216057308f * (t3 + 0.044715f * t3 * t3 * t3)));
            }
            *(uint32_t*)(Ch + (size_t)r0 * Nd + col)       = packh2(o0.x, o0.y);
            *(uint32_t*)(Ch + (size_t)(r0 + 8) * Nd + col) = packh2(o1.x, o1.y);
        }
    }
}

__global__ __launch_bounds__(256, 2) void k_gemm_qkv(
    const __half* __restrict__ xn, const __half* __restrict__ wh,
    const float* __restrict__ bq, const float* __restrict__ bk,
    const float* __restrict__ bv,
    __half* __restrict__ q, __half* __restrict__ k, __half* __restrict__ v) {
    int z = blockIdx.z;
    const __half* W  = wh + ((z == 0) ? WH_Q : (z == 1) ? WH_K : WH_V);
    const float* bb  = (z == 0) ? bq : (z == 1) ? bk : bv;
    __half* o        = (z == 0) ? q  : (z == 1) ? k  : v;
    gemm_core128<3>(xn, W, bb, o, DIM_, DIM_);
}

__global__ __launch_bounds__(256, 2) void k_gemm128_gelu(
    const __half* __restrict__ A, const __half* __restrict__ W,
    const float* __restrict__ bias, __half* __restrict__ C, int Nd, int Kd) {
    gemm_core128<2>(A, W, bias, C, Nd, Kd);
}

// ======================= 128x64 fp16 GEMM (Wo / FFN2, +residual, f32 out) ====
struct GSmem64 {
    uint2 Ap[2][2][4][132];
    uint2 Bp[2][2][4][68];
};

__global__ __launch_bounds__(256, 3) void k_gemm64_res(
    const __half* __restrict__ A, const __half* __restrict__ Bw,
    const float* __restrict__ bias, const float* __restrict__ res,
    float* __restrict__ C, int Nd, int Kd) {
    __shared__ GSmem64 sm;
    const int m0 = blockIdx.y * 128, n0 = blockIdx.x * 64;
    const int tid = threadIdx.x;
    const int lane = tid & 31, wid = tid >> 5;
    const int g = lane >> 2, tg = lane & 3;
    const int wm = wid >> 1, wn = wid & 1;

    const int arow = tid >> 1, akh = tid & 1;
    const __half* aPtr = A + (size_t)(m0 + arow) * Kd + akh * 16;
    const int bks = tid >> 7, btg = (tid >> 5) & 3, bcp = tid & 31;
    const __half* bPtr = Bw + (size_t)(bks * 16 + 2 * btg) * Nd + n0 + 2 * bcp;

    float4 acc[2][4];
#pragma unroll
    for (int i = 0; i < 2; i++)
#pragma unroll
        for (int j = 0; j < 4; j++) acc[i][j] = make_float4(0.f, 0.f, 0.f, 0.f);

    uint4 alo, ahi;
    uint32_t w0, w1, w2, w3;
    alo = *(const uint4*)(aPtr);
    ahi = *(const uint4*)(aPtr + 8);
    w0 = *(const uint32_t*)(bPtr);
    w1 = *(const uint32_t*)(bPtr + Nd);
    w2 = *(const uint32_t*)(bPtr + 8 * Nd);
    w3 = *(const uint32_t*)(bPtr + 9 * Nd);

    auto store_tile = [&](int buf) {
        sm.Ap[buf][akh][0][arow] = make_uint2(alo.x, ahi.x);
        sm.Ap[buf][akh][1][arow] = make_uint2(alo.y, ahi.y);
        sm.Ap[buf][akh][2][arow] = make_uint2(alo.z, ahi.z);
        sm.Ap[buf][akh][3][arow] = make_uint2(alo.w, ahi.w);
        uint32_t lo0 = __byte_perm(w0, w1, 0x5410);
        uint32_t lo1 = __byte_perm(w0, w1, 0x7632);
        uint32_t hi0 = __byte_perm(w2, w3, 0x5410);
        uint32_t hi1 = __byte_perm(w2, w3, 0x7632);
        *(uint4*)&sm.Bp[buf][bks][btg][2 * bcp] = make_uint4(lo0, hi0, lo1, hi1);
    };

    store_tile(0);
    __syncthreads();

    const int nT = Kd >> 5;
    for (int t = 0; t < nT; t++) {
        const int buf = t & 1;
        const bool more = (t + 1 < nT);
        if (more) {
            const __half* ap = aPtr + (t + 1) * 32;
            alo = *(const uint4*)(ap);
            ahi = *(const uint4*)(ap + 8);
            const __half* bp = bPtr + (size_t)(t + 1) * 32 * Nd;
            w0 = *(const uint32_t*)(bp);
            w1 = *(const uint32_t*)(bp + Nd);
            w2 = *(const uint32_t*)(bp + 8 * Nd);
            w3 = *(const uint32_t*)(bp + 9 * Nd);
        }
#pragma unroll
        for (int ks = 0; ks < 2; ks++) {
            uint2 fal[2], fah[2], fb[4];
#pragma unroll
            for (int mi = 0; mi < 2; mi++) {
                fal[mi] = sm.Ap[buf][ks][tg][wm * 32 + mi * 16 + g];
                fah[mi] = sm.Ap[buf][ks][tg][wm * 32 + mi * 16 + g + 8];
            }
#pragma unroll
            for (int nj = 0; nj < 4; nj++)
                fb[nj] = sm.Bp[buf][ks][tg][wn * 32 + nj * 8 + g];
#pragma unroll
            for (int mi = 0; mi < 2; mi++)
#pragma unroll
                for (int nj = 0; nj < 4; nj++)
                    mma_f16(acc[mi][nj],
                            fal[mi].x, fah[mi].x, fal[mi].y, fah[mi].y,
                            fb[nj].x, fb[nj].y);
        }
        if (more) store_tile(buf ^ 1);
        __syncthreads();
    }

#pragma unroll
    for (int mi = 0; mi < 2; mi++) {
        int r0 = m0 + wm * 32 + mi * 16 + g;
#pragma unroll
        for (int nj = 0; nj < 4; nj++) {
            int col = n0 + wn * 32 + nj * 8 + tg * 2;
            float2 bbv = *(const float2*)(bias + col);
            float4 a = acc[mi][nj];
            float2 r0v = *(const float2*)(res + (size_t)r0 * Nd + col);
            float2 r1v = *(const float2*)(res + (size_t)(r0 + 8) * Nd + col);
            float2 o0 = make_float2(a.x + bbv.x + r0v.x, a.y + bbv.y + r0v.y);
            float2 o1 = make_float2(a.z + bbv.x + r1v.x, a.w + bbv.y + r1v.y);
            *(float2*)(C + (size_t)r0 * Nd + col)       = o0;
            *(float2*)(C + (size_t)(r0 + 8) * Nd + col) = o1;
        }
    }
}

// ------------------------ prep (half in, half out) ---------------------------
__global__ void prep_kernel(const __half* __restrict__ qb, const __half* __restrict__ kb,
                            const __half* __restrict__ vb, const float* __restrict__ cos_t,
                            const float* __restrict__ sin_t, const float* __restrict__ c_arr,
                            const float* __restrict__ hash_off,
                            __half* __restrict__ qh, __half* __restrict__ kh,
                            __half* __restrict__ vt) {
    int bn = blockIdx.x;
    int b = bn / N_, n = bn % N_;
    int h = threadIdx.x >> 5, lane = threadIdx.x & 31;
    const float LOG9 = 2.1972245773362196f;
    float cs = cos_t[n * 32 + lane];
    float sn = sin_t[n * 32 + lane];
    float cb = c_arr[b];
    float sqrt_c = fmaxf(sqrtf(cb), EPSV);
    size_t in_off  = (size_t)bn * DIM_ + h * HD_;
    size_t out_off = (((size_t)(b * NH_ + h)) * N_ + n) * HD_;

    {
        float v0 = __half2float(qb[in_off + lane])      + hash_off[h * HD_ + lane]      * LOG9;
        float v1 = __half2float(qb[in_off + lane + 32]) + hash_off[h * HD_ + lane + 32] * LOG9;
        float r0 = v0 * cs - v1 * sn;
        float r1 = v0 * sn + v1 * cs;
        float nrm = sqrtf(warpsum(r0 * r0 + r1 * r1));
        float o0 = 0.f, o1 = 0.f;
        if (nrm >= EPSV) {
            float safe = fmaxf(nrm, EPSV);
            float sc   = __fdividef(tanh_pos(sqrt_c * safe), sqrt_c * safe);
            o0 = sc * r0; o1 = sc * r1;
        }
        qh[out_off + lane] = __float2half_rn(o0);
        qh[out_off + lane + 32] = __float2half_rn(o1);
    }
    {
        float v0 = __half2float(kb[in_off + lane]);
        float v1 = __half2float(kb[in_off + lane + 32]);
        float r0 = v0 * cs - v1 * sn;
        float r1 = v0 * sn + v1 * cs;
        float nrm = sqrtf(warpsum(r0 * r0 + r1 * r1));
        float o0 = 0.f, o1 = 0.f;
        if (nrm >= EPSV) {
            float safe = fmaxf(nrm, EPSV);
            float sc   = __fdividef(tanh_pos(sqrt_c * safe), sqrt_c * safe);
            o0 = sc * r0; o1 = sc * r1;
        }
        kh[out_off + lane] = __float2half_rn(o0);
        kh[out_off + lane + 32] = __float2half_rn(o1);
    }
    vt[out_off + lane]      = vb[in_off + lane];
    vt[out_off + lane + 32] = vb[in_off + lane + 32];
}

// ---------------- windowed Poincaré attention (QT=32, hfma2, 1-wave) ---------
#define QT3    32
#define KR3    (QT3 + WIN_ - 1)   // 95
#define KU_STR 33                 // uint (half2) stride
#define QU_STR 33                 // Q half2 stride
#define SW_STR 65
#define NT3    ((N_ / QT3) * B_ * NH_)   // 512 tiles = grid
#define RMIN_  5.0000003e-8f             // (1e-7)/(2-1e-7)

__global__ __launch_bounds__(256, 4) void attn4_kernel(
    const __half* __restrict__ qh, const __half* __restrict__ kh,
    const __half* __restrict__ vt, const float* __restrict__ c_arr,
    const float* __restrict__ geo, __half* __restrict__ attn_out) {
    __shared__ uint32_t Ku[KR3 * KU_STR + 4];   // K tile (half2); reused for V
    __shared__ uint32_t Qu[QT3 * QU_STR];       // Q tile (half2)
    __shared__ float Sw[QT3 * SW_STR];
    __shared__ float y2s[KR3 + 1];

    const int tid = threadIdx.x;
    const int w = tid >> 5, l = tid & 31;
    const int qi = tid >> 3;          // 0..31 (query)
    const int kg = tid & 7;           // 0..7  (key group)

    const int t = blockIdx.x;
    const int bh = t >> 5;
    const int b = bh >> 3, h = bh & 7;
    const int n0 = (t & 31) << 5;
    const __half* Kb = kh + (size_t)bh * (N_ * HD_);
    const __half* Vb = vt + (size_t)bh * (N_ * HD_);
    const __half* Qb = qh + (size_t)bh * (N_ * HD_);

    // ---- K tile -> smem (uint4 gmem loads, scalar STS at stride 33)
#pragma unroll
    for (int i = 0; i < 3; i++) {
        int f = tid + i * 256;
        if (f < KR3 * 8) {
            int row = f >> 3, u4 = (f & 7) * 4;
            int gn = n0 - (WIN_ - 1) + row;
            uint4 val = make_uint4(0u, 0u, 0u, 0u);
            if (gn >= 0) val = *(const uint4*)(Kb + (size_t)gn * HD_ + u4 * 2);
            uint32_t* d = &Ku[row * KU_STR + u4];
            d[0] = val.x; d[1] = val.y; d[2] = val.z; d[3] = val.w;
        }
    }
    // ---- Q tile -> smem half2 (straight copy)
    {
        int row = tid >> 3, u4 = (tid & 7) * 4;
        uint4 qv = *(const uint4*)(Qb + (size_t)(n0 + row) * HD_ + u4 * 2);
        uint32_t* d = &Qu[row * QU_STR + u4];
        d[0] = qv.x; d[1] = qv.y; d[2] = qv.z; d[3] = qv.w;
    }
    // ---- prefetch V into registers
    uint4 vreg[3];
#pragma unroll
    for (int i = 0; i < 3; i++) {
        int f = tid + i * 256;
        vreg[i] = make_uint4(0u, 0u, 0u, 0u);
        if (f < KR3 * 8) {
            int row = f >> 3, u4 = (f & 7) * 4;
            int gn = n0 - (WIN_ - 1) + row;
            if (gn >= 0) vreg[i] = *(const uint4*)(Vb + (size_t)gn * HD_ + u4 * 2);
        }
    }
    __syncthreads();

    // ---- y2 per key row (f32)
    for (int row = w; row < KR3; row += 8) {
        float2 f = unpackh2(Ku[row * KU_STR + l]);
        float s = warpsum(f.x * f.x + f.y * f.y);
        if (l == 0) y2s[row] = s;
    }
    __syncthreads();

    const float cb = c_arr[b];
    const float sc = fmaxf(sqrtf(cb), EPSV);
    const float gs = geo[h];
    const float p2 = gs / sc;
    const float cc = cb * cb;

    // ---- dots: hfma2 inner, promote to f32 every 8 half2-steps (16 dims)
    float xy[8], q2 = 0.f;
#pragma unroll
    for (int j = 0; j < 8; j++) xy[j] = 0.f;
    {
        const uint32_t* qrow = &Qu[qi * QU_STR];
        const uint32_t* kr = &Ku[(qi + kg) * KU_STR];
#pragma unroll
        for (int ch = 0; ch < 4; ch++) {
            __half2 hq2 = __half2half2(__float2half(0.f));
            __half2 hxy[8];
#pragma unroll
            for (int j = 0; j < 8; j++) hxy[j] = hq2;
#pragma unroll
            for (int d2 = ch * 8; d2 < ch * 8 + 8; d2++) {
                __half2 qv = ash2(qrow[d2]);
                hq2 = __hfma2(qv, qv, hq2);
#pragma unroll
                for (int j = 0; j < 8; j++) {
                    __half2 kv = ash2(kr[d2 + j * 8 * KU_STR]);
                    hxy[j] = __hfma2(qv, kv, hxy[j]);
                }
            }
            float2 fq = __half22float2(hq2);
            q2 += fq.x + fq.y;
#pragma unroll
            for (int j = 0; j < 8; j++) {
                float2 f = __half22float2(hxy[j]);
                xy[j] += f.x + f.y;
            }
        }
    }
    {
        const float Bc = 1.f - cb * q2;
        const float c2x2 = cc * q2;
#pragma unroll
        for (int j = 0; j < 8; j++) {
            float xyv = xy[j];
            float y2 = y2s[qi + kg + 8 * j];
            float u  = fmaf(-2.f * cb, xyv, 1.f);
            float A  = fmaf(cb, y2, u);
            float dn2 = fmaf(A * A, q2, fmaf(Bc * Bc, y2, -2.f * A * Bc * xyv));
            float den = fmaxf(fmaf(c2x2, y2, u), EPSV);
            float s   = sc * sqrt_fast(fmaxf(dn2, 0.f));
            float ratio = __fdividef(den - s, den + s);
            ratio = fmaxf(ratio, RMIN_);
            Sw[qi * SW_STR + kg + 8 * j] = p2 * __log2f(ratio);
        }
    }
    __syncthreads();

    // ---- softmax (base-2): warp w handles queries w, w+8, w+16, w+24
#pragma unroll
    for (int qq = 0; qq < 4; qq++) {
        int q = w + qq * 8;
        float s0 = Sw[q * SW_STR + l];
        float s1 = Sw[q * SW_STR + 32 + l];
        float m = warpmax(fmaxf(s0, s1));
        float e0 = exp2f(s0 - m), e1 = exp2f(s1 - m);
        float inv = __fdividef(1.f, warpsum(e0 + e1));
        Sw[q * SW_STR + l] = e0 * inv;
        Sw[q * SW_STR + 32 + l] = e1 * inv;
    }
    __syncthreads();

    // ---- V regs -> smem (same stride-33 layout)
#pragma unroll
    for (int i = 0; i < 3; i++) {
        int f = tid + i * 256;
        if (f < KR3 * 8) {
            int row = f >> 3, u4 = (f & 7) * 4;
            uint32_t* d = &Ku[row * KU_STR + u4];
            d[0] = vreg[i].x; d[1] = vreg[i].y; d[2] = vreg[i].z; d[3] = vreg[i].w;
        }
    }
    __syncthreads();

    // ---- AV: hfma2 inner (weights as half2), promote every 8 keys
    {
        const int dg = tid & 7;
        float accf[8];
#pragma unroll
        for (int j = 0; j < 8; j++) accf[j] = 0.f;
        const float* wrow = &Sw[qi * SW_STR];
        const uint32_t* vbase = &Ku[qi * KU_STR + dg * 4];
#pragma unroll
        for (int ch = 0; ch < 8; ch++) {
            __half2 hacc[4];
            hacc[0] = hacc[1] = hacc[2] = hacc[3] = __half2half2(__float2half(0.f));
#pragma unroll
            for (int k = ch * 8; k < ch * 8 + 8; k++) {
                __half2 wh2 = __float2half2_rn(wrow[k]);
                const uint32_t* vp = vbase + k * KU_STR;
#pragma unroll
                for (int u = 0; u < 4; u++)
                    hacc[u] = __hfma2(wh2, ash2(vp[u]), hacc[u]);
            }
#pragma unroll
            for (int u = 0; u < 4; u++) {
                float2 f = __half22float2(hacc[u]);
                accf[2 * u]     += f.x;
                accf[2 * u + 1] += f.y;
            }
        }
        __half* orow = attn_out + ((size_t)(b * N_ + n0 + qi)) * DIM_ + h * HD_ + dg * 8;
        *(uint4*)orow = make_uint4(packh2(accf[0], accf[1]), packh2(accf[2], accf[3]),
                                   packh2(accf[4], accf[5]), packh2(accf[6], accf[7]));
    }
}

// ------------------------ launch --------------------------------------------
extern "C" void kernel_launch(void* const* d_in, const int* in_sizes, int n_in,
                              void* d_out, int out_size) {
    (void)in_sizes; (void)n_in; (void)out_size;
    const float* x     = (const float*)d_in[0];
    const float* fcos  = (const float*)d_in[1];
    const float* fsin  = (const float*)d_in[2];
    const float* c     = (const float*)d_in[3];
    const float* Wq    = (const float*)d_in[4];
    const float* bq    = (const float*)d_in[5];
    const float* Wk    = (const float*)d_in[6];
    const float* bk    = (const float*)d_in[7];
    const float* Wv    = (const float*)d_in[8];
    const float* bv    = (const float*)d_in[9];
    const float* Wo    = (const float*)d_in[10];
    const float* bo    = (const float*)d_in[11];
    const float* W1    = (const float*)d_in[12];
    const float* b1    = (const float*)d_in[13];
    const float* W2    = (const float*)d_in[14];
    const float* b2    = (const float*)d_in[15];
    const float* ln1s  = (const float*)d_in[16];
    const float* ln1b  = (const float*)d_in[17];
    const float* ln2s  = (const float*)d_in[18];
    const float* ln2b  = (const float*)d_in[19];
    const float* geo   = (const float*)d_in[20];
    const float* hasho = (const float*)d_in[21];
    float* out = (float*)d_out;

    __half *xnh, *attnh, *hhh, *midh, *wh, *q, *k, *v, *qh, *kh, *vt;
    float *xout;
    cudaGetSymbolAddress((void**)&xnh,   g_xnh);
    cudaGetSymbolAddress((void**)&q,     g_q);
    cudaGetSymbolAddress((void**)&k,     g_k);
    cudaGetSymbolAddress((void**)&v,     g_v);
    cudaGetSymbolAddress((void**)&qh,    g_qh);
    cudaGetSymbolAddress((void**)&kh,    g_kh);
    cudaGetSymbolAddress((void**)&vt,    g_vt);
    cudaGetSymbolAddress((void**)&attnh, g_attnh);
    cudaGetSymbolAddress((void**)&xout,  g_xout);
    cudaGetSymbolAddress((void**)&hhh,   g_hhh);
    cudaGetSymbolAddress((void**)&midh,  g_midh);
    cudaGetSymbolAddress((void**)&wh,    g_wh);

    // 0+1) fused: LN1 (blocks 0..2047) + weight cvt (blocks 2048..8191)
    ln1_cvtw_kernel<<<8192, 128>>>(x, ln1s, ln1b, xnh,
                                   Wq, Wk, Wv, Wo, W1, W2, wh);

    // 2) fused QKV projections (half out)
    dim3 gqkv(DIM_ / 128, M_ / 128, 3);
    k_gemm_qkv<<<gqkv, 256>>>(xnh, wh, bq, bk, bv, q, k, v);

    // 3) hash + rope + expmap0 + transpose (half in/out)
    prep_kernel<<<M_, 256>>>(q, k, v, fcos, fsin, c, hasho, qh, kh, vt);

    // 4) sliding-window Poincaré attention (4 CTAs/SM -> single wave)
    attn4_kernel<<<NT3, 256>>>(qh, kh, vt, c, geo, attnh);

    // 5) Wo projection + residual(x) -> xout (f32)
    dim3 gwo(DIM_ / 64, M_ / 128);
    k_gemm64_res<<<gwo, 256>>>(attnh, wh + WH_O, bo, x, xout, DIM_, DIM_);

    // 6) LN2 (half out)
    ln_kernel<<<M_, 128>>>(xout, ln2s, ln2b, hhh);

    // 7) FFN1 + gelu (half out)
    dim3 gffn1(DFF_ / 128, M_ / 128);
    k_gemm128_gelu<<<gffn1, 256>>>(hhh, wh + WH_1, b1, midh, DFF_, DIM_);

    // 8) FFN2 + residual(xout) -> out (f32)
    k_gemm64_res<<<gwo, 256>>>(midh, wh + WH_2, b2, xout, out, DIM_, DFF_);
}